// round 3
// baseline (speedup 1.0000x reference)
#include <cuda_runtime.h>
#include <math.h>

// Problem constants
#define BB   4
#define NXC  1024
#define NYC  1024
#define EC   512
#define HC   8
#define DHC  64
#define LC   4
#define FFC  2048
#define MC   (BB * NXC)          // 4096 rows of x/y flattened

// ---------------------------------------------------------------------------
// Scratch (device globals; allocation-free per harness rules)
// ---------------------------------------------------------------------------
#define BNE  (BB * NXC * EC)                   // 2,097,152
#define BHNN ((size_t)BB * HC * NXC * NYC)     // 33,554,432

__device__ float g_Q [BNE];
__device__ float g_K [BNE];
__device__ float g_V [BNE];
__device__ float g_O [BNE];
__device__ float g_O2[BNE];
__device__ float g_Hb[BNE];
__device__ float g_F2[BNE];
__device__ float g_F1[(size_t)BB * NXC * FFC]; // 8,388,608
__device__ float g_S [BHNN];                   // raw scores scratch
__device__ float g_A [BHNN];                   // attn (residual-chained)

// ---------------------------------------------------------------------------
// Generic fp32 GEMM: C[M,N] = A[M,K] @ W[K,N] + bias[N]  (optional exact GELU)
// 128x128 tile, BK=8, 256 threads, 8x8 per thread.
// Double-buffered smem: 1 barrier per k-step, STS of tile k+1 overlaps FMAs of k.
// ---------------------------------------------------------------------------
__global__ __launch_bounds__(256) void gemm_k(
    const float* __restrict__ A, const float* __restrict__ W,
    const float* __restrict__ bias, float* __restrict__ C,
    int M, int K, int N, int dogelu)
{
    __shared__ float As[2][8][128];
    __shared__ float Bs[2][8][128];

    const int tid = threadIdx.x;
    const int bx = blockIdx.x, by = blockIdx.y;
    const int tx = tid & 15, ty = tid >> 4;

    const int rowA = tid >> 1;        // 0..127
    const int segA = (tid & 1) * 4;   // 0 or 4
    const int rowW = tid >> 5;        // 0..7
    const int colW = (tid & 31) * 4;  // 0..124

    const float* Ag = A + (size_t)(by * 128 + rowA) * K + segA;
    const float* Wg = W + (size_t)rowW * N + bx * 128 + colW;

    float acc[8][8];
#pragma unroll
    for (int i = 0; i < 8; i++)
#pragma unroll
        for (int j = 0; j < 8; j++) acc[i][j] = 0.f;

    // prologue: tile 0 -> buffer 0
    {
        float4 av = *(const float4*)(Ag);
        float4 wv = *(const float4*)(Wg);
        As[0][segA + 0][rowA] = av.x;
        As[0][segA + 1][rowA] = av.y;
        As[0][segA + 2][rowA] = av.z;
        As[0][segA + 3][rowA] = av.w;
        *(float4*)&Bs[0][rowW][colW] = wv;
    }
    __syncthreads();

    int buf = 0;
    for (int k0 = 0; k0 < K; k0 += 8) {
        const int haveNext = (k0 + 8 < K);
        float4 av, wv;
        if (haveNext) {
            av = *(const float4*)(Ag + k0 + 8);
            wv = *(const float4*)(Wg + (size_t)(k0 + 8) * N);
        }

#pragma unroll
        for (int kk = 0; kk < 8; kk++) {
            float a[8], b[8];
            *(float4*)&a[0] = *(const float4*)&As[buf][kk][ty * 8];
            *(float4*)&a[4] = *(const float4*)&As[buf][kk][ty * 8 + 4];
            *(float4*)&b[0] = *(const float4*)&Bs[buf][kk][tx * 8];
            *(float4*)&b[4] = *(const float4*)&Bs[buf][kk][tx * 8 + 4];
#pragma unroll
            for (int i = 0; i < 8; i++)
#pragma unroll
                for (int j = 0; j < 8; j++)
                    acc[i][j] = fmaf(a[i], b[j], acc[i][j]);
        }

        if (haveNext) {
            const int nb = buf ^ 1;
            As[nb][segA + 0][rowA] = av.x;
            As[nb][segA + 1][rowA] = av.y;
            As[nb][segA + 2][rowA] = av.z;
            As[nb][segA + 3][rowA] = av.w;
            *(float4*)&Bs[nb][rowW][colW] = wv;
            __syncthreads();
            buf = nb;
        }
    }

    float bv[8];
#pragma unroll
    for (int j = 0; j < 8; j++) bv[j] = bias[bx * 128 + tx * 8 + j];

#pragma unroll
    for (int i = 0; i < 8; i++) {
        int row = by * 128 + ty * 8 + i;
        float* Crow = C + (size_t)row * N + bx * 128 + tx * 8;
        float v[8];
#pragma unroll
        for (int j = 0; j < 8; j++) {
            float t = acc[i][j] + bv[j];
            if (dogelu) t = 0.5f * t * (1.0f + erff(t * 0.70710678118654752f));
            v[j] = t;
        }
        *(float4*)&Crow[0] = make_float4(v[0], v[1], v[2], v[3]);
        *(float4*)&Crow[4] = make_float4(v[4], v[5], v[6], v[7]);
    }
}

// ---------------------------------------------------------------------------
// Scores: S[b,h,n,m] = (q_head . k_head) * 0.125, masked to -1e9.
// Head split is a plain reshape => per (b,h) the Q/K heads are CONTIGUOUS
// (1024 x 64) blocks at offset b*NX*E + h*NX*DH.
// Grid: (NY/64, NX/64, B*H), 256 threads, 4x4 per thread.
// ---------------------------------------------------------------------------
__global__ __launch_bounds__(256) void scores_k(
    const float* __restrict__ Q, const float* __restrict__ Kt,
    const int* __restrict__ xm, const int* __restrict__ ym,
    float* __restrict__ S)
{
    __shared__ float Qs[64][65];
    __shared__ float Ks[64][65];

    const int bh = blockIdx.z;
    const int b = bh >> 3, h = bh & 7;
    const int n0 = blockIdx.y * 64, m0 = blockIdx.x * 64;
    const int tid = threadIdx.x;

    const float* qb = Q + (size_t)b * NXC * EC + (size_t)h * NXC * DHC + (size_t)n0 * DHC;
    const float* kb = Kt + (size_t)b * NYC * EC + (size_t)h * NYC * DHC + (size_t)m0 * DHC;

#pragma unroll
    for (int t = tid; t < 4096; t += 256) {
        Qs[t >> 6][t & 63] = qb[t];
        Ks[t >> 6][t & 63] = kb[t];
    }
    __syncthreads();

    const int tx = tid & 15, ty = tid >> 4;
    float acc[4][4];
#pragma unroll
    for (int i = 0; i < 4; i++)
#pragma unroll
        for (int j = 0; j < 4; j++) acc[i][j] = 0.f;

#pragma unroll 16
    for (int k = 0; k < 64; k++) {
        float a[4], b_[4];
#pragma unroll
        for (int i = 0; i < 4; i++) a[i] = Qs[ty * 4 + i][k];
#pragma unroll
        for (int j = 0; j < 4; j++) b_[j] = Ks[tx * 4 + j][k];
#pragma unroll
        for (int i = 0; i < 4; i++)
#pragma unroll
            for (int j = 0; j < 4; j++)
                acc[i][j] = fmaf(a[i], b_[j], acc[i][j]);
    }

    int ymv[4];
#pragma unroll
    for (int j = 0; j < 4; j++) ymv[j] = ym[b * NYC + m0 + tx * 4 + j];

#pragma unroll
    for (int i = 0; i < 4; i++) {
        int n = n0 + ty * 4 + i;
        int xmv = xm[b * NXC + n];
        float v[4];
#pragma unroll
        for (int j = 0; j < 4; j++) {
            float s = acc[i][j] * 0.125f;
            if (xmv == 0 || ymv[j] == 0) s = -1e9f;
            v[j] = s;
        }
        float* Srow = S + ((size_t)bh * NXC + n) * NYC + m0 + tx * 4;
        *(float4*)Srow = make_float4(v[0], v[1], v[2], v[3]);
    }
}

// ---------------------------------------------------------------------------
// Row softmax + residual attention: A[row] = softmax(S[row]) + (hasPrev? A[row] : 0)
// One block (256 threads) per row of 1024.
// ---------------------------------------------------------------------------
__global__ __launch_bounds__(256) void softmax_k(
    const float* __restrict__ S, float* __restrict__ A, int hasPrev)
{
    __shared__ float sred[8];
    __shared__ float sbc;

    const size_t base = (size_t)blockIdx.x * NYC;
    const int tid = threadIdx.x, lane = tid & 31, w = tid >> 5;

    float v[4];
#pragma unroll
    for (int i = 0; i < 4; i++) v[i] = S[base + tid + i * 256];

    float m = fmaxf(fmaxf(v[0], v[1]), fmaxf(v[2], v[3]));
#pragma unroll
    for (int o = 16; o > 0; o >>= 1) m = fmaxf(m, __shfl_xor_sync(0xffffffffu, m, o));
    if (lane == 0) sred[w] = m;
    __syncthreads();
    if (tid == 0) {
        float t = sred[0];
#pragma unroll
        for (int i = 1; i < 8; i++) t = fmaxf(t, sred[i]);
        sbc = t;
    }
    __syncthreads();
    const float bm = sbc;

    float p[4], s = 0.f;
#pragma unroll
    for (int i = 0; i < 4; i++) { p[i] = __expf(v[i] - bm); s += p[i]; }
#pragma unroll
    for (int o = 16; o > 0; o >>= 1) s += __shfl_xor_sync(0xffffffffu, s, o);
    if (lane == 0) sred[w] = s;
    __syncthreads();
    if (tid == 0) {
        float t = 0.f;
#pragma unroll
        for (int i = 0; i < 8; i++) t += sred[i];
        sbc = t;
    }
    __syncthreads();
    const float inv = 1.0f / sbc;

#pragma unroll
    for (int i = 0; i < 4; i++) {
        size_t idx = base + tid + i * 256;
        float r = p[i] * inv;
        if (hasPrev) r += A[idx];
        A[idx] = r;
    }
}

// ---------------------------------------------------------------------------
// O = attn @ V, writing directly into transposed layout O[b, n, h*64 + d].
// Grid: (NX/64, B*H), 256 threads, 4x4 per thread (full DH=64 per block).
// ---------------------------------------------------------------------------
__global__ __launch_bounds__(256) void attnv_k(
    const float* __restrict__ A, const float* __restrict__ V,
    float* __restrict__ O)
{
    __shared__ float As[64][65];
    __shared__ float Vs[64][65];

    const int bh = blockIdx.y;
    const int b = bh >> 3, h = bh & 7;
    const int n0 = blockIdx.x * 64;
    const int tid = threadIdx.x, tx = tid & 15, ty = tid >> 4;

    const float* arow = A + ((size_t)bh * NXC + n0) * NYC;
    const float* vb = V + (size_t)b * NYC * EC + (size_t)h * NYC * DHC;

    float acc[4][4];
#pragma unroll
    for (int i = 0; i < 4; i++)
#pragma unroll
        for (int j = 0; j < 4; j++) acc[i][j] = 0.f;

    for (int m0 = 0; m0 < NYC; m0 += 64) {
#pragma unroll
        for (int t = tid; t < 4096; t += 256) {
            As[t >> 6][t & 63] = arow[(size_t)(t >> 6) * NYC + m0 + (t & 63)];
            Vs[t >> 6][t & 63] = vb[(size_t)m0 * DHC + t];
        }
        __syncthreads();
#pragma unroll 16
        for (int k = 0; k < 64; k++) {
            float a[4], b_[4];
#pragma unroll
            for (int i = 0; i < 4; i++) a[i] = As[ty * 4 + i][k];
#pragma unroll
            for (int j = 0; j < 4; j++) b_[j] = Vs[k][tx * 4 + j];
#pragma unroll
            for (int i = 0; i < 4; i++)
#pragma unroll
                for (int j = 0; j < 4; j++)
                    acc[i][j] = fmaf(a[i], b_[j], acc[i][j]);
        }
        __syncthreads();
    }

#pragma unroll
    for (int i = 0; i < 4; i++) {
        int n = n0 + ty * 4 + i;
        float* orow = O + (size_t)b * NXC * EC + (size_t)n * EC + h * DHC + tx * 4;
        *(float4*)orow = make_float4(acc[i][0], acc[i][1], acc[i][2], acc[i][3]);
    }
}

// ---------------------------------------------------------------------------
// Residual + LayerNorm: Out[row] = LN(X[row] + R[row]) * g + be
// One block (128 threads) per row of E=512.
// ---------------------------------------------------------------------------
__global__ __launch_bounds__(128) void resln_k(
    const float* __restrict__ X, const float* __restrict__ R,
    const float* __restrict__ g, const float* __restrict__ be,
    float* __restrict__ Out)
{
    __shared__ float sred[4];
    __shared__ float sbc;

    const size_t base = (size_t)blockIdx.x * EC;
    const int tid = threadIdx.x, lane = tid & 31, w = tid >> 5;

    float r[4];
    int col[4];
#pragma unroll
    for (int i = 0; i < 4; i++) {
        col[i] = tid + i * 128;
        r[i] = X[base + col[i]] + R[base + col[i]];
    }

    float s = r[0] + r[1] + r[2] + r[3];
#pragma unroll
    for (int o = 16; o > 0; o >>= 1) s += __shfl_xor_sync(0xffffffffu, s, o);
    if (lane == 0) sred[w] = s;
    __syncthreads();
    if (tid == 0) sbc = sred[0] + sred[1] + sred[2] + sred[3];
    __syncthreads();
    const float mu = sbc * (1.0f / EC);

    float d[4], ss = 0.f;
#pragma unroll
    for (int i = 0; i < 4; i++) { d[i] = r[i] - mu; ss += d[i] * d[i]; }
#pragma unroll
    for (int o = 16; o > 0; o >>= 1) ss += __shfl_xor_sync(0xffffffffu, ss, o);
    if (lane == 0) sred[w] = ss;
    __syncthreads();
    if (tid == 0) sbc = sred[0] + sred[1] + sred[2] + sred[3];
    __syncthreads();
    const float rs = rsqrtf(sbc * (1.0f / EC) + 1e-5f);

#pragma unroll
    for (int i = 0; i < 4; i++)
        Out[base + col[i]] = d[i] * rs * g[col[i]] + be[col[i]];
}

// ---------------------------------------------------------------------------
// Host
// ---------------------------------------------------------------------------
extern "C" void kernel_launch(void* const* d_in, const int* in_sizes, int n_in,
                              void* d_out, int out_size)
{
    (void)in_sizes; (void)n_in; (void)out_size;

    const float* x   = (const float*)d_in[0];
    const float* y   = (const float*)d_in[1];
    const int*   xm  = (const int*)  d_in[2];
    const int*   ym  = (const int*)  d_in[3];
    const float* Wq  = (const float*)d_in[4];
    const float* bq  = (const float*)d_in[5];
    const float* Wk  = (const float*)d_in[6];
    const float* bk  = (const float*)d_in[7];
    const float* Wv  = (const float*)d_in[8];
    const float* bv  = (const float*)d_in[9];
    const float* Wo  = (const float*)d_in[10];
    const float* bo  = (const float*)d_in[11];
    const float* g1  = (const float*)d_in[12];
    const float* be1 = (const float*)d_in[13];
    const float* g2  = (const float*)d_in[14];
    const float* be2 = (const float*)d_in[15];
    const float* W1  = (const float*)d_in[16];
    const float* bf1 = (const float*)d_in[17];
    const float* W2  = (const float*)d_in[18];
    const float* bf2 = (const float*)d_in[19];
    float* out = (float*)d_out;

    float *Q, *K, *V, *O, *O2, *Hb, *F1, *F2, *S, *Aa;
    cudaGetSymbolAddress((void**)&Q,  g_Q);
    cudaGetSymbolAddress((void**)&K,  g_K);
    cudaGetSymbolAddress((void**)&V,  g_V);
    cudaGetSymbolAddress((void**)&O,  g_O);
    cudaGetSymbolAddress((void**)&O2, g_O2);
    cudaGetSymbolAddress((void**)&Hb, g_Hb);
    cudaGetSymbolAddress((void**)&F1, g_F1);
    cudaGetSymbolAddress((void**)&F2, g_F2);
    cudaGetSymbolAddress((void**)&S,  g_S);
    cudaGetSymbolAddress((void**)&Aa, g_A);

    const dim3 gP (EC  / 128, MC / 128);   // N=512 GEMMs
    const dim3 gF1(FFC / 128, MC / 128);   // N=2048 GEMM
    const dim3 gSc(NYC / 64, NXC / 64, BB * HC);
    const dim3 gAV(NXC / 64, BB * HC);

    for (int l = 0; l < LC; l++) {
        const size_t oEE = (size_t)l * EC * EC;
        const size_t oE  = (size_t)l * EC;

        // Q = x @ Wq[l] + bq[l], K = y @ Wk[l] + bk[l]
        gemm_k<<<gP, 256>>>(x, Wq + oEE, bq + oE, Q, MC, EC, EC, 0);
        gemm_k<<<gP, 256>>>(y, Wk + oEE, bk + oE, K, MC, EC, EC, 0);
        // scores (+mask), then softmax + residual-attention chain
        scores_k<<<gSc, 256>>>(Q, K, xm, ym, S);
        softmax_k<<<BB * HC * NXC, 256>>>(S, Aa, l > 0 ? 1 : 0);

        // Everything downstream of attn is DEAD for l < L-1 (x,y never update;
        // only attn_prev chains; final output is last layer's out).
        if (l == LC - 1) {
            gemm_k<<<gP, 256>>>(y, Wv + oEE, bv + oE, V, MC, EC, EC, 0);
            attnv_k<<<gAV, 256>>>(Aa, V, O);
            gemm_k<<<gP, 256>>>(O, Wo + oEE, bo + oE, O2, MC, EC, EC, 0);
            resln_k<<<MC, 128>>>(x, O2, g1 + oE, be1 + oE, Hb);
            gemm_k<<<gF1, 256>>>(Hb, W1 + (size_t)l * EC * FFC, bf1 + (size_t)l * FFC,
                                 F1, MC, EC, FFC, 1 /*gelu*/);
            gemm_k<<<gP, 256>>>(F1, W2 + (size_t)l * FFC * EC, bf2 + oE,
                                F2, MC, FFC, EC, 0);
            resln_k<<<MC, 128>>>(Hb, F2, g2 + oE, be2 + oE, out);
        }
    }
}

// round 5
// speedup vs baseline: 2.7343x; 2.7343x over previous
#include <cuda_runtime.h>
#include <math.h>
#include <stdint.h>

// Problem constants
#define BB   4
#define NXC  1024
#define NYC  1024
#define EC   512
#define HC   8
#define DHC  64
#define LC   4
#define FFC  2048
#define MC   (BB * NXC)

#define BNE  (BB * NXC * EC)                  // 2,097,152
#define BHNN ((size_t)BB * HC * NXC * NYC)    // 33,554,432

// ---------------------------------------------------------------------------
// Scratch (device globals; allocation-free per harness rules)
// ---------------------------------------------------------------------------
__device__ float g_QK[8 * (size_t)BNE];       // Q0,K0,Q1,K1,Q2,K2,Q3,K3 (64MB)
__device__ float g_V [BNE];
__device__ float g_O [BNE];
__device__ float g_O2[BNE];
__device__ float g_Hb[BNE];
__device__ float g_F1[(size_t)MC * FFC];
__device__ float g_F2[BNE];
__device__ float g_S4[4 * BHNN];              // all 4 layers' raw scores (512MB)
__device__ float g_A [BHNN];                  // final summed attention

// ---------------------------------------------------------------------------
// TF32 helpers
// ---------------------------------------------------------------------------
__device__ __forceinline__ float tf32f(float x) {
    uint32_t r;
    asm("cvt.rna.tf32.f32 %0, %1;" : "=r"(r) : "f"(x));
    return __uint_as_float(r);
}

__device__ __forceinline__ void mma8(float* c,
    uint32_t a0, uint32_t a1, uint32_t a2, uint32_t a3,
    uint32_t b0, uint32_t b1)
{
    asm volatile(
        "mma.sync.aligned.m16n8k8.row.col.f32.tf32.tf32.f32 "
        "{%0,%1,%2,%3},{%4,%5,%6,%7},{%8,%9},{%0,%1,%2,%3};"
        : "+f"(c[0]), "+f"(c[1]), "+f"(c[2]), "+f"(c[3])
        : "r"(a0), "r"(a1), "r"(a2), "r"(a3), "r"(b0), "r"(b1));
}

// ---------------------------------------------------------------------------
// TF32 GEMM body: C[M,N] = A[M,K] @ W[K,N] + bias (opt exact GELU)
// block 128x128, BK=16, 256 threads (8 warps as 4x2), warp tile 32x64.
// Double-buffered smem; conflict-free pads (20 / 136).
// ---------------------------------------------------------------------------
__device__ __forceinline__ void gemm_body(
    const float* __restrict__ A, const float* __restrict__ W,
    const float* __restrict__ bias, float* __restrict__ C,
    int K, int N, int dogelu)
{
    __shared__ float As[2][128][20];
    __shared__ float Bs[2][16][136];

    const int tid  = threadIdx.x;
    const int warp = tid >> 5, lane = tid & 31;
    const int wm = warp >> 1, wn = warp & 1;
    const int g  = lane >> 2, tg = lane & 3;
    const int mblk = blockIdx.y * 128, nblk = blockIdx.x * 128;

    const int arow = tid >> 1, acol = (tid & 1) * 8;
    const int brow = tid >> 5, bcol = (tid & 31) * 4;

    const float* Ag = A + (size_t)(mblk + arow) * K + acol;
    const float* Wg = W + (size_t)brow * N + nblk + bcol;

    float acc[2][8][4];
#pragma unroll
    for (int mi = 0; mi < 2; mi++)
#pragma unroll
        for (int ni = 0; ni < 8; ni++)
#pragma unroll
            for (int q = 0; q < 4; q++) acc[mi][ni][q] = 0.f;

    // stage 0
    {
        float4 a0 = *(const float4*)(Ag);
        float4 a1 = *(const float4*)(Ag + 4);
        float4 w0 = *(const float4*)(Wg);
        float4 w1 = *(const float4*)(Wg + (size_t)8 * N);
        As[0][arow][acol+0]=tf32f(a0.x); As[0][arow][acol+1]=tf32f(a0.y);
        As[0][arow][acol+2]=tf32f(a0.z); As[0][arow][acol+3]=tf32f(a0.w);
        As[0][arow][acol+4]=tf32f(a1.x); As[0][arow][acol+5]=tf32f(a1.y);
        As[0][arow][acol+6]=tf32f(a1.z); As[0][arow][acol+7]=tf32f(a1.w);
        Bs[0][brow][bcol+0]=tf32f(w0.x); Bs[0][brow][bcol+1]=tf32f(w0.y);
        Bs[0][brow][bcol+2]=tf32f(w0.z); Bs[0][brow][bcol+3]=tf32f(w0.w);
        Bs[0][brow+8][bcol+0]=tf32f(w1.x); Bs[0][brow+8][bcol+1]=tf32f(w1.y);
        Bs[0][brow+8][bcol+2]=tf32f(w1.z); Bs[0][brow+8][bcol+3]=tf32f(w1.w);
    }
    __syncthreads();

    const int nst = K >> 4;
    for (int s = 0; s < nst; s++) {
        const int buf = s & 1;
        const bool more = (s + 1 < nst);
        float4 pa0, pa1, pw0, pw1;
        if (more) {
            const float* Ap = Ag + (s + 1) * 16;
            const float* Wp = Wg + (size_t)(s + 1) * 16 * N;
            pa0 = *(const float4*)Ap; pa1 = *(const float4*)(Ap + 4);
            pw0 = *(const float4*)Wp; pw1 = *(const float4*)(Wp + (size_t)8 * N);
        }

#pragma unroll
        for (int kk = 0; kk < 16; kk += 8) {
            uint32_t af[2][4];
#pragma unroll
            for (int mi = 0; mi < 2; mi++) {
                int m = wm * 32 + mi * 16 + g;
                af[mi][0] = __float_as_uint(As[buf][m    ][kk + tg]);
                af[mi][1] = __float_as_uint(As[buf][m + 8][kk + tg]);
                af[mi][2] = __float_as_uint(As[buf][m    ][kk + tg + 4]);
                af[mi][3] = __float_as_uint(As[buf][m + 8][kk + tg + 4]);
            }
            uint32_t bf[8][2];
#pragma unroll
            for (int ni = 0; ni < 8; ni++) {
                int n = wn * 64 + ni * 8 + g;
                bf[ni][0] = __float_as_uint(Bs[buf][kk + tg    ][n]);
                bf[ni][1] = __float_as_uint(Bs[buf][kk + tg + 4][n]);
            }
#pragma unroll
            for (int mi = 0; mi < 2; mi++)
#pragma unroll
                for (int ni = 0; ni < 8; ni++)
                    mma8(acc[mi][ni], af[mi][0], af[mi][1], af[mi][2], af[mi][3],
                         bf[ni][0], bf[ni][1]);
        }

        if (more) {
            const int nb = buf ^ 1;
            As[nb][arow][acol+0]=tf32f(pa0.x); As[nb][arow][acol+1]=tf32f(pa0.y);
            As[nb][arow][acol+2]=tf32f(pa0.z); As[nb][arow][acol+3]=tf32f(pa0.w);
            As[nb][arow][acol+4]=tf32f(pa1.x); As[nb][arow][acol+5]=tf32f(pa1.y);
            As[nb][arow][acol+6]=tf32f(pa1.z); As[nb][arow][acol+7]=tf32f(pa1.w);
            Bs[nb][brow][bcol+0]=tf32f(pw0.x); Bs[nb][brow][bcol+1]=tf32f(pw0.y);
            Bs[nb][brow][bcol+2]=tf32f(pw0.z); Bs[nb][brow][bcol+3]=tf32f(pw0.w);
            Bs[nb][brow+8][bcol+0]=tf32f(pw1.x); Bs[nb][brow+8][bcol+1]=tf32f(pw1.y);
            Bs[nb][brow+8][bcol+2]=tf32f(pw1.z); Bs[nb][brow+8][bcol+3]=tf32f(pw1.w);
            __syncthreads();
        }
    }

    // epilogue
#pragma unroll
    for (int mi = 0; mi < 2; mi++) {
        int r0 = mblk + wm * 32 + mi * 16 + g;
#pragma unroll
        for (int ni = 0; ni < 8; ni++) {
            int c = nblk + wn * 64 + ni * 8 + tg * 2;
            float b0 = bias[c], b1 = bias[c + 1];
            float v0 = acc[mi][ni][0] + b0, v1 = acc[mi][ni][1] + b1;
            float v2 = acc[mi][ni][2] + b0, v3 = acc[mi][ni][3] + b1;
            if (dogelu) {
                v0 = 0.5f * v0 * (1.0f + erff(v0 * 0.70710678118654752f));
                v1 = 0.5f * v1 * (1.0f + erff(v1 * 0.70710678118654752f));
                v2 = 0.5f * v2 * (1.0f + erff(v2 * 0.70710678118654752f));
                v3 = 0.5f * v3 * (1.0f + erff(v3 * 0.70710678118654752f));
            }
            *(float2*)&C[(size_t)r0 * N + c]       = make_float2(v0, v1);
            *(float2*)&C[(size_t)(r0 + 8) * N + c] = make_float2(v2, v3);
        }
    }
}

__global__ __launch_bounds__(256) void gemm_k(
    const float* __restrict__ A, const float* __restrict__ W,
    const float* __restrict__ bias, float* __restrict__ C,
    int K, int N, int dogelu)
{
    gemm_body(A, W, bias, C, K, N, dogelu);
}

// Batched projections: z = 0..7 -> (layer l = z/2, Q/K), z = 8 -> V of layer 3.
__global__ __launch_bounds__(256) void proj_k(
    const float* __restrict__ x, const float* __restrict__ y,
    const float* __restrict__ Wq, const float* __restrict__ bq,
    const float* __restrict__ Wk, const float* __restrict__ bk,
    const float* __restrict__ Wv, const float* __restrict__ bv,
    float* __restrict__ QK, float* __restrict__ V)
{
    const int z = blockIdx.z;
    const float *A, *W, *Bi;
    float* C;
    if (z < 8) {
        int l = z >> 1, isK = z & 1;
        A  = isK ? y : x;
        W  = (isK ? Wk : Wq) + (size_t)l * EC * EC;
        Bi = (isK ? bk : bq) + (size_t)l * EC;
        C  = QK + (size_t)z * BNE;
    } else {
        A = y; W = Wv + (size_t)3 * EC * EC; Bi = bv + (size_t)3 * EC; C = V;
    }
    gemm_body(A, W, Bi, C, EC, EC, 0);
}

// ---------------------------------------------------------------------------
// Scores (all layers, all heads in one launch): S = (Q @ K^T)*0.125, masked.
// Head blocks are contiguous [1024 x 64] per (b,h) (plain-reshape semantics).
// Grid: (NY/128, NX/128, 4*32). Block 128x128 over scores, K-dim 64.
// ---------------------------------------------------------------------------
__global__ __launch_bounds__(256) void scores_k(
    const float* __restrict__ QK, const int* __restrict__ xm,
    const int* __restrict__ ym, float* __restrict__ S4)
{
    __shared__ float Qs[2][128][20];
    __shared__ float Ks[2][128][20];

    const int z = blockIdx.z;
    const int l = z >> 5, bh = z & 31, b = bh >> 3, h = bh & 7;
    const float* Qb = QK + (size_t)(2 * l)     * BNE + (size_t)b * NXC * EC + (size_t)h * NXC * DHC;
    const float* Kb = QK + (size_t)(2 * l + 1) * BNE + (size_t)b * NYC * EC + (size_t)h * NYC * DHC;

    const int mblk = blockIdx.y * 128;   // NX rows
    const int nblk = blockIdx.x * 128;   // NY cols
    const int tid  = threadIdx.x;
    const int warp = tid >> 5, lane = tid & 31;
    const int wm = warp >> 1, wn = warp & 1;
    const int g = lane >> 2, tg = lane & 3;
    const int arow = tid >> 1, acol = (tid & 1) * 8;

    float acc[2][8][4];
#pragma unroll
    for (int mi = 0; mi < 2; mi++)
#pragma unroll
        for (int ni = 0; ni < 8; ni++)
#pragma unroll
            for (int q = 0; q < 4; q++) acc[mi][ni][q] = 0.f;

    // stage 0 (k chunk 0..15)
    {
        float4 q0 = *(const float4*)(Qb + (size_t)(mblk + arow) * DHC + acol);
        float4 q1 = *(const float4*)(Qb + (size_t)(mblk + arow) * DHC + acol + 4);
        float4 k0 = *(const float4*)(Kb + (size_t)(nblk + arow) * DHC + acol);
        float4 k1 = *(const float4*)(Kb + (size_t)(nblk + arow) * DHC + acol + 4);
        Qs[0][arow][acol+0]=tf32f(q0.x); Qs[0][arow][acol+1]=tf32f(q0.y);
        Qs[0][arow][acol+2]=tf32f(q0.z); Qs[0][arow][acol+3]=tf32f(q0.w);
        Qs[0][arow][acol+4]=tf32f(q1.x); Qs[0][arow][acol+5]=tf32f(q1.y);
        Qs[0][arow][acol+6]=tf32f(q1.z); Qs[0][arow][acol+7]=tf32f(q1.w);
        Ks[0][arow][acol+0]=tf32f(k0.x); Ks[0][arow][acol+1]=tf32f(k0.y);
        Ks[0][arow][acol+2]=tf32f(k0.z); Ks[0][arow][acol+3]=tf32f(k0.w);
        Ks[0][arow][acol+4]=tf32f(k1.x); Ks[0][arow][acol+5]=tf32f(k1.y);
        Ks[0][arow][acol+6]=tf32f(k1.z); Ks[0][arow][acol+7]=tf32f(k1.w);
    }
    __syncthreads();

    for (int s = 0; s < 4; s++) {
        const int buf = s & 1;
        const bool more = (s + 1 < 4);
        float4 pq0, pq1, pk0, pk1;
        if (more) {
            int k0 = (s + 1) * 16;
            pq0 = *(const float4*)(Qb + (size_t)(mblk + arow) * DHC + k0 + acol);
            pq1 = *(const float4*)(Qb + (size_t)(mblk + arow) * DHC + k0 + acol + 4);
            pk0 = *(const float4*)(Kb + (size_t)(nblk + arow) * DHC + k0 + acol);
            pk1 = *(const float4*)(Kb + (size_t)(nblk + arow) * DHC + k0 + acol + 4);
        }

#pragma unroll
        for (int kk = 0; kk < 16; kk += 8) {
            uint32_t af[2][4];
#pragma unroll
            for (int mi = 0; mi < 2; mi++) {
                int m = wm * 32 + mi * 16 + g;
                af[mi][0] = __float_as_uint(Qs[buf][m    ][kk + tg]);
                af[mi][1] = __float_as_uint(Qs[buf][m + 8][kk + tg]);
                af[mi][2] = __float_as_uint(Qs[buf][m    ][kk + tg + 4]);
                af[mi][3] = __float_as_uint(Qs[buf][m + 8][kk + tg + 4]);
            }
            uint32_t bf[8][2];
#pragma unroll
            for (int ni = 0; ni < 8; ni++) {
                int n = wn * 64 + ni * 8 + g;
                bf[ni][0] = __float_as_uint(Ks[buf][n][kk + tg]);
                bf[ni][1] = __float_as_uint(Ks[buf][n][kk + tg + 4]);
            }
#pragma unroll
            for (int mi = 0; mi < 2; mi++)
#pragma unroll
                for (int ni = 0; ni < 8; ni++)
                    mma8(acc[mi][ni], af[mi][0], af[mi][1], af[mi][2], af[mi][3],
                         bf[ni][0], bf[ni][1]);
        }

        if (more) {
            const int nb = buf ^ 1;
            Qs[nb][arow][acol+0]=tf32f(pq0.x); Qs[nb][arow][acol+1]=tf32f(pq0.y);
            Qs[nb][arow][acol+2]=tf32f(pq0.z); Qs[nb][arow][acol+3]=tf32f(pq0.w);
            Qs[nb][arow][acol+4]=tf32f(pq1.x); Qs[nb][arow][acol+5]=tf32f(pq1.y);
            Qs[nb][arow][acol+6]=tf32f(pq1.z); Qs[nb][arow][acol+7]=tf32f(pq1.w);
            Ks[nb][arow][acol+0]=tf32f(pk0.x); Ks[nb][arow][acol+1]=tf32f(pk0.y);
            Ks[nb][arow][acol+2]=tf32f(pk0.z); Ks[nb][arow][acol+3]=tf32f(pk0.w);
            Ks[nb][arow][acol+4]=tf32f(pk1.x); Ks[nb][arow][acol+5]=tf32f(pk1.y);
            Ks[nb][arow][acol+6]=tf32f(pk1.z); Ks[nb][arow][acol+7]=tf32f(pk1.w);
            __syncthreads();
        }
    }

    // epilogue: scale + mask + store
    float* Sl = S4 + (size_t)l * BHNN + (size_t)bh * NXC * NYC;
#pragma unroll
    for (int mi = 0; mi < 2; mi++) {
        int r0 = mblk + wm * 32 + mi * 16 + g;
        int xr0 = xm[b * NXC + r0], xr1 = xm[b * NXC + r0 + 8];
#pragma unroll
        for (int ni = 0; ni < 8; ni++) {
            int c = nblk + wn * 64 + ni * 8 + tg * 2;
            int yc0 = ym[b * NYC + c], yc1 = ym[b * NYC + c + 1];
            float v0 = (xr0 && yc0) ? acc[mi][ni][0] * 0.125f : -1e9f;
            float v1 = (xr0 && yc1) ? acc[mi][ni][1] * 0.125f : -1e9f;
            float v2 = (xr1 && yc0) ? acc[mi][ni][2] * 0.125f : -1e9f;
            float v3 = (xr1 && yc1) ? acc[mi][ni][3] * 0.125f : -1e9f;
            *(float2*)&Sl[(size_t)r0 * NYC + c]       = make_float2(v0, v1);
            *(float2*)&Sl[(size_t)(r0 + 8) * NYC + c] = make_float2(v2, v3);
        }
    }
}

// ---------------------------------------------------------------------------
// Fused softmax-sum: A[row] = sum_{l=0..3} softmax(S_l[row]).
// (a_l = softmax_l + a_{l-1} ==> a_3 = sum of softmaxes; only a_3 is consumed.)
// One block (256 threads) per row of 1024.
// ---------------------------------------------------------------------------
__global__ __launch_bounds__(256) void softmax4_k(
    const float* __restrict__ S4, float* __restrict__ A)
{
    __shared__ float sred[8];
    __shared__ float sbc;

    const size_t base = (size_t)blockIdx.x * NYC;
    const int tid = threadIdx.x, lane = tid & 31, w = tid >> 5;

    float acc[4] = {0.f, 0.f, 0.f, 0.f};

#pragma unroll
    for (int l = 0; l < 4; l++) {
        const float* S = S4 + (size_t)l * BHNN;
        float v[4];
#pragma unroll
        for (int i = 0; i < 4; i++) v[i] = S[base + tid + i * 256];

        float m = fmaxf(fmaxf(v[0], v[1]), fmaxf(v[2], v[3]));
#pragma unroll
        for (int o = 16; o > 0; o >>= 1) m = fmaxf(m, __shfl_xor_sync(0xffffffffu, m, o));
        if (lane == 0) sred[w] = m;
        __syncthreads();
        if (tid == 0) {
            float t = sred[0];
#pragma unroll
            for (int i = 1; i < 8; i++) t = fmaxf(t, sred[i]);
            sbc = t;
        }
        __syncthreads();
        const float bm = sbc;

        float p[4], s = 0.f;
#pragma unroll
        for (int i = 0; i < 4; i++) { p[i] = __expf(v[i] - bm); s += p[i]; }
#pragma unroll
        for (int o = 16; o > 0; o >>= 1) s += __shfl_xor_sync(0xffffffffu, s, o);
        if (lane == 0) sred[w] = s;
        __syncthreads();
        if (tid == 0) {
            float t = 0.f;
#pragma unroll
            for (int i = 0; i < 8; i++) t += sred[i];
            sbc = t;
        }
        __syncthreads();
        const float inv = 1.0f / sbc;
#pragma unroll
        for (int i = 0; i < 4; i++) acc[i] += p[i] * inv;
        __syncthreads();   // protect sred/sbc reuse next l
    }

#pragma unroll
    for (int i = 0; i < 4; i++) A[base + tid + i * 256] = acc[i];
}

// ---------------------------------------------------------------------------
// O = attn @ V (tf32), written in transposed layout O[b, n, h*64 + d].
// Block 128x64, 8 warps (warp tile 16x64), K-dim 1024 in 64 stages of 16.
// Grid: (NX/128, B*H).
// ---------------------------------------------------------------------------
__global__ __launch_bounds__(256) void attnv_k(
    const float* __restrict__ Aa, const float* __restrict__ V,
    float* __restrict__ O)
{
    __shared__ float As_[2][128][20];
    __shared__ float Vs[2][16][72];

    const int bh = blockIdx.y, b = bh >> 3, h = bh & 7;
    const int mblk = blockIdx.x * 128;
    const int tid = threadIdx.x;
    const int warp = tid >> 5, lane = tid & 31;
    const int g = lane >> 2, tg = lane & 3;

    const float* Ab = Aa + ((size_t)bh * NXC + mblk) * NYC;
    const float* Vb = V + (size_t)b * NYC * EC + (size_t)h * NYC * DHC;

    const int arow = tid >> 1, acol = (tid & 1) * 8;
    const int vrow = tid >> 4, vcol = (tid & 15) * 4;

    float acc[8][4];
#pragma unroll
    for (int ni = 0; ni < 8; ni++)
#pragma unroll
        for (int q = 0; q < 4; q++) acc[ni][q] = 0.f;

    {
        float4 a0 = *(const float4*)(Ab + (size_t)arow * NYC + acol);
        float4 a1 = *(const float4*)(Ab + (size_t)arow * NYC + acol + 4);
        float4 v0 = *(const float4*)(Vb + (size_t)vrow * DHC + vcol);
        As_[0][arow][acol+0]=tf32f(a0.x); As_[0][arow][acol+1]=tf32f(a0.y);
        As_[0][arow][acol+2]=tf32f(a0.z); As_[0][arow][acol+3]=tf32f(a0.w);
        As_[0][arow][acol+4]=tf32f(a1.x); As_[0][arow][acol+5]=tf32f(a1.y);
        As_[0][arow][acol+6]=tf32f(a1.z); As_[0][arow][acol+7]=tf32f(a1.w);
        Vs[0][vrow][vcol+0]=tf32f(v0.x); Vs[0][vrow][vcol+1]=tf32f(v0.y);
        Vs[0][vrow][vcol+2]=tf32f(v0.z); Vs[0][vrow][vcol+3]=tf32f(v0.w);
    }
    __syncthreads();

    for (int s = 0; s < 64; s++) {
        const int buf = s & 1;
        const bool more = (s + 1 < 64);
        float4 pa0, pa1, pv0;
        if (more) {
            int k0 = (s + 1) * 16;
            pa0 = *(const float4*)(Ab + (size_t)arow * NYC + k0 + acol);
            pa1 = *(const float4*)(Ab + (size_t)arow * NYC + k0 + acol + 4);
            pv0 = *(const float4*)(Vb + (size_t)(k0 + vrow) * DHC + vcol);
        }

#pragma unroll
        for (int kk = 0; kk < 16; kk += 8) {
            int m = warp * 16 + g;
            uint32_t a0 = __float_as_uint(As_[buf][m    ][kk + tg]);
            uint32_t a1 = __float_as_uint(As_[buf][m + 8][kk + tg]);
            uint32_t a2 = __float_as_uint(As_[buf][m    ][kk + tg + 4]);
            uint32_t a3 = __float_as_uint(As_[buf][m + 8][kk + tg + 4]);
#pragma unroll
            for (int ni = 0; ni < 8; ni++) {
                int n = ni * 8 + g;
                uint32_t b0 = __float_as_uint(Vs[buf][kk + tg    ][n]);
                uint32_t b1 = __float_as_uint(Vs[buf][kk + tg + 4][n]);
                mma8(acc[ni], a0, a1, a2, a3, b0, b1);
            }
        }

        if (more) {
            const int nb = buf ^ 1;
            As_[nb][arow][acol+0]=tf32f(pa0.x); As_[nb][arow][acol+1]=tf32f(pa0.y);
            As_[nb][arow][acol+2]=tf32f(pa0.z); As_[nb][arow][acol+3]=tf32f(pa0.w);
            As_[nb][arow][acol+4]=tf32f(pa1.x); As_[nb][arow][acol+5]=tf32f(pa1.y);
            As_[nb][arow][acol+6]=tf32f(pa1.z); As_[nb][arow][acol+7]=tf32f(pa1.w);
            Vs[nb][vrow][vcol+0]=tf32f(pv0.x); Vs[nb][vrow][vcol+1]=tf32f(pv0.y);
            Vs[nb][vrow][vcol+2]=tf32f(pv0.z); Vs[nb][vrow][vcol+3]=tf32f(pv0.w);
            __syncthreads();
        }
    }

    const int r0 = mblk + warp * 16 + g;
    float* Ob = O + (size_t)b * NXC * EC + (size_t)h * DHC;
#pragma unroll
    for (int ni = 0; ni < 8; ni++) {
        int c = ni * 8 + tg * 2;
        *(float2*)&Ob[(size_t)r0 * EC + c]       = make_float2(acc[ni][0], acc[ni][1]);
        *(float2*)&Ob[(size_t)(r0 + 8) * EC + c] = make_float2(acc[ni][2], acc[ni][3]);
    }
}

// ---------------------------------------------------------------------------
// Residual + LayerNorm: Out[row] = LN(X[row] + R[row]) * g + be
// ---------------------------------------------------------------------------
__global__ __launch_bounds__(128) void resln_k(
    const float* __restrict__ X, const float* __restrict__ R,
    const float* __restrict__ g, const float* __restrict__ be,
    float* __restrict__ Out)
{
    __shared__ float sred[4];
    __shared__ float sbc;

    const size_t base = (size_t)blockIdx.x * EC;
    const int tid = threadIdx.x, lane = tid & 31, w = tid >> 5;

    float r[4];
    int col[4];
#pragma unroll
    for (int i = 0; i < 4; i++) {
        col[i] = tid + i * 128;
        r[i] = X[base + col[i]] + R[base + col[i]];
    }

    float s = r[0] + r[1] + r[2] + r[3];
#pragma unroll
    for (int o = 16; o > 0; o >>= 1) s += __shfl_xor_sync(0xffffffffu, s, o);
    if (lane == 0) sred[w] = s;
    __syncthreads();
    if (tid == 0) sbc = sred[0] + sred[1] + sred[2] + sred[3];
    __syncthreads();
    const float mu = sbc * (1.0f / EC);

    float d[4], ss = 0.f;
#pragma unroll
    for (int i = 0; i < 4; i++) { d[i] = r[i] - mu; ss += d[i] * d[i]; }
#pragma unroll
    for (int o = 16; o > 0; o >>= 1) ss += __shfl_xor_sync(0xffffffffu, ss, o);
    if (lane == 0) sred[w] = ss;
    __syncthreads();
    if (tid == 0) sbc = sred[0] + sred[1] + sred[2] + sred[3];
    __syncthreads();
    const float rs = rsqrtf(sbc * (1.0f / EC) + 1e-5f);

#pragma unroll
    for (int i = 0; i < 4; i++)
        Out[base + col[i]] = d[i] * rs * g[col[i]] + be[col[i]];
}

// ---------------------------------------------------------------------------
// Host
// ---------------------------------------------------------------------------
extern "C" void kernel_launch(void* const* d_in, const int* in_sizes, int n_in,
                              void* d_out, int out_size)
{
    (void)in_sizes; (void)n_in; (void)out_size;

    const float* x   = (const float*)d_in[0];
    const float* y   = (const float*)d_in[1];
    const int*   xm  = (const int*)  d_in[2];
    const int*   ym  = (const int*)  d_in[3];
    const float* Wq  = (const float*)d_in[4];
    const float* bq  = (const float*)d_in[5];
    const float* Wk  = (const float*)d_in[6];
    const float* bk  = (const float*)d_in[7];
    const float* Wv  = (const float*)d_in[8];
    const float* bv  = (const float*)d_in[9];
    const float* Wo  = (const float*)d_in[10];
    const float* bo  = (const float*)d_in[11];
    const float* g1  = (const float*)d_in[12];
    const float* be1 = (const float*)d_in[13];
    const float* g2  = (const float*)d_in[14];
    const float* be2 = (const float*)d_in[15];
    const float* W1  = (const float*)d_in[16];
    const float* bf1 = (const float*)d_in[17];
    const float* W2  = (const float*)d_in[18];
    const float* bf2 = (const float*)d_in[19];
    float* out = (float*)d_out;

    float *QK, *V, *O, *O2, *Hb, *F1, *F2, *S4, *Aa;
    cudaGetSymbolAddress((void**)&QK, g_QK);
    cudaGetSymbolAddress((void**)&V,  g_V);
    cudaGetSymbolAddress((void**)&O,  g_O);
    cudaGetSymbolAddress((void**)&O2, g_O2);
    cudaGetSymbolAddress((void**)&Hb, g_Hb);
    cudaGetSymbolAddress((void**)&F1, g_F1);
    cudaGetSymbolAddress((void**)&F2, g_F2);
    cudaGetSymbolAddress((void**)&S4, g_S4);
    cudaGetSymbolAddress((void**)&Aa, g_A);

    // 1. All Q_l, K_l projections + V_3 in one launch (9 GEMM slices)
    proj_k<<<dim3(4, 32, 9), 256>>>(x, y, Wq, bq, Wk, bk, Wv, bv, QK, V);
    // 2. All layers' masked scores in one launch
    scores_k<<<dim3(8, 8, 128), 256>>>(QK, xm, ym, S4);
    // 3. Single fused softmax-sum (a_3 = sum_l softmax(S_l))
    softmax4_k<<<BB * HC * NXC, 256>>>(S4, Aa);
    // 4. Tail (only last layer's downstream path is live)
    attnv_k<<<dim3(8, 32), 256>>>(Aa, V, O);
    gemm_k<<<dim3(4, 32), 256>>>(O, Wo + (size_t)3 * EC * EC, bo + 3 * EC, O2, EC, EC, 0);
    resln_k<<<MC, 128>>>(x, O2, g1 + 3 * EC, be1 + 3 * EC, Hb);
    gemm_k<<<dim3(16, 32), 256>>>(Hb, W1 + (size_t)3 * EC * FFC, bf1 + (size_t)3 * FFC, F1, EC, FFC, 1);
    gemm_k<<<dim3(4, 32), 256>>>(F1, W2 + (size_t)3 * FFC * EC, bf2 + 3 * EC, F2, FFC, EC, 0);
    resln_k<<<MC, 128>>>(Hb, F2, g2 + 3 * EC, be2 + 3 * EC, out);
}

// round 6
// speedup vs baseline: 2.7566x; 1.0082x over previous
#include <cuda_runtime.h>
#include <cuda_fp16.h>
#include <math.h>
#include <stdint.h>

// Problem constants
#define BB   4
#define NXC  1024
#define NYC  1024
#define EC   512
#define HC   8
#define DHC  64
#define LC   4
#define FFC  2048
#define MC   (BB * NXC)

#define BNE  (BB * NXC * EC)                  // 2,097,152
#define BHNN ((size_t)BB * HC * NXC * NYC)    // 33,554,432

// ---------------------------------------------------------------------------
// Scratch (device globals; allocation-free per harness rules)
// ---------------------------------------------------------------------------
__device__ float g_QK[8 * (size_t)BNE];       // Q0,K0,Q1,K1,Q2,K2,Q3,K3 (64MB)
__device__ float g_V [BNE];
__device__ float g_O [BNE];
__device__ float g_O2[BNE];
__device__ float g_Hb[BNE];
__device__ float g_F1[(size_t)MC * FFC];
__device__ float g_F2[BNE];
__device__ __half g_S4[4 * BHNN];             // all 4 layers' raw scores (fp16, 256MB)
__device__ float g_A [BHNN];                  // final summed attention

#define MASKED_H (-30000.0f)

// ---------------------------------------------------------------------------
// TF32 helpers
// ---------------------------------------------------------------------------
__device__ __forceinline__ float tf32f(float x) {
    uint32_t r;
    asm("cvt.rna.tf32.f32 %0, %1;" : "=r"(r) : "f"(x));
    return __uint_as_float(r);
}

__device__ __forceinline__ void mma8(float* c,
    uint32_t a0, uint32_t a1, uint32_t a2, uint32_t a3,
    uint32_t b0, uint32_t b1)
{
    asm volatile(
        "mma.sync.aligned.m16n8k8.row.col.f32.tf32.tf32.f32 "
        "{%0,%1,%2,%3},{%4,%5,%6,%7},{%8,%9},{%0,%1,%2,%3};"
        : "+f"(c[0]), "+f"(c[1]), "+f"(c[2]), "+f"(c[3])
        : "r"(a0), "r"(a1), "r"(a2), "r"(a3), "r"(b0), "r"(b1));
}

// ---------------------------------------------------------------------------
// TF32 GEMM body: C[M,N] = A[M,K] @ W[K,N] + bias (opt exact GELU)
// block 128x128, BK=16, 256 threads (8 warps as 4x2), warp tile 32x64.
// ---------------------------------------------------------------------------
__device__ __forceinline__ void gemm_body(
    const float* __restrict__ A, const float* __restrict__ W,
    const float* __restrict__ bias, float* __restrict__ C,
    int K, int N, int dogelu)
{
    __shared__ float As[2][128][20];
    __shared__ float Bs[2][16][136];

    const int tid  = threadIdx.x;
    const int warp = tid >> 5, lane = tid & 31;
    const int wm = warp >> 1, wn = warp & 1;
    const int g  = lane >> 2, tg = lane & 3;
    const int mblk = blockIdx.y * 128, nblk = blockIdx.x * 128;

    const int arow = tid >> 1, acol = (tid & 1) * 8;
    const int brow = tid >> 5, bcol = (tid & 31) * 4;

    const float* Ag = A + (size_t)(mblk + arow) * K + acol;
    const float* Wg = W + (size_t)brow * N + nblk + bcol;

    float acc[2][8][4];
#pragma unroll
    for (int mi = 0; mi < 2; mi++)
#pragma unroll
        for (int ni = 0; ni < 8; ni++)
#pragma unroll
            for (int q = 0; q < 4; q++) acc[mi][ni][q] = 0.f;

    {
        float4 a0 = *(const float4*)(Ag);
        float4 a1 = *(const float4*)(Ag + 4);
        float4 w0 = *(const float4*)(Wg);
        float4 w1 = *(const float4*)(Wg + (size_t)8 * N);
        As[0][arow][acol+0]=tf32f(a0.x); As[0][arow][acol+1]=tf32f(a0.y);
        As[0][arow][acol+2]=tf32f(a0.z); As[0][arow][acol+3]=tf32f(a0.w);
        As[0][arow][acol+4]=tf32f(a1.x); As[0][arow][acol+5]=tf32f(a1.y);
        As[0][arow][acol+6]=tf32f(a1.z); As[0][arow][acol+7]=tf32f(a1.w);
        Bs[0][brow][bcol+0]=tf32f(w0.x); Bs[0][brow][bcol+1]=tf32f(w0.y);
        Bs[0][brow][bcol+2]=tf32f(w0.z); Bs[0][brow][bcol+3]=tf32f(w0.w);
        Bs[0][brow+8][bcol+0]=tf32f(w1.x); Bs[0][brow+8][bcol+1]=tf32f(w1.y);
        Bs[0][brow+8][bcol+2]=tf32f(w1.z); Bs[0][brow+8][bcol+3]=tf32f(w1.w);
    }
    __syncthreads();

    const int nst = K >> 4;
    for (int s = 0; s < nst; s++) {
        const int buf = s & 1;
        const bool more = (s + 1 < nst);
        float4 pa0, pa1, pw0, pw1;
        if (more) {
            const float* Ap = Ag + (s + 1) * 16;
            const float* Wp = Wg + (size_t)(s + 1) * 16 * N;
            pa0 = *(const float4*)Ap; pa1 = *(const float4*)(Ap + 4);
            pw0 = *(const float4*)Wp; pw1 = *(const float4*)(Wp + (size_t)8 * N);
        }

#pragma unroll
        for (int kk = 0; kk < 16; kk += 8) {
            uint32_t af[2][4];
#pragma unroll
            for (int mi = 0; mi < 2; mi++) {
                int m = wm * 32 + mi * 16 + g;
                af[mi][0] = __float_as_uint(As[buf][m    ][kk + tg]);
                af[mi][1] = __float_as_uint(As[buf][m + 8][kk + tg]);
                af[mi][2] = __float_as_uint(As[buf][m    ][kk + tg + 4]);
                af[mi][3] = __float_as_uint(As[buf][m + 8][kk + tg + 4]);
            }
            uint32_t bf[8][2];
#pragma unroll
            for (int ni = 0; ni < 8; ni++) {
                int n = wn * 64 + ni * 8 + g;
                bf[ni][0] = __float_as_uint(Bs[buf][kk + tg    ][n]);
                bf[ni][1] = __float_as_uint(Bs[buf][kk + tg + 4][n]);
            }
#pragma unroll
            for (int mi = 0; mi < 2; mi++)
#pragma unroll
                for (int ni = 0; ni < 8; ni++)
                    mma8(acc[mi][ni], af[mi][0], af[mi][1], af[mi][2], af[mi][3],
                         bf[ni][0], bf[ni][1]);
        }

        if (more) {
            const int nb = buf ^ 1;
            As[nb][arow][acol+0]=tf32f(pa0.x); As[nb][arow][acol+1]=tf32f(pa0.y);
            As[nb][arow][acol+2]=tf32f(pa0.z); As[nb][arow][acol+3]=tf32f(pa0.w);
            As[nb][arow][acol+4]=tf32f(pa1.x); As[nb][arow][acol+5]=tf32f(pa1.y);
            As[nb][arow][acol+6]=tf32f(pa1.z); As[nb][arow][acol+7]=tf32f(pa1.w);
            Bs[nb][brow][bcol+0]=tf32f(pw0.x); Bs[nb][brow][bcol+1]=tf32f(pw0.y);
            Bs[nb][brow][bcol+2]=tf32f(pw0.z); Bs[nb][brow][bcol+3]=tf32f(pw0.w);
            Bs[nb][brow+8][bcol+0]=tf32f(pw1.x); Bs[nb][brow+8][bcol+1]=tf32f(pw1.y);
            Bs[nb][brow+8][bcol+2]=tf32f(pw1.z); Bs[nb][brow+8][bcol+3]=tf32f(pw1.w);
            __syncthreads();
        }
    }

#pragma unroll
    for (int mi = 0; mi < 2; mi++) {
        int r0 = mblk + wm * 32 + mi * 16 + g;
#pragma unroll
        for (int ni = 0; ni < 8; ni++) {
            int c = nblk + wn * 64 + ni * 8 + tg * 2;
            float b0 = bias[c], b1 = bias[c + 1];
            float v0 = acc[mi][ni][0] + b0, v1 = acc[mi][ni][1] + b1;
            float v2 = acc[mi][ni][2] + b0, v3 = acc[mi][ni][3] + b1;
            if (dogelu) {
                v0 = 0.5f * v0 * (1.0f + erff(v0 * 0.70710678118654752f));
                v1 = 0.5f * v1 * (1.0f + erff(v1 * 0.70710678118654752f));
                v2 = 0.5f * v2 * (1.0f + erff(v2 * 0.70710678118654752f));
                v3 = 0.5f * v3 * (1.0f + erff(v3 * 0.70710678118654752f));
            }
            *(float2*)&C[(size_t)r0 * N + c]       = make_float2(v0, v1);
            *(float2*)&C[(size_t)(r0 + 8) * N + c] = make_float2(v2, v3);
        }
    }
}

__global__ __launch_bounds__(256) void gemm_k(
    const float* __restrict__ A, const float* __restrict__ W,
    const float* __restrict__ bias, float* __restrict__ C,
    int K, int N, int dogelu)
{
    gemm_body(A, W, bias, C, K, N, dogelu);
}

// Batched projections: z = 0..7 -> (layer l = z/2, Q/K), z = 8 -> V of layer 3.
__global__ __launch_bounds__(256) void proj_k(
    const float* __restrict__ x, const float* __restrict__ y,
    const float* __restrict__ Wq, const float* __restrict__ bq,
    const float* __restrict__ Wk, const float* __restrict__ bk,
    const float* __restrict__ Wv, const float* __restrict__ bv,
    float* __restrict__ QK, float* __restrict__ V)
{
    const int z = blockIdx.z;
    const float *A, *W, *Bi;
    float* C;
    if (z < 8) {
        int l = z >> 1, isK = z & 1;
        A  = isK ? y : x;
        W  = (isK ? Wk : Wq) + (size_t)l * EC * EC;
        Bi = (isK ? bk : bq) + (size_t)l * EC;
        C  = QK + (size_t)z * BNE;
    } else {
        A = y; W = Wv + (size_t)3 * EC * EC; Bi = bv + (size_t)3 * EC; C = V;
    }
    gemm_body(A, W, Bi, C, EC, EC, 0);
}

// ---------------------------------------------------------------------------
// Scores (all layers/heads, one launch): S = (Q @ K^T)*0.125, masked, fp16 out.
// Grid: (NY/128, NX/128, 4*32).
// ---------------------------------------------------------------------------
__global__ __launch_bounds__(256) void scores_k(
    const float* __restrict__ QK, const int* __restrict__ xm,
    const int* __restrict__ ym, __half* __restrict__ S4)
{
    __shared__ float Qs[2][128][20];
    __shared__ float Ks[2][128][20];

    const int z = blockIdx.z;
    const int l = z >> 5, bh = z & 31, b = bh >> 3, h = bh & 7;
    const float* Qb = QK + (size_t)(2 * l)     * BNE + (size_t)b * NXC * EC + (size_t)h * NXC * DHC;
    const float* Kb = QK + (size_t)(2 * l + 1) * BNE + (size_t)b * NYC * EC + (size_t)h * NYC * DHC;

    const int mblk = blockIdx.y * 128;
    const int nblk = blockIdx.x * 128;
    const int tid  = threadIdx.x;
    const int warp = tid >> 5, lane = tid & 31;
    const int wm = warp >> 1, wn = warp & 1;
    const int g = lane >> 2, tg = lane & 3;
    const int arow = tid >> 1, acol = (tid & 1) * 8;

    float acc[2][8][4];
#pragma unroll
    for (int mi = 0; mi < 2; mi++)
#pragma unroll
        for (int ni = 0; ni < 8; ni++)
#pragma unroll
            for (int q = 0; q < 4; q++) acc[mi][ni][q] = 0.f;

    {
        float4 q0 = *(const float4*)(Qb + (size_t)(mblk + arow) * DHC + acol);
        float4 q1 = *(const float4*)(Qb + (size_t)(mblk + arow) * DHC + acol + 4);
        float4 k0 = *(const float4*)(Kb + (size_t)(nblk + arow) * DHC + acol);
        float4 k1 = *(const float4*)(Kb + (size_t)(nblk + arow) * DHC + acol + 4);
        Qs[0][arow][acol+0]=tf32f(q0.x); Qs[0][arow][acol+1]=tf32f(q0.y);
        Qs[0][arow][acol+2]=tf32f(q0.z); Qs[0][arow][acol+3]=tf32f(q0.w);
        Qs[0][arow][acol+4]=tf32f(q1.x); Qs[0][arow][acol+5]=tf32f(q1.y);
        Qs[0][arow][acol+6]=tf32f(q1.z); Qs[0][arow][acol+7]=tf32f(q1.w);
        Ks[0][arow][acol+0]=tf32f(k0.x); Ks[0][arow][acol+1]=tf32f(k0.y);
        Ks[0][arow][acol+2]=tf32f(k0.z); Ks[0][arow][acol+3]=tf32f(k0.w);
        Ks[0][arow][acol+4]=tf32f(k1.x); Ks[0][arow][acol+5]=tf32f(k1.y);
        Ks[0][arow][acol+6]=tf32f(k1.z); Ks[0][arow][acol+7]=tf32f(k1.w);
    }
    __syncthreads();

    for (int s = 0; s < 4; s++) {
        const int buf = s & 1;
        const bool more = (s + 1 < 4);
        float4 pq0, pq1, pk0, pk1;
        if (more) {
            int k0 = (s + 1) * 16;
            pq0 = *(const float4*)(Qb + (size_t)(mblk + arow) * DHC + k0 + acol);
            pq1 = *(const float4*)(Qb + (size_t)(mblk + arow) * DHC + k0 + acol + 4);
            pk0 = *(const float4*)(Kb + (size_t)(nblk + arow) * DHC + k0 + acol);
            pk1 = *(const float4*)(Kb + (size_t)(nblk + arow) * DHC + k0 + acol + 4);
        }

#pragma unroll
        for (int kk = 0; kk < 16; kk += 8) {
            uint32_t af[2][4];
#pragma unroll
            for (int mi = 0; mi < 2; mi++) {
                int m = wm * 32 + mi * 16 + g;
                af[mi][0] = __float_as_uint(Qs[buf][m    ][kk + tg]);
                af[mi][1] = __float_as_uint(Qs[buf][m + 8][kk + tg]);
                af[mi][2] = __float_as_uint(Qs[buf][m    ][kk + tg + 4]);
                af[mi][3] = __float_as_uint(Qs[buf][m + 8][kk + tg + 4]);
            }
            uint32_t bf[8][2];
#pragma unroll
            for (int ni = 0; ni < 8; ni++) {
                int n = wn * 64 + ni * 8 + g;
                bf[ni][0] = __float_as_uint(Ks[buf][n][kk + tg]);
                bf[ni][1] = __float_as_uint(Ks[buf][n][kk + tg + 4]);
            }
#pragma unroll
            for (int mi = 0; mi < 2; mi++)
#pragma unroll
                for (int ni = 0; ni < 8; ni++)
                    mma8(acc[mi][ni], af[mi][0], af[mi][1], af[mi][2], af[mi][3],
                         bf[ni][0], bf[ni][1]);
        }

        if (more) {
            const int nb = buf ^ 1;
            Qs[nb][arow][acol+0]=tf32f(pq0.x); Qs[nb][arow][acol+1]=tf32f(pq0.y);
            Qs[nb][arow][acol+2]=tf32f(pq0.z); Qs[nb][arow][acol+3]=tf32f(pq0.w);
            Qs[nb][arow][acol+4]=tf32f(pq1.x); Qs[nb][arow][acol+5]=tf32f(pq1.y);
            Qs[nb][arow][acol+6]=tf32f(pq1.z); Qs[nb][arow][acol+7]=tf32f(pq1.w);
            Ks[nb][arow][acol+0]=tf32f(pk0.x); Ks[nb][arow][acol+1]=tf32f(pk0.y);
            Ks[nb][arow][acol+2]=tf32f(pk0.z); Ks[nb][arow][acol+3]=tf32f(pk0.w);
            Ks[nb][arow][acol+4]=tf32f(pk1.x); Ks[nb][arow][acol+5]=tf32f(pk1.y);
            Ks[nb][arow][acol+6]=tf32f(pk1.z); Ks[nb][arow][acol+7]=tf32f(pk1.w);
            __syncthreads();
        }
    }

    // epilogue: scale + mask + fp16 store
    __half* Sl = S4 + (size_t)l * BHNN + (size_t)bh * NXC * NYC;
#pragma unroll
    for (int mi = 0; mi < 2; mi++) {
        int r0 = mblk + wm * 32 + mi * 16 + g;
        int xr0 = xm[b * NXC + r0], xr1 = xm[b * NXC + r0 + 8];
#pragma unroll
        for (int ni = 0; ni < 8; ni++) {
            int c = nblk + wn * 64 + ni * 8 + tg * 2;
            int yc0 = ym[b * NYC + c], yc1 = ym[b * NYC + c + 1];
            float v0 = (xr0 && yc0) ? acc[mi][ni][0] * 0.125f : MASKED_H;
            float v1 = (xr0 && yc1) ? acc[mi][ni][1] * 0.125f : MASKED_H;
            float v2 = (xr1 && yc0) ? acc[mi][ni][2] * 0.125f : MASKED_H;
            float v3 = (xr1 && yc1) ? acc[mi][ni][3] * 0.125f : MASKED_H;
            *(__half2*)&Sl[(size_t)r0 * NYC + c]       = __floats2half2_rn(v0, v1);
            *(__half2*)&Sl[(size_t)(r0 + 8) * NYC + c] = __floats2half2_rn(v2, v3);
        }
    }
}

// ---------------------------------------------------------------------------
// Fused softmax-sum: A[row] = sum_{l=0..3} softmax(S_l[row]).   (fp16 input)
// One block (256 threads) per row of 1024.
// ---------------------------------------------------------------------------
__global__ __launch_bounds__(256) void softmax4_k(
    const __half* __restrict__ S4, float* __restrict__ A)
{
    __shared__ float sred[8];
    __shared__ float sbc;

    const size_t base = (size_t)blockIdx.x * NYC;
    const int tid = threadIdx.x, lane = tid & 31, w = tid >> 5;

    float acc[4] = {0.f, 0.f, 0.f, 0.f};

#pragma unroll
    for (int l = 0; l < 4; l++) {
        const __half2* S2 = (const __half2*)(S4 + (size_t)l * BHNN + base) + tid * 2;
        float2 f01 = __half22float2(S2[0]);
        float2 f23 = __half22float2(S2[1]);
        float v[4] = {f01.x, f01.y, f23.x, f23.y};

        float m = fmaxf(fmaxf(v[0], v[1]), fmaxf(v[2], v[3]));
#pragma unroll
        for (int o = 16; o > 0; o >>= 1) m = fmaxf(m, __shfl_xor_sync(0xffffffffu, m, o));
        if (lane == 0) sred[w] = m;
        __syncthreads();
        if (tid == 0) {
            float t = sred[0];
#pragma unroll
            for (int i = 1; i < 8; i++) t = fmaxf(t, sred[i]);
            sbc = t;
        }
        __syncthreads();
        const float bm = sbc;

        float p[4], s = 0.f;
#pragma unroll
        for (int i = 0; i < 4; i++) { p[i] = __expf(v[i] - bm); s += p[i]; }
#pragma unroll
        for (int o = 16; o > 0; o >>= 1) s += __shfl_xor_sync(0xffffffffu, s, o);
        if (lane == 0) sred[w] = s;
        __syncthreads();
        if (tid == 0) {
            float t = 0.f;
#pragma unroll
            for (int i = 0; i < 8; i++) t += sred[i];
            sbc = t;
        }
        __syncthreads();
        const float inv = 1.0f / sbc;
#pragma unroll
        for (int i = 0; i < 4; i++) acc[i] += p[i] * inv;
        __syncthreads();
    }

    // A layout matches half2 load pattern: indices tid*4 .. tid*4+3
#pragma unroll
    for (int i = 0; i < 4; i++) A[base + tid * 4 + i] = acc[i];
}

// ---------------------------------------------------------------------------
// O = attn @ V (tf32), transposed output O[b, n, h*64 + d].
// Block 64x64, 128 threads (4 warps x 16-row warp tile), grid (NX/64, B*H)=512.
// ---------------------------------------------------------------------------
__global__ __launch_bounds__(128) void attnv_k(
    const float* __restrict__ Aa, const float* __restrict__ V,
    float* __restrict__ O)
{
    __shared__ float As_[2][64][20];
    __shared__ float Vs[2][16][72];

    const int bh = blockIdx.y, b = bh >> 3, h = bh & 7;
    const int mblk = blockIdx.x * 64;
    const int tid = threadIdx.x;
    const int warp = tid >> 5, lane = tid & 31;
    const int g = lane >> 2, tg = lane & 3;

    const float* Ab = Aa + ((size_t)bh * NXC + mblk) * NYC;
    const float* Vb = V + (size_t)b * NYC * EC + (size_t)h * NYC * DHC;

    const int arow = tid >> 1, acol = (tid & 1) * 8;   // 64 rows x 16 k
    const int vrow = tid >> 3, vcol = (tid & 7) * 8;   // 16 rows x 64 cols

    float acc[8][4];
#pragma unroll
    for (int ni = 0; ni < 8; ni++)
#pragma unroll
        for (int q = 0; q < 4; q++) acc[ni][q] = 0.f;

    {
        float4 a0 = *(const float4*)(Ab + (size_t)arow * NYC + acol);
        float4 a1 = *(const float4*)(Ab + (size_t)arow * NYC + acol + 4);
        float4 v0 = *(const float4*)(Vb + (size_t)vrow * DHC + vcol);
        float4 v1 = *(const float4*)(Vb + (size_t)vrow * DHC + vcol + 4);
        As_[0][arow][acol+0]=tf32f(a0.x); As_[0][arow][acol+1]=tf32f(a0.y);
        As_[0][arow][acol+2]=tf32f(a0.z); As_[0][arow][acol+3]=tf32f(a0.w);
        As_[0][arow][acol+4]=tf32f(a1.x); As_[0][arow][acol+5]=tf32f(a1.y);
        As_[0][arow][acol+6]=tf32f(a1.z); As_[0][arow][acol+7]=tf32f(a1.w);
        Vs[0][vrow][vcol+0]=tf32f(v0.x); Vs[0][vrow][vcol+1]=tf32f(v0.y);
        Vs[0][vrow][vcol+2]=tf32f(v0.z); Vs[0][vrow][vcol+3]=tf32f(v0.w);
        Vs[0][vrow][vcol+4]=tf32f(v1.x); Vs[0][vrow][vcol+5]=tf32f(v1.y);
        Vs[0][vrow][vcol+6]=tf32f(v1.z); Vs[0][vrow][vcol+7]=tf32f(v1.w);
    }
    __syncthreads();

    for (int s = 0; s < 64; s++) {
        const int buf = s & 1;
        const bool more = (s + 1 < 64);
        float4 pa0, pa1, pv0, pv1;
        if (more) {
            int k0 = (s + 1) * 16;
            pa0 = *(const float4*)(Ab + (size_t)arow * NYC + k0 + acol);
            pa1 = *(const float4*)(Ab + (size_t)arow * NYC + k0 + acol + 4);
            pv0 = *(const float4*)(Vb + (size_t)(k0 + vrow) * DHC + vcol);
            pv1 = *(const float4*)(Vb + (size_t)(k0 + vrow) * DHC + vcol + 4);
        }

#pragma unroll
        for (int kk = 0; kk < 16; kk += 8) {
            int m = warp * 16 + g;
            uint32_t a0 = __float_as_uint(As_[buf][m    ][kk + tg]);
            uint32_t a1 = __float_as_uint(As_[buf][m + 8][kk + tg]);
            uint32_t a2 = __float_as_uint(As_[buf][m    ][kk + tg + 4]);
            uint32_t a3 = __float_as_uint(As_[buf][m + 8][kk + tg + 4]);
#pragma unroll
            for (int ni = 0; ni < 8; ni++) {
                int n = ni * 8 + g;
                uint32_t b0 = __float_as_uint(Vs[buf][kk + tg    ][n]);
                uint32_t b1 = __float_as_uint(Vs[buf][kk + tg + 4][n]);
                mma8(acc[ni], a0, a1, a2, a3, b0, b1);
            }
        }

        if (more) {
            const int nb = buf ^ 1;
            As_[nb][arow][acol+0]=tf32f(pa0.x); As_[nb][arow][acol+1]=tf32f(pa0.y);
            As_[nb][arow][acol+2]=tf32f(pa0.z); As_[nb][arow][acol+3]=tf32f(pa0.w);
            As_[nb][arow][acol+4]=tf32f(pa1.x); As_[nb][arow][acol+5]=tf32f(pa1.y);
            As_[nb][arow][acol+6]=tf32f(pa1.z); As_[nb][arow][acol+7]=tf32f(pa1.w);
            Vs[nb][vrow][vcol+0]=tf32f(pv0.x); Vs[nb][vrow][vcol+1]=tf32f(pv0.y);
            Vs[nb][vrow][vcol+2]=tf32f(pv0.z); Vs[nb][vrow][vcol+3]=tf32f(pv0.w);
            Vs[nb][vrow][vcol+4]=tf32f(pv1.x); Vs[nb][vrow][vcol+5]=tf32f(pv1.y);
            Vs[nb][vrow][vcol+6]=tf32f(pv1.z); Vs[nb][vrow][vcol+7]=tf32f(pv1.w);
            __syncthreads();
        }
    }

    const int r0 = mblk + warp * 16 + g;
    float* Ob = O + (size_t)b * NXC * EC + (size_t)h * DHC;
#pragma unroll
    for (int ni = 0; ni < 8; ni++) {
        int c = ni * 8 + tg * 2;
        *(float2*)&Ob[(size_t)r0 * EC + c]       = make_float2(acc[ni][0], acc[ni][1]);
        *(float2*)&Ob[(size_t)(r0 + 8) * EC + c] = make_float2(acc[ni][2], acc[ni][3]);
    }
}

// ---------------------------------------------------------------------------
// Residual + LayerNorm: Out[row] = LN(X[row] + R[row]) * g + be
// ---------------------------------------------------------------------------
__global__ __launch_bounds__(128) void resln_k(
    const float* __restrict__ X, const float* __restrict__ R,
    const float* __restrict__ g, const float* __restrict__ be,
    float* __restrict__ Out)
{
    __shared__ float sred[4];
    __shared__ float sbc;

    const size_t base = (size_t)blockIdx.x * EC;
    const int tid = threadIdx.x, lane = tid & 31, w = tid >> 5;

    float r[4];
    int col[4];
#pragma unroll
    for (int i = 0; i < 4; i++) {
        col[i] = tid + i * 128;
        r[i] = X[base + col[i]] + R[base + col[i]];
    }

    float s = r[0] + r[1] + r[2] + r[3];
#pragma unroll
    for (int o = 16; o > 0; o >>= 1) s += __shfl_xor_sync(0xffffffffu, s, o);
    if (lane == 0) sred[w] = s;
    __syncthreads();
    if (tid == 0) sbc = sred[0] + sred[1] + sred[2] + sred[3];
    __syncthreads();
    const float mu = sbc * (1.0f / EC);

    float d[4], ss = 0.f;
#pragma unroll
    for (int i = 0; i < 4; i++) { d[i] = r[i] - mu; ss += d[i] * d[i]; }
#pragma unroll
    for (int o = 16; o > 0; o >>= 1) ss += __shfl_xor_sync(0xffffffffu, ss, o);
    if (lane == 0) sred[w] = ss;
    __syncthreads();
    if (tid == 0) sbc = sred[0] + sred[1] + sred[2] + sred[3];
    __syncthreads();
    const float rs = rsqrtf(sbc * (1.0f / EC) + 1e-5f);

#pragma unroll
    for (int i = 0; i < 4; i++)
        Out[base + col[i]] = d[i] * rs * g[col[i]] + be[col[i]];
}

// ---------------------------------------------------------------------------
// Host
// ---------------------------------------------------------------------------
extern "C" void kernel_launch(void* const* d_in, const int* in_sizes, int n_in,
                              void* d_out, int out_size)
{
    (void)in_sizes; (void)n_in; (void)out_size;

    const float* x   = (const float*)d_in[0];
    const float* y   = (const float*)d_in[1];
    const int*   xm  = (const int*)  d_in[2];
    const int*   ym  = (const int*)  d_in[3];
    const float* Wq  = (const float*)d_in[4];
    const float* bq  = (const float*)d_in[5];
    const float* Wk  = (const float*)d_in[6];
    const float* bk  = (const float*)d_in[7];
    const float* Wv  = (const float*)d_in[8];
    const float* bv  = (const float*)d_in[9];
    const float* Wo  = (const float*)d_in[10];
    const float* bo  = (const float*)d_in[11];
    const float* g1  = (const float*)d_in[12];
    const float* be1 = (const float*)d_in[13];
    const float* g2  = (const float*)d_in[14];
    const float* be2 = (const float*)d_in[15];
    const float* W1  = (const float*)d_in[16];
    const float* bf1 = (const float*)d_in[17];
    const float* W2  = (const float*)d_in[18];
    const float* bf2 = (const float*)d_in[19];
    float* out = (float*)d_out;

    float *QK, *V, *O, *O2, *Hb, *F1, *F2, *Aa;
    __half* S4;
    cudaGetSymbolAddress((void**)&QK, g_QK);
    cudaGetSymbolAddress((void**)&V,  g_V);
    cudaGetSymbolAddress((void**)&O,  g_O);
    cudaGetSymbolAddress((void**)&O2, g_O2);
    cudaGetSymbolAddress((void**)&Hb, g_Hb);
    cudaGetSymbolAddress((void**)&F1, g_F1);
    cudaGetSymbolAddress((void**)&F2, g_F2);
    cudaGetSymbolAddress((void**)&S4, g_S4);
    cudaGetSymbolAddress((void**)&Aa, g_A);

    // 1. All Q_l, K_l projections + V_3 in one launch (9 GEMM slices)
    proj_k<<<dim3(4, 32, 9), 256>>>(x, y, Wq, bq, Wk, bk, Wv, bv, QK, V);
    // 2. All layers' masked scores in one launch (fp16 store)
    scores_k<<<dim3(8, 8, 128), 256>>>(QK, xm, ym, S4);
    // 3. Single fused softmax-sum (a_3 = sum_l softmax(S_l))
    softmax4_k<<<BB * HC * NXC, 256>>>(S4, Aa);
    // 4. Tail (only last layer's downstream path is live)
    attnv_k<<<dim3(16, 32), 128>>>(Aa, V, O);
    gemm_k<<<dim3(4, 32), 256>>>(O, Wo + (size_t)3 * EC * EC, bo + 3 * EC, O2, EC, EC, 0);
    resln_k<<<MC, 128>>>(x, O2, g1 + 3 * EC, be1 + 3 * EC, Hb);
    gemm_k<<<dim3(16, 32), 256>>>(Hb, W1 + (size_t)3 * EC * FFC, bf1 + (size_t)3 * FFC, F1, EC, FFC, 1);
    gemm_k<<<dim3(4, 32), 256>>>(F1, W2 + (size_t)3 * FFC * EC, bf2 + 3 * EC, F2, FFC, EC, 0);
    resln_k<<<MC, 128>>>(Hb, F2, g2 + 3 * EC, be2 + 3 * EC, out);
}

// round 9
// speedup vs baseline: 3.0212x; 1.0960x over previous
#include <cuda_runtime.h>
#include <cuda_fp16.h>
#include <math.h>
#include <stdint.h>

// Problem constants
#define BB   4
#define NXC  1024
#define NYC  1024
#define EC   512
#define HC   8
#define DHC  64
#define LC   4
#define FFC  2048
#define MC   (BB * NXC)

#define BNE  (BB * NXC * EC)                  // 2,097,152
#define BHNN ((size_t)BB * HC * NXC * NYC)    // 33,554,432

// ---------------------------------------------------------------------------
// Scratch (device globals; allocation-free per harness rules)
// ---------------------------------------------------------------------------
__device__ __half g_QK[8 * (size_t)BNE];      // Q0,K0,..,Q3,K3 fp16 (32MB)
__device__ __half g_V [BNE];                  // V3 fp16
__device__ float  g_O [BNE];
__device__ float  g_O2[BNE];
__device__ float  g_Hb[BNE];
__device__ float  g_F1[(size_t)MC * FFC];
__device__ float  g_F2[BNE];
__device__ __half g_S4[4 * BHNN];             // 4 layers' raw scores fp16 (256MB)
__device__ __half g_A [BHNN];                 // summed attention fp16 (64MB)

#define MASKED_H (-30000.0f)

// ---------------------------------------------------------------------------
// FP16 MMA helpers (fp32 accumulate)
// ---------------------------------------------------------------------------
__device__ __forceinline__ uint32_t pack2(float a, float b) {
    __half2 h = __floats2half2_rn(a, b);
    return *(uint32_t*)&h;
}

__device__ __forceinline__ uint32_t packus(unsigned short lo, unsigned short hi) {
    uint32_t r;
    asm("mov.b32 %0, {%1,%2};" : "=r"(r) : "h"(lo), "h"(hi));
    return r;
}

__device__ __forceinline__ void mma16(float* c,
    uint32_t a0, uint32_t a1, uint32_t a2, uint32_t a3,
    uint32_t b0, uint32_t b1)
{
    asm volatile(
        "mma.sync.aligned.m16n8k16.row.col.f32.f16.f16.f32 "
        "{%0,%1,%2,%3},{%4,%5,%6,%7},{%8,%9},{%0,%1,%2,%3};"
        : "+f"(c[0]), "+f"(c[1]), "+f"(c[2]), "+f"(c[3])
        : "r"(a0), "r"(a1), "r"(a2), "r"(a3), "r"(b0), "r"(b1));
}

// ---------------------------------------------------------------------------
// FP16 GEMM body: C[M,N] = A[M,K] @ W[K,N] + bias (opt exact GELU)
// A,W fp32 in (converted to fp16 in smem); out fp32 (Cf) or fp16 (Ch).
// block 128x128, BK=16, 256 threads (8 warps 4x2), warp tile 32x64.
// ---------------------------------------------------------------------------
__device__ __forceinline__ void gemm16_body(
    const float* __restrict__ A, const float* __restrict__ W,
    const float* __restrict__ bias, float* __restrict__ Cf,
    __half* __restrict__ Ch, int K, int N, int dogelu)
{
    __shared__ uint32_t As2[2][128][12];   // [m][kpair 0..7], stride 12 words
    __shared__ __half   Bs [2][16][136];   // [k][n], stride 136 halves

    const int tid  = threadIdx.x;
    const int warp = tid >> 5, lane = tid & 31;
    const int wm = warp >> 1, wn = warp & 1;
    const int g  = lane >> 2, tg = lane & 3;
    const int mblk = blockIdx.y * 128, nblk = blockIdx.x * 128;

    const int arow = tid >> 1, aseg = (tid & 1) * 4;    // kpair offset 0/4
    const int wrow = tid >> 4, wcol = (tid & 15) * 8;   // k row 0..15

    const float* Ag = A + (size_t)(mblk + arow) * K + aseg * 2;
    const float* Wg = W + (size_t)wrow * N + nblk + wcol;

    float acc[2][8][4];
#pragma unroll
    for (int mi = 0; mi < 2; mi++)
#pragma unroll
        for (int ni = 0; ni < 8; ni++)
#pragma unroll
            for (int q = 0; q < 4; q++) acc[mi][ni][q] = 0.f;

    // stage 0
    {
        float4 a0 = *(const float4*)(Ag);
        float4 a1 = *(const float4*)(Ag + 4);
        As2[0][arow][aseg+0] = pack2(a0.x, a0.y);
        As2[0][arow][aseg+1] = pack2(a0.z, a0.w);
        As2[0][arow][aseg+2] = pack2(a1.x, a1.y);
        As2[0][arow][aseg+3] = pack2(a1.z, a1.w);
        float4 w0 = *(const float4*)(Wg);
        float4 w1 = *(const float4*)(Wg + 4);
        __half2* bp = (__half2*)&Bs[0][wrow][wcol];
        bp[0] = __floats2half2_rn(w0.x, w0.y);
        bp[1] = __floats2half2_rn(w0.z, w0.w);
        bp[2] = __floats2half2_rn(w1.x, w1.y);
        bp[3] = __floats2half2_rn(w1.z, w1.w);
    }
    __syncthreads();

    const int nst = K >> 4;
    for (int s = 0; s < nst; s++) {
        const int buf = s & 1;
        const bool more = (s + 1 < nst);
        float4 pa0, pa1, pw0, pw1;
        if (more) {
            const float* Ap = Ag + (s + 1) * 16;
            const float* Wp = Wg + (size_t)(s + 1) * 16 * N;
            pa0 = *(const float4*)Ap; pa1 = *(const float4*)(Ap + 4);
            pw0 = *(const float4*)Wp; pw1 = *(const float4*)(Wp + 4);
        }

        uint32_t af[2][4];
#pragma unroll
        for (int mi = 0; mi < 2; mi++) {
            int m = wm * 32 + mi * 16 + g;
            af[mi][0] = As2[buf][m    ][tg];
            af[mi][1] = As2[buf][m + 8][tg];
            af[mi][2] = As2[buf][m    ][tg + 4];
            af[mi][3] = As2[buf][m + 8][tg + 4];
        }
#pragma unroll
        for (int ni = 0; ni < 8; ni++) {
            int n = wn * 64 + ni * 8 + g;
            unsigned short l0 = *(const unsigned short*)&Bs[buf][2*tg    ][n];
            unsigned short h0 = *(const unsigned short*)&Bs[buf][2*tg + 1][n];
            unsigned short l1 = *(const unsigned short*)&Bs[buf][2*tg + 8][n];
            unsigned short h1 = *(const unsigned short*)&Bs[buf][2*tg + 9][n];
            uint32_t b0 = packus(l0, h0), b1 = packus(l1, h1);
#pragma unroll
            for (int mi = 0; mi < 2; mi++)
                mma16(acc[mi][ni], af[mi][0], af[mi][1], af[mi][2], af[mi][3], b0, b1);
        }

        if (more) {
            const int nb = buf ^ 1;
            As2[nb][arow][aseg+0] = pack2(pa0.x, pa0.y);
            As2[nb][arow][aseg+1] = pack2(pa0.z, pa0.w);
            As2[nb][arow][aseg+2] = pack2(pa1.x, pa1.y);
            As2[nb][arow][aseg+3] = pack2(pa1.z, pa1.w);
            __half2* bp = (__half2*)&Bs[nb][wrow][wcol];
            bp[0] = __floats2half2_rn(pw0.x, pw0.y);
            bp[1] = __floats2half2_rn(pw0.z, pw0.w);
            bp[2] = __floats2half2_rn(pw1.x, pw1.y);
            bp[3] = __floats2half2_rn(pw1.z, pw1.w);
            __syncthreads();
        }
    }

#pragma unroll
    for (int mi = 0; mi < 2; mi++) {
        int r0 = mblk + wm * 32 + mi * 16 + g;
#pragma unroll
        for (int ni = 0; ni < 8; ni++) {
            int c = nblk + wn * 64 + ni * 8 + tg * 2;
            float b0 = bias[c], b1 = bias[c + 1];
            float v0 = acc[mi][ni][0] + b0, v1 = acc[mi][ni][1] + b1;
            float v2 = acc[mi][ni][2] + b0, v3 = acc[mi][ni][3] + b1;
            if (dogelu) {
                v0 = 0.5f * v0 * (1.0f + erff(v0 * 0.70710678118654752f));
                v1 = 0.5f * v1 * (1.0f + erff(v1 * 0.70710678118654752f));
                v2 = 0.5f * v2 * (1.0f + erff(v2 * 0.70710678118654752f));
                v3 = 0.5f * v3 * (1.0f + erff(v3 * 0.70710678118654752f));
            }
            if (Ch) {
                *(__half2*)&Ch[(size_t)r0 * N + c]       = __floats2half2_rn(v0, v1);
                *(__half2*)&Ch[(size_t)(r0 + 8) * N + c] = __floats2half2_rn(v2, v3);
            } else {
                *(float2*)&Cf[(size_t)r0 * N + c]       = make_float2(v0, v1);
                *(float2*)&Cf[(size_t)(r0 + 8) * N + c] = make_float2(v2, v3);
            }
        }
    }
}

__global__ __launch_bounds__(256) void gemm_k(
    const float* __restrict__ A, const float* __restrict__ W,
    const float* __restrict__ bias, float* __restrict__ C,
    int K, int N, int dogelu)
{
    gemm16_body(A, W, bias, C, (__half*)0, K, N, dogelu);
}

// Batched projections (fp16 out): z=0..7 -> (layer z/2, Q/K), z=8 -> V3.
__global__ __launch_bounds__(256) void proj_k(
    const float* __restrict__ x, const float* __restrict__ y,
    const float* __restrict__ Wq, const float* __restrict__ bq,
    const float* __restrict__ Wk, const float* __restrict__ bk,
    const float* __restrict__ Wv, const float* __restrict__ bv,
    __half* __restrict__ QK, __half* __restrict__ V)
{
    const int z = blockIdx.z;
    const float *A, *W, *Bi;
    __half* C;
    if (z < 8) {
        int l = z >> 1, isK = z & 1;
        A  = isK ? y : x;
        W  = (isK ? Wk : Wq) + (size_t)l * EC * EC;
        Bi = (isK ? bk : bq) + (size_t)l * EC;
        C  = QK + (size_t)z * BNE;
    } else {
        A = y; W = Wv + (size_t)3 * EC * EC; Bi = bv + (size_t)3 * EC; C = V;
    }
    gemm16_body(A, W, Bi, (float*)0, C, EC, EC, 0);
}

// ---------------------------------------------------------------------------
// Scores (all layers/heads): S = (Q @ K^T)*0.125, masked, fp16 in+out.
// FAITHFUL head split: head block = contiguous [1024 x 64] chunk at
// element offset b*NX*E + h*NX*DH (row stride DH = 32 uint32).
// Grid (NY/128, NX/128, 4*32), 256 threads.
// ---------------------------------------------------------------------------
__global__ __launch_bounds__(256) void scores_k(
    const __half* __restrict__ QK, const int* __restrict__ xm,
    const int* __restrict__ ym, __half* __restrict__ S4)
{
    __shared__ uint32_t Qs2[128][36];   // [m][kpair 0..31]
    __shared__ uint32_t Ks2[128][36];   // [n][kpair 0..31]

    const int z = blockIdx.z;
    const int l = z >> 5, bh = z & 31, b = bh >> 3, h = bh & 7;
    // uint32 units: half offset / 2.  Head block base, row stride 32 uint32.
    const uint32_t* Qb = (const uint32_t*)(QK + (size_t)(2 * l) * BNE)
                         + (size_t)b * NXC * 256 + (size_t)h * NXC * 32;
    const uint32_t* Kb = (const uint32_t*)(QK + (size_t)(2 * l + 1) * BNE)
                         + (size_t)b * NYC * 256 + (size_t)h * NYC * 32;

    const int mblk = blockIdx.y * 128;
    const int nblk = blockIdx.x * 128;
    const int tid  = threadIdx.x;
    const int warp = tid >> 5, lane = tid & 31;
    const int wm = warp >> 1, wn = warp & 1;
    const int g = lane >> 2, tg = lane & 3;

    // load whole 128x64 Q and K tiles (row stride 32 uint32, fully coalesced)
    for (int t = tid; t < 128 * 32; t += 256) {
        int r = t >> 5, p = t & 31;
        Qs2[r][p] = Qb[(size_t)(mblk + r) * 32 + p];
        Ks2[r][p] = Kb[(size_t)(nblk + r) * 32 + p];
    }
    __syncthreads();

    float acc[2][8][4];
#pragma unroll
    for (int mi = 0; mi < 2; mi++)
#pragma unroll
        for (int ni = 0; ni < 8; ni++)
#pragma unroll
            for (int q = 0; q < 4; q++) acc[mi][ni][q] = 0.f;

#pragma unroll
    for (int c = 0; c < 4; c++) {          // 4 chunks of k16
        uint32_t af[2][4];
#pragma unroll
        for (int mi = 0; mi < 2; mi++) {
            int m = wm * 32 + mi * 16 + g;
            af[mi][0] = Qs2[m    ][8*c + tg];
            af[mi][1] = Qs2[m + 8][8*c + tg];
            af[mi][2] = Qs2[m    ][8*c + tg + 4];
            af[mi][3] = Qs2[m + 8][8*c + tg + 4];
        }
#pragma unroll
        for (int ni = 0; ni < 8; ni++) {
            int n = wn * 64 + ni * 8 + g;
            uint32_t b0 = Ks2[n][8*c + tg];
            uint32_t b1 = Ks2[n][8*c + tg + 4];
#pragma unroll
            for (int mi = 0; mi < 2; mi++)
                mma16(acc[mi][ni], af[mi][0], af[mi][1], af[mi][2], af[mi][3], b0, b1);
        }
    }

    __half* Sl = S4 + (size_t)l * BHNN + (size_t)bh * NXC * NYC;
#pragma unroll
    for (int mi = 0; mi < 2; mi++) {
        int r0 = mblk + wm * 32 + mi * 16 + g;
        int xr0 = xm[b * NXC + r0], xr1 = xm[b * NXC + r0 + 8];
#pragma unroll
        for (int ni = 0; ni < 8; ni++) {
            int c = nblk + wn * 64 + ni * 8 + tg * 2;
            int yc0 = ym[b * NYC + c], yc1 = ym[b * NYC + c + 1];
            float v0 = (xr0 && yc0) ? acc[mi][ni][0] * 0.125f : MASKED_H;
            float v1 = (xr0 && yc1) ? acc[mi][ni][1] * 0.125f : MASKED_H;
            float v2 = (xr1 && yc0) ? acc[mi][ni][2] * 0.125f : MASKED_H;
            float v3 = (xr1 && yc1) ? acc[mi][ni][3] * 0.125f : MASKED_H;
            *(__half2*)&Sl[(size_t)r0 * NYC + c]       = __floats2half2_rn(v0, v1);
            *(__half2*)&Sl[(size_t)(r0 + 8) * NYC + c] = __floats2half2_rn(v2, v3);
        }
    }
}

// ---------------------------------------------------------------------------
// Fused softmax-sum: A[row] = sum_{l=0..3} softmax(S_l[row]). fp16 in/out.
// One block (256 threads) per row of 1024.
// ---------------------------------------------------------------------------
__global__ __launch_bounds__(256) void softmax4_k(
    const __half* __restrict__ S4, __half* __restrict__ A)
{
    __shared__ float sred[8];
    __shared__ float sbc;

    const size_t base = (size_t)blockIdx.x * NYC;
    const int tid = threadIdx.x, lane = tid & 31, w = tid >> 5;

    float acc[4] = {0.f, 0.f, 0.f, 0.f};

#pragma unroll
    for (int l = 0; l < 4; l++) {
        const __half2* S2 = (const __half2*)(S4 + (size_t)l * BHNN + base) + tid * 2;
        float2 f01 = __half22float2(S2[0]);
        float2 f23 = __half22float2(S2[1]);
        float v[4] = {f01.x, f01.y, f23.x, f23.y};

        float m = fmaxf(fmaxf(v[0], v[1]), fmaxf(v[2], v[3]));
#pragma unroll
        for (int o = 16; o > 0; o >>= 1) m = fmaxf(m, __shfl_xor_sync(0xffffffffu, m, o));
        if (lane == 0) sred[w] = m;
        __syncthreads();
        if (tid == 0) {
            float t = sred[0];
#pragma unroll
            for (int i = 1; i < 8; i++) t = fmaxf(t, sred[i]);
            sbc = t;
        }
        __syncthreads();
        const float bm = sbc;

        float p[4], s = 0.f;
#pragma unroll
        for (int i = 0; i < 4; i++) { p[i] = __expf(v[i] - bm); s += p[i]; }
#pragma unroll
        for (int o = 16; o > 0; o >>= 1) s += __shfl_xor_sync(0xffffffffu, s, o);
        if (lane == 0) sred[w] = s;
        __syncthreads();
        if (tid == 0) {
            float t = 0.f;
#pragma unroll
            for (int i = 0; i < 8; i++) t += sred[i];
            sbc = t;
        }
        __syncthreads();
        const float inv = 1.0f / sbc;
#pragma unroll
        for (int i = 0; i < 4; i++) acc[i] += p[i] * inv;
        __syncthreads();
    }

    *(__half2*)&A[base + tid * 4]     = __floats2half2_rn(acc[0], acc[1]);
    *(__half2*)&A[base + tid * 4 + 2] = __floats2half2_rn(acc[2], acc[3]);
}

// ---------------------------------------------------------------------------
// O = attn @ V (fp16 in, fp32 out), transposed output O[b, n, h*64+d].
// FAITHFUL V head split: V head block = contiguous [1024 x 64] chunk at
// element offset b*NY*E + h*NY*DH (row stride DH=64 halves).
// Block 64x64, 128 threads (4 warps x m16), BK=32 double-buffered.
// Grid (NX/64, B*H).
// ---------------------------------------------------------------------------
__global__ __launch_bounds__(128) void attnv_k(
    const __half* __restrict__ Aa, const __half* __restrict__ V,
    float* __restrict__ O)
{
    __shared__ uint32_t As2[2][64][20];   // [m][kpair 0..15]
    __shared__ __half   Vs [2][32][72];   // [k][n], stride 72 halves

    const int bh = blockIdx.y, b = bh >> 3, h = bh & 7;
    const int mblk = blockIdx.x * 64;
    const int tid = threadIdx.x;
    const int warp = tid >> 5, lane = tid & 31;
    const int g = lane >> 2, tg = lane & 3;

    // A row stride = 1024 halves = 512 uint32
    const uint32_t* Ab = (const uint32_t*)(Aa + ((size_t)bh * NXC + 0) * NYC);
    // V head block: contiguous [NY x DH] chunk, row stride DHC halves
    const __half* Vb = V + (size_t)b * NYC * EC + (size_t)h * NYC * DHC;

    const int arow = tid >> 1, aseg = (tid & 1) * 8;   // kpair offset 0/8
    const int vrow = tid >> 2, vcol = (tid & 3) * 16;  // k row 0..31

    const uint32_t* Ag = Ab + (size_t)(mblk + arow) * 512 + aseg;

    float acc[8][4];
#pragma unroll
    for (int ni = 0; ni < 8; ni++)
#pragma unroll
        for (int q = 0; q < 4; q++) acc[ni][q] = 0.f;

    // stage 0
    {
        uint4 u0 = *(const uint4*)(Ag);
        uint4 u1 = *(const uint4*)(Ag + 4);
        As2[0][arow][aseg+0]=u0.x; As2[0][arow][aseg+1]=u0.y;
        As2[0][arow][aseg+2]=u0.z; As2[0][arow][aseg+3]=u0.w;
        As2[0][arow][aseg+4]=u1.x; As2[0][arow][aseg+5]=u1.y;
        As2[0][arow][aseg+6]=u1.z; As2[0][arow][aseg+7]=u1.w;
        const __half* Vg = Vb + (size_t)vrow * DHC + vcol;
        uint4 v0 = *(const uint4*)(Vg);
        uint4 v1 = *(const uint4*)(Vg + 8);
        *(uint4*)&Vs[0][vrow][vcol]     = v0;
        *(uint4*)&Vs[0][vrow][vcol + 8] = v1;
    }
    __syncthreads();

    for (int s = 0; s < 32; s++) {
        const int buf = s & 1;
        const bool more = (s + 1 < 32);
        uint4 pa0, pa1, pv0, pv1;
        if (more) {
            const uint32_t* Ap = Ag + (s + 1) * 16;
            pa0 = *(const uint4*)(Ap);
            pa1 = *(const uint4*)(Ap + 4);
            const __half* Vg = Vb + (size_t)((s + 1) * 32 + vrow) * DHC + vcol;
            pv0 = *(const uint4*)(Vg);
            pv1 = *(const uint4*)(Vg + 8);
        }

#pragma unroll
        for (int cc = 0; cc < 2; cc++) {
            int m = warp * 16 + g;
            uint32_t a0 = As2[buf][m    ][8*cc + tg];
            uint32_t a1 = As2[buf][m + 8][8*cc + tg];
            uint32_t a2 = As2[buf][m    ][8*cc + tg + 4];
            uint32_t a3 = As2[buf][m + 8][8*cc + tg + 4];
#pragma unroll
            for (int ni = 0; ni < 8; ni++) {
                int n = ni * 8 + g;
                unsigned short l0 = *(const unsigned short*)&Vs[buf][16*cc + 2*tg    ][n];
                unsigned short h0 = *(const unsigned short*)&Vs[buf][16*cc + 2*tg + 1][n];
                unsigned short l1 = *(const unsigned short*)&Vs[buf][16*cc + 2*tg + 8][n];
                unsigned short h1 = *(const unsigned short*)&Vs[buf][16*cc + 2*tg + 9][n];
                mma16(acc[ni], a0, a1, a2, a3, packus(l0, h0), packus(l1, h1));
            }
        }

        if (more) {
            const int nb = buf ^ 1;
            As2[nb][arow][aseg+0]=pa0.x; As2[nb][arow][aseg+1]=pa0.y;
            As2[nb][arow][aseg+2]=pa0.z; As2[nb][arow][aseg+3]=pa0.w;
            As2[nb][arow][aseg+4]=pa1.x; As2[nb][arow][aseg+5]=pa1.y;
            As2[nb][arow][aseg+6]=pa1.z; As2[nb][arow][aseg+7]=pa1.w;
            *(uint4*)&Vs[nb][vrow][vcol]     = pv0;
            *(uint4*)&Vs[nb][vrow][vcol + 8] = pv1;
            __syncthreads();
        }
    }

    // Output: transposed layout O[b, n, h*DH + d] (standard rows)
    const int r0 = mblk + warp * 16 + g;
    float* Ob = O + (size_t)b * NXC * EC + (size_t)h * DHC;
#pragma unroll
    for (int ni = 0; ni < 8; ni++) {
        int c = ni * 8 + tg * 2;
        *(float2*)&Ob[(size_t)r0 * EC + c]       = make_float2(acc[ni][0], acc[ni][1]);
        *(float2*)&Ob[(size_t)(r0 + 8) * EC + c] = make_float2(acc[ni][2], acc[ni][3]);
    }
}

// ---------------------------------------------------------------------------
// Residual + LayerNorm: Out[row] = LN(X[row] + R[row]) * g + be
// ---------------------------------------------------------------------------
__global__ __launch_bounds__(128) void resln_k(
    const float* __restrict__ X, const float* __restrict__ R,
    const float* __restrict__ g, const float* __restrict__ be,
    float* __restrict__ Out)
{
    __shared__ float sred[4];
    __shared__ float sbc;

    const size_t base = (size_t)blockIdx.x * EC;
    const int tid = threadIdx.x, lane = tid & 31, w = tid >> 5;

    float r[4];
    int col[4];
#pragma unroll
    for (int i = 0; i < 4; i++) {
        col[i] = tid + i * 128;
        r[i] = X[base + col[i]] + R[base + col[i]];
    }

    float s = r[0] + r[1] + r[2] + r[3];
#pragma unroll
    for (int o = 16; o > 0; o >>= 1) s += __shfl_xor_sync(0xffffffffu, s, o);
    if (lane == 0) sred[w] = s;
    __syncthreads();
    if (tid == 0) sbc = sred[0] + sred[1] + sred[2] + sred[3];
    __syncthreads();
    const float mu = sbc * (1.0f / EC);

    float d[4], ss = 0.f;
#pragma unroll
    for (int i = 0; i < 4; i++) { d[i] = r[i] - mu; ss += d[i] * d[i]; }
#pragma unroll
    for (int o = 16; o > 0; o >>= 1) ss += __shfl_xor_sync(0xffffffffu, ss, o);
    if (lane == 0) sred[w] = ss;
    __syncthreads();
    if (tid == 0) sbc = sred[0] + sred[1] + sred[2] + sred[3];
    __syncthreads();
    const float rs = rsqrtf(sbc * (1.0f / EC) + 1e-5f);

#pragma unroll
    for (int i = 0; i < 4; i++)
        Out[base + col[i]] = d[i] * rs * g[col[i]] + be[col[i]];
}

// ---------------------------------------------------------------------------
// Host
// ---------------------------------------------------------------------------
extern "C" void kernel_launch(void* const* d_in, const int* in_sizes, int n_in,
                              void* d_out, int out_size)
{
    (void)in_sizes; (void)n_in; (void)out_size;

    const float* x   = (const float*)d_in[0];
    const float* y   = (const float*)d_in[1];
    const int*   xm  = (const int*)  d_in[2];
    const int*   ym  = (const int*)  d_in[3];
    const float* Wq  = (const float*)d_in[4];
    const float* bq  = (const float*)d_in[5];
    const float* Wk  = (const float*)d_in[6];
    const float* bk  = (const float*)d_in[7];
    const float* Wv  = (const float*)d_in[8];
    const float* bv  = (const float*)d_in[9];
    const float* Wo  = (const float*)d_in[10];
    const float* bo  = (const float*)d_in[11];
    const float* g1  = (const float*)d_in[12];
    const float* be1 = (const float*)d_in[13];
    const float* g2  = (const float*)d_in[14];
    const float* be2 = (const float*)d_in[15];
    const float* W1  = (const float*)d_in[16];
    const float* bf1 = (const float*)d_in[17];
    const float* W2  = (const float*)d_in[18];
    const float* bf2 = (const float*)d_in[19];
    float* out = (float*)d_out;

    float *O, *O2, *Hb, *F1, *F2;
    __half *QK, *V, *S4, *Aa;
    cudaGetSymbolAddress((void**)&QK, g_QK);
    cudaGetSymbolAddress((void**)&V,  g_V);
    cudaGetSymbolAddress((void**)&O,  g_O);
    cudaGetSymbolAddress((void**)&O2, g_O2);
    cudaGetSymbolAddress((void**)&Hb, g_Hb);
    cudaGetSymbolAddress((void**)&F1, g_F1);
    cudaGetSymbolAddress((void**)&F2, g_F2);
    cudaGetSymbolAddress((void**)&S4, g_S4);
    cudaGetSymbolAddress((void**)&Aa, g_A);

    // 1. All Q_l, K_l projections + V_3 in one launch (9 GEMM slices, fp16 out)
    proj_k<<<dim3(4, 32, 9), 256>>>(x, y, Wq, bq, Wk, bk, Wv, bv, QK, V);
    // 2. All layers' masked scores in one launch (fp16 in/out)
    scores_k<<<dim3(8, 8, 128), 256>>>(QK, xm, ym, S4);
    // 3. Single fused softmax-sum (a_3 = sum_l softmax(S_l)), fp16 out
    softmax4_k<<<BB * HC * NXC, 256>>>(S4, Aa);
    // 4. Tail (only last layer's downstream path is live)
    attnv_k<<<dim3(16, 32), 128>>>(Aa, V, O);
    gemm_k<<<dim3(4, 32), 256>>>(O, Wo + (size_t)3 * EC * EC, bo + 3 * EC, O2, EC, EC, 0);
    resln_k<<<MC, 128>>>(x, O2, g1 + 3 * EC, be1 + 3 * EC, Hb);
    gemm_k<<<dim3(16, 32), 256>>>(Hb, W1 + (size_t)3 * EC * FFC, bf1 + (size_t)3 * FFC, F1, EC, FFC, 1);
    gemm_k<<<dim3(4, 32), 256>>>(F1, W2 + (size_t)3 * FFC * EC, bf2 + 3 * EC, F2, FFC, EC, 0);
    resln_k<<<MC, 128>>>(Hb, F2, g2 + 3 * EC, be2 + 3 * EC, out);
}

// round 10
// speedup vs baseline: 3.0715x; 1.0167x over previous
#include <cuda_runtime.h>
#include <cuda_fp16.h>
#include <math.h>
#include <stdint.h>

// Problem constants
#define BB   4
#define NXC  1024
#define NYC  1024
#define EC   512
#define HC   8
#define DHC  64
#define LC   4
#define FFC  2048
#define MC   (BB * NXC)

#define BNE  (BB * NXC * EC)                  // 2,097,152
#define BHNN ((size_t)BB * HC * NXC * NYC)    // 33,554,432

// ---------------------------------------------------------------------------
// Scratch (device globals; allocation-free per harness rules)
// ---------------------------------------------------------------------------
__device__ __half g_QK[8 * (size_t)BNE];      // Q0,K0,..,Q3,K3 fp16 (32MB)
__device__ __half g_V [BNE];                  // V3 fp16
__device__ float  g_O [BNE];                  // attnv partial 0 / W2 out
__device__ float  g_O2[BNE];                  // attnv partial 1
__device__ float  g_Hb[BNE];
__device__ float  g_F1[(size_t)MC * FFC];
__device__ float  g_F2[BNE];                  // Wo out
__device__ __half g_S4[4 * BHNN];             // 4 layers' raw scores fp16 (256MB)
__device__ __half g_A [BHNN];                 // summed attention fp16 (64MB)

#define MASKED_H (-30000.0f)

// ---------------------------------------------------------------------------
// FP16 MMA helpers (fp32 accumulate)
// ---------------------------------------------------------------------------
__device__ __forceinline__ uint32_t pack2(float a, float b) {
    __half2 h = __floats2half2_rn(a, b);
    return *(uint32_t*)&h;
}

__device__ __forceinline__ uint32_t sptr(const void* p) {
    return (uint32_t)__cvta_generic_to_shared(p);
}

__device__ __forceinline__ void mma16(float* c,
    uint32_t a0, uint32_t a1, uint32_t a2, uint32_t a3,
    uint32_t b0, uint32_t b1)
{
    asm volatile(
        "mma.sync.aligned.m16n8k16.row.col.f32.f16.f16.f32 "
        "{%0,%1,%2,%3},{%4,%5,%6,%7},{%8,%9},{%0,%1,%2,%3};"
        : "+f"(c[0]), "+f"(c[1]), "+f"(c[2]), "+f"(c[3])
        : "r"(a0), "r"(a1), "r"(a2), "r"(a3), "r"(b0), "r"(b1));
}

// ldmatrix x4 transposed (B-operand fragments from [k][n] smem tiles)
__device__ __forceinline__ void ldm4t(uint32_t addr,
    uint32_t& r0, uint32_t& r1, uint32_t& r2, uint32_t& r3)
{
    asm volatile(
        "ldmatrix.sync.aligned.m8n8.x4.trans.shared.b16 {%0,%1,%2,%3}, [%4];"
        : "=r"(r0), "=r"(r1), "=r"(r2), "=r"(r3) : "r"(addr));
}

// ---------------------------------------------------------------------------
// FP16 GEMM body: C[M,N] = (A (+A2?)) @ W[K,N] + bias (opt exact GELU)
// A,W fp32 in (fp16 in smem); out fp32 (Cf) or fp16 (Ch).
// block 128x128, BK=16, 256 threads (8 warps 4x2), warp tile 32x64.
// B fragments via ldmatrix.x4.trans (conflict-free, stride 136 halves).
// ---------------------------------------------------------------------------
__device__ __forceinline__ void gemm16_body(
    const float* __restrict__ A, const float* __restrict__ A2,
    const float* __restrict__ W,
    const float* __restrict__ bias, float* __restrict__ Cf,
    __half* __restrict__ Ch, int K, int N, int dogelu)
{
    __shared__ uint32_t As2[2][128][12];   // [m][kpair 0..7], stride 12 words
    __shared__ __half   Bs [2][16][136];   // [k][n], stride 136 halves

    const int tid  = threadIdx.x;
    const int warp = tid >> 5, lane = tid & 31;
    const int wm = warp >> 1, wn = warp & 1;
    const int g  = lane >> 2, tg = lane & 3;
    const int mblk = blockIdx.y * 128, nblk = blockIdx.x * 128;

    const int arow = tid >> 1, aseg = (tid & 1) * 4;    // kpair offset 0/4
    const int wrow = tid >> 4, wcol = (tid & 15) * 8;   // k row 0..15

    const float* Ag  = A  + (size_t)(mblk + arow) * K + aseg * 2;
    const float* Ag2 = A2 ? A2 + (size_t)(mblk + arow) * K + aseg * 2 : (const float*)0;
    const float* Wg  = W + (size_t)wrow * N + nblk + wcol;

    // ldmatrix lane addressing for B: k = (lane&7) + 8*((lane>>3)&1), n += (lane>>4)*8
    const int bl_k = (lane & 7) + ((lane >> 3) & 1) * 8;
    const int bl_n = wn * 64 + (lane >> 4) * 8;

    float acc[2][8][4];
#pragma unroll
    for (int mi = 0; mi < 2; mi++)
#pragma unroll
        for (int ni = 0; ni < 8; ni++)
#pragma unroll
            for (int q = 0; q < 4; q++) acc[mi][ni][q] = 0.f;

    // stage 0
    {
        float4 a0 = *(const float4*)(Ag);
        float4 a1 = *(const float4*)(Ag + 4);
        if (Ag2) {
            float4 c0 = *(const float4*)(Ag2);
            float4 c1 = *(const float4*)(Ag2 + 4);
            a0.x += c0.x; a0.y += c0.y; a0.z += c0.z; a0.w += c0.w;
            a1.x += c1.x; a1.y += c1.y; a1.z += c1.z; a1.w += c1.w;
        }
        As2[0][arow][aseg+0] = pack2(a0.x, a0.y);
        As2[0][arow][aseg+1] = pack2(a0.z, a0.w);
        As2[0][arow][aseg+2] = pack2(a1.x, a1.y);
        As2[0][arow][aseg+3] = pack2(a1.z, a1.w);
        float4 w0 = *(const float4*)(Wg);
        float4 w1 = *(const float4*)(Wg + 4);
        __half2* bp = (__half2*)&Bs[0][wrow][wcol];
        bp[0] = __floats2half2_rn(w0.x, w0.y);
        bp[1] = __floats2half2_rn(w0.z, w0.w);
        bp[2] = __floats2half2_rn(w1.x, w1.y);
        bp[3] = __floats2half2_rn(w1.z, w1.w);
    }
    __syncthreads();

    const int nst = K >> 4;
    for (int s = 0; s < nst; s++) {
        const int buf = s & 1;
        const bool more = (s + 1 < nst);
        float4 pa0, pa1, pw0, pw1;
        if (more) {
            const float* Ap = Ag + (s + 1) * 16;
            const float* Wp = Wg + (size_t)(s + 1) * 16 * N;
            pa0 = *(const float4*)Ap; pa1 = *(const float4*)(Ap + 4);
            if (Ag2) {
                const float* Ap2 = Ag2 + (s + 1) * 16;
                float4 c0 = *(const float4*)Ap2;
                float4 c1 = *(const float4*)(Ap2 + 4);
                pa0.x += c0.x; pa0.y += c0.y; pa0.z += c0.z; pa0.w += c0.w;
                pa1.x += c1.x; pa1.y += c1.y; pa1.z += c1.z; pa1.w += c1.w;
            }
            pw0 = *(const float4*)Wp; pw1 = *(const float4*)(Wp + 4);
        }

        uint32_t af[2][4];
#pragma unroll
        for (int mi = 0; mi < 2; mi++) {
            int m = wm * 32 + mi * 16 + g;
            af[mi][0] = As2[buf][m    ][tg];
            af[mi][1] = As2[buf][m + 8][tg];
            af[mi][2] = As2[buf][m    ][tg + 4];
            af[mi][3] = As2[buf][m + 8][tg + 4];
        }
#pragma unroll
        for (int pair = 0; pair < 4; pair++) {
            uint32_t b00, b10, b01, b11;
            ldm4t(sptr(&Bs[buf][bl_k][bl_n + pair * 16]), b00, b10, b01, b11);
#pragma unroll
            for (int mi = 0; mi < 2; mi++) {
                mma16(acc[mi][2*pair    ], af[mi][0], af[mi][1], af[mi][2], af[mi][3], b00, b10);
                mma16(acc[mi][2*pair + 1], af[mi][0], af[mi][1], af[mi][2], af[mi][3], b01, b11);
            }
        }

        if (more) {
            const int nb = buf ^ 1;
            As2[nb][arow][aseg+0] = pack2(pa0.x, pa0.y);
            As2[nb][arow][aseg+1] = pack2(pa0.z, pa0.w);
            As2[nb][arow][aseg+2] = pack2(pa1.x, pa1.y);
            As2[nb][arow][aseg+3] = pack2(pa1.z, pa1.w);
            __half2* bp = (__half2*)&Bs[nb][wrow][wcol];
            bp[0] = __floats2half2_rn(pw0.x, pw0.y);
            bp[1] = __floats2half2_rn(pw0.z, pw0.w);
            bp[2] = __floats2half2_rn(pw1.x, pw1.y);
            bp[3] = __floats2half2_rn(pw1.z, pw1.w);
            __syncthreads();
        }
    }

#pragma unroll
    for (int mi = 0; mi < 2; mi++) {
        int r0 = mblk + wm * 32 + mi * 16 + g;
#pragma unroll
        for (int ni = 0; ni < 8; ni++) {
            int c = nblk + wn * 64 + ni * 8 + tg * 2;
            float b0 = bias[c], b1 = bias[c + 1];
            float v0 = acc[mi][ni][0] + b0, v1 = acc[mi][ni][1] + b1;
            float v2 = acc[mi][ni][2] + b0, v3 = acc[mi][ni][3] + b1;
            if (dogelu) {
                v0 = 0.5f * v0 * (1.0f + erff(v0 * 0.70710678118654752f));
                v1 = 0.5f * v1 * (1.0f + erff(v1 * 0.70710678118654752f));
                v2 = 0.5f * v2 * (1.0f + erff(v2 * 0.70710678118654752f));
                v3 = 0.5f * v3 * (1.0f + erff(v3 * 0.70710678118654752f));
            }
            if (Ch) {
                *(__half2*)&Ch[(size_t)r0 * N + c]       = __floats2half2_rn(v0, v1);
                *(__half2*)&Ch[(size_t)(r0 + 8) * N + c] = __floats2half2_rn(v2, v3);
            } else {
                *(float2*)&Cf[(size_t)r0 * N + c]       = make_float2(v0, v1);
                *(float2*)&Cf[(size_t)(r0 + 8) * N + c] = make_float2(v2, v3);
            }
        }
    }
}

__global__ __launch_bounds__(256) void gemm_k(
    const float* __restrict__ A, const float* __restrict__ W,
    const float* __restrict__ bias, float* __restrict__ C,
    int K, int N, int dogelu)
{
    gemm16_body(A, (const float*)0, W, bias, C, (__half*)0, K, N, dogelu);
}

// GEMM with elementwise-summed A operand: C = (A + A2) @ W + bias
__global__ __launch_bounds__(256) void gemm2_k(
    const float* __restrict__ A, const float* __restrict__ A2,
    const float* __restrict__ W,
    const float* __restrict__ bias, float* __restrict__ C,
    int K, int N, int dogelu)
{
    gemm16_body(A, A2, W, bias, C, (__half*)0, K, N, dogelu);
}

// Batched projections (fp16 out): z=0..7 -> (layer z/2, Q/K), z=8 -> V3.
__global__ __launch_bounds__(256) void proj_k(
    const float* __restrict__ x, const float* __restrict__ y,
    const float* __restrict__ Wq, const float* __restrict__ bq,
    const float* __restrict__ Wk, const float* __restrict__ bk,
    const float* __restrict__ Wv, const float* __restrict__ bv,
    __half* __restrict__ QK, __half* __restrict__ V)
{
    const int z = blockIdx.z;
    const float *A, *W, *Bi;
    __half* C;
    if (z < 8) {
        int l = z >> 1, isK = z & 1;
        A  = isK ? y : x;
        W  = (isK ? Wk : Wq) + (size_t)l * EC * EC;
        Bi = (isK ? bk : bq) + (size_t)l * EC;
        C  = QK + (size_t)z * BNE;
    } else {
        A = y; W = Wv + (size_t)3 * EC * EC; Bi = bv + (size_t)3 * EC; C = V;
    }
    gemm16_body(A, (const float*)0, W, Bi, (float*)0, C, EC, EC, 0);
}

// ---------------------------------------------------------------------------
// Scores (all layers/heads): S = (Q @ K^T)*0.125, masked, fp16 in+out.
// FAITHFUL head split: head block = contiguous [1024 x 64] chunk at
// element offset b*NX*E + h*NX*DH (row stride DH = 32 uint32).
// Grid (NY/128, NX/128, 4*32), 256 threads.
// ---------------------------------------------------------------------------
__global__ __launch_bounds__(256) void scores_k(
    const __half* __restrict__ QK, const int* __restrict__ xm,
    const int* __restrict__ ym, __half* __restrict__ S4)
{
    __shared__ uint32_t Qs2[128][36];   // [m][kpair 0..31]
    __shared__ uint32_t Ks2[128][36];   // [n][kpair 0..31]

    const int z = blockIdx.z;
    const int l = z >> 5, bh = z & 31, b = bh >> 3, h = bh & 7;
    const uint32_t* Qb = (const uint32_t*)(QK + (size_t)(2 * l) * BNE)
                         + (size_t)b * NXC * 256 + (size_t)h * NXC * 32;
    const uint32_t* Kb = (const uint32_t*)(QK + (size_t)(2 * l + 1) * BNE)
                         + (size_t)b * NYC * 256 + (size_t)h * NYC * 32;

    const int mblk = blockIdx.y * 128;
    const int nblk = blockIdx.x * 128;
    const int tid  = threadIdx.x;
    const int warp = tid >> 5, lane = tid & 31;
    const int wm = warp >> 1, wn = warp & 1;
    const int g = lane >> 2, tg = lane & 3;

    for (int t = tid; t < 128 * 32; t += 256) {
        int r = t >> 5, p = t & 31;
        Qs2[r][p] = Qb[(size_t)(mblk + r) * 32 + p];
        Ks2[r][p] = Kb[(size_t)(nblk + r) * 32 + p];
    }
    __syncthreads();

    float acc[2][8][4];
#pragma unroll
    for (int mi = 0; mi < 2; mi++)
#pragma unroll
        for (int ni = 0; ni < 8; ni++)
#pragma unroll
            for (int q = 0; q < 4; q++) acc[mi][ni][q] = 0.f;

#pragma unroll
    for (int c = 0; c < 4; c++) {          // 4 chunks of k16
        uint32_t af[2][4];
#pragma unroll
        for (int mi = 0; mi < 2; mi++) {
            int m = wm * 32 + mi * 16 + g;
            af[mi][0] = Qs2[m    ][8*c + tg];
            af[mi][1] = Qs2[m + 8][8*c + tg];
            af[mi][2] = Qs2[m    ][8*c + tg + 4];
            af[mi][3] = Qs2[m + 8][8*c + tg + 4];
        }
#pragma unroll
        for (int ni = 0; ni < 8; ni++) {
            int n = wn * 64 + ni * 8 + g;
            uint32_t b0 = Ks2[n][8*c + tg];
            uint32_t b1 = Ks2[n][8*c + tg + 4];
#pragma unroll
            for (int mi = 0; mi < 2; mi++)
                mma16(acc[mi][ni], af[mi][0], af[mi][1], af[mi][2], af[mi][3], b0, b1);
        }
    }

    __half* Sl = S4 + (size_t)l * BHNN + (size_t)bh * NXC * NYC;
#pragma unroll
    for (int mi = 0; mi < 2; mi++) {
        int r0 = mblk + wm * 32 + mi * 16 + g;
        int xr0 = xm[b * NXC + r0], xr1 = xm[b * NXC + r0 + 8];
#pragma unroll
        for (int ni = 0; ni < 8; ni++) {
            int c = nblk + wn * 64 + ni * 8 + tg * 2;
            int yc0 = ym[b * NYC + c], yc1 = ym[b * NYC + c + 1];
            float v0 = (xr0 && yc0) ? acc[mi][ni][0] * 0.125f : MASKED_H;
            float v1 = (xr0 && yc1) ? acc[mi][ni][1] * 0.125f : MASKED_H;
            float v2 = (xr1 && yc0) ? acc[mi][ni][2] * 0.125f : MASKED_H;
            float v3 = (xr1 && yc1) ? acc[mi][ni][3] * 0.125f : MASKED_H;
            *(__half2*)&Sl[(size_t)r0 * NYC + c]       = __floats2half2_rn(v0, v1);
            *(__half2*)&Sl[(size_t)(r0 + 8) * NYC + c] = __floats2half2_rn(v2, v3);
        }
    }
}

// ---------------------------------------------------------------------------
// Fused softmax-sum: A[row] = sum_{l=0..3} softmax(S_l[row]). fp16 in/out.
// ---------------------------------------------------------------------------
__global__ __launch_bounds__(256) void softmax4_k(
    const __half* __restrict__ S4, __half* __restrict__ A)
{
    __shared__ float sred[8];
    __shared__ float sbc;

    const size_t base = (size_t)blockIdx.x * NYC;
    const int tid = threadIdx.x, lane = tid & 31, w = tid >> 5;

    float acc[4] = {0.f, 0.f, 0.f, 0.f};

#pragma unroll
    for (int l = 0; l < 4; l++) {
        const __half2* S2 = (const __half2*)(S4 + (size_t)l * BHNN + base) + tid * 2;
        float2 f01 = __half22float2(S2[0]);
        float2 f23 = __half22float2(S2[1]);
        float v[4] = {f01.x, f01.y, f23.x, f23.y};

        float m = fmaxf(fmaxf(v[0], v[1]), fmaxf(v[2], v[3]));
#pragma unroll
        for (int o = 16; o > 0; o >>= 1) m = fmaxf(m, __shfl_xor_sync(0xffffffffu, m, o));
        if (lane == 0) sred[w] = m;
        __syncthreads();
        if (tid == 0) {
            float t = sred[0];
#pragma unroll
            for (int i = 1; i < 8; i++) t = fmaxf(t, sred[i]);
            sbc = t;
        }
        __syncthreads();
        const float bm = sbc;

        float p[4], s = 0.f;
#pragma unroll
        for (int i = 0; i < 4; i++) { p[i] = __expf(v[i] - bm); s += p[i]; }
#pragma unroll
        for (int o = 16; o > 0; o >>= 1) s += __shfl_xor_sync(0xffffffffu, s, o);
        if (lane == 0) sred[w] = s;
        __syncthreads();
        if (tid == 0) {
            float t = 0.f;
#pragma unroll
            for (int i = 0; i < 8; i++) t += sred[i];
            sbc = t;
        }
        __syncthreads();
        const float inv = 1.0f / sbc;
#pragma unroll
        for (int i = 0; i < 4; i++) acc[i] += p[i] * inv;
        __syncthreads();
    }

    *(__half2*)&A[base + tid * 4]     = __floats2half2_rn(acc[0], acc[1]);
    *(__half2*)&A[base + tid * 4 + 2] = __floats2half2_rn(acc[2], acc[3]);
}

// ---------------------------------------------------------------------------
// O_partial = attn[:, z*512:(z+1)*512] @ V[z*512:(z+1)*512, :]
// FAITHFUL V head split (contiguous [NY x DH] chunk, row stride DH).
// Block 64x64, 128 threads, BK=32, split-K=2 via blockIdx.z.
// V fragments via ldmatrix.x4.trans (stride 136 halves, conflict-free).
// Grid (NX/64, B*H, 2).
// ---------------------------------------------------------------------------
__global__ __launch_bounds__(128) void attnv_k(
    const __half* __restrict__ Aa, const __half* __restrict__ V,
    float* __restrict__ O0, float* __restrict__ O1)
{
    __shared__ uint32_t As2[2][64][20];   // [m][kpair 0..15]
    __shared__ __half   Vs [2][32][136];  // [k][n], stride 136 halves

    const int bh = blockIdx.y, b = bh >> 3, h = bh & 7;
    const int mblk = blockIdx.x * 64;
    const int zz = blockIdx.z;            // split-K index
    const int tid = threadIdx.x;
    const int warp = tid >> 5, lane = tid & 31;
    const int g = lane >> 2, tg = lane & 3;

    const uint32_t* Ab = (const uint32_t*)(Aa + (size_t)bh * NXC * NYC);
    const __half* Vb = V + (size_t)b * NYC * EC + (size_t)h * NYC * DHC
                         + (size_t)zz * 512 * DHC;

    const int arow = tid >> 1, aseg = (tid & 1) * 8;   // kpair offset 0/8
    const int vrow = tid >> 2, vcol = (tid & 3) * 16;  // k row 0..31

    const uint32_t* Ag = Ab + (size_t)(mblk + arow) * 512 + zz * 256 + aseg;

    // ldmatrix lane addressing for V
    const int vl_k = (lane & 7) + ((lane >> 3) & 1) * 8;
    const int vl_n = (lane >> 4) * 8;

    float acc[8][4];
#pragma unroll
    for (int ni = 0; ni < 8; ni++)
#pragma unroll
        for (int q = 0; q < 4; q++) acc[ni][q] = 0.f;

    // stage 0
    {
        uint4 u0 = *(const uint4*)(Ag);
        uint4 u1 = *(const uint4*)(Ag + 4);
        As2[0][arow][aseg+0]=u0.x; As2[0][arow][aseg+1]=u0.y;
        As2[0][arow][aseg+2]=u0.z; As2[0][arow][aseg+3]=u0.w;
        As2[0][arow][aseg+4]=u1.x; As2[0][arow][aseg+5]=u1.y;
        As2[0][arow][aseg+6]=u1.z; As2[0][arow][aseg+7]=u1.w;
        const __half* Vg = Vb + (size_t)vrow * DHC + vcol;
        *(uint4*)&Vs[0][vrow][vcol]     = *(const uint4*)(Vg);
        *(uint4*)&Vs[0][vrow][vcol + 8] = *(const uint4*)(Vg + 8);
    }
    __syncthreads();

    for (int s = 0; s < 16; s++) {
        const int buf = s & 1;
        const bool more = (s + 1 < 16);
        uint4 pa0, pa1, pv0, pv1;
        if (more) {
            const uint32_t* Ap = Ag + (s + 1) * 16;
            pa0 = *(const uint4*)(Ap);
            pa1 = *(const uint4*)(Ap + 4);
            const __half* Vg = Vb + (size_t)((s + 1) * 32 + vrow) * DHC + vcol;
            pv0 = *(const uint4*)(Vg);
            pv1 = *(const uint4*)(Vg + 8);
        }

#pragma unroll
        for (int cc = 0; cc < 2; cc++) {
            int m = warp * 16 + g;
            uint32_t a0 = As2[buf][m    ][8*cc + tg];
            uint32_t a1 = As2[buf][m + 8][8*cc + tg];
            uint32_t a2 = As2[buf][m    ][8*cc + tg + 4];
            uint32_t a3 = As2[buf][m + 8][8*cc + tg + 4];
#pragma unroll
            for (int pair = 0; pair < 4; pair++) {
                uint32_t b00, b10, b01, b11;
                ldm4t(sptr(&Vs[buf][16*cc + vl_k][pair * 16 + vl_n]), b00, b10, b01, b11);
                mma16(acc[2*pair    ], a0, a1, a2, a3, b00, b10);
                mma16(acc[2*pair + 1], a0, a1, a2, a3, b01, b11);
            }
        }

        if (more) {
            const int nb = buf ^ 1;
            As2[nb][arow][aseg+0]=pa0.x; As2[nb][arow][aseg+1]=pa0.y;
            As2[nb][arow][aseg+2]=pa0.z; As2[nb][arow][aseg+3]=pa0.w;
            As2[nb][arow][aseg+4]=pa1.x; As2[nb][arow][aseg+5]=pa1.y;
            As2[nb][arow][aseg+6]=pa1.z; As2[nb][arow][aseg+7]=pa1.w;
            *(uint4*)&Vs[nb][vrow][vcol]     = pv0;
            *(uint4*)&Vs[nb][vrow][vcol + 8] = pv1;
            __syncthreads();
        }
    }

    // Output partial: transposed layout O[b, n, h*DH + d] (standard rows)
    float* Op = (zz == 0 ? O0 : O1);
    const int r0 = mblk + warp * 16 + g;
    float* Ob = Op + (size_t)b * NXC * EC + (size_t)h * DHC;
#pragma unroll
    for (int ni = 0; ni < 8; ni++) {
        int c = ni * 8 + tg * 2;
        *(float2*)&Ob[(size_t)r0 * EC + c]       = make_float2(acc[ni][0], acc[ni][1]);
        *(float2*)&Ob[(size_t)(r0 + 8) * EC + c] = make_float2(acc[ni][2], acc[ni][3]);
    }
}

// ---------------------------------------------------------------------------
// Residual + LayerNorm: Out[row] = LN(X[row] + R[row]) * g + be
// ---------------------------------------------------------------------------
__global__ __launch_bounds__(128) void resln_k(
    const float* __restrict__ X, const float* __restrict__ R,
    const float* __restrict__ g, const float* __restrict__ be,
    float* __restrict__ Out)
{
    __shared__ float sred[4];
    __shared__ float sbc;

    const size_t base = (size_t)blockIdx.x * EC;
    const int tid = threadIdx.x, lane = tid & 31, w = tid >> 5;

    float r[4];
    int col[4];
#pragma unroll
    for (int i = 0; i < 4; i++) {
        col[i] = tid + i * 128;
        r[i] = X[base + col[i]] + R[base + col[i]];
    }

    float s = r[0] + r[1] + r[2] + r[3];
#pragma unroll
    for (int o = 16; o > 0; o >>= 1) s += __shfl_xor_sync(0xffffffffu, s, o);
    if (lane == 0) sred[w] = s;
    __syncthreads();
    if (tid == 0) sbc = sred[0] + sred[1] + sred[2] + sred[3];
    __syncthreads();
    const float mu = sbc * (1.0f / EC);

    float d[4], ss = 0.f;
#pragma unroll
    for (int i = 0; i < 4; i++) { d[i] = r[i] - mu; ss += d[i] * d[i]; }
#pragma unroll
    for (int o = 16; o > 0; o >>= 1) ss += __shfl_xor_sync(0xffffffffu, ss, o);
    if (lane == 0) sred[w] = ss;
    __syncthreads();
    if (tid == 0) sbc = sred[0] + sred[1] + sred[2] + sred[3];
    __syncthreads();
    const float rs = rsqrtf(sbc * (1.0f / EC) + 1e-5f);

#pragma unroll
    for (int i = 0; i < 4; i++)
        Out[base + col[i]] = d[i] * rs * g[col[i]] + be[col[i]];
}

// ---------------------------------------------------------------------------
// Host
// ---------------------------------------------------------------------------
extern "C" void kernel_launch(void* const* d_in, const int* in_sizes, int n_in,
                              void* d_out, int out_size)
{
    (void)in_sizes; (void)n_in; (void)out_size;

    const float* x   = (const float*)d_in[0];
    const float* y   = (const float*)d_in[1];
    const int*   xm  = (const int*)  d_in[2];
    const int*   ym  = (const int*)  d_in[3];
    const float* Wq  = (const float*)d_in[4];
    const float* bq  = (const float*)d_in[5];
    const float* Wk  = (const float*)d_in[6];
    const float* bk  = (const float*)d_in[7];
    const float* Wv  = (const float*)d_in[8];
    const float* bv  = (const float*)d_in[9];
    const float* Wo  = (const float*)d_in[10];
    const float* bo  = (const float*)d_in[11];
    const float* g1  = (const float*)d_in[12];
    const float* be1 = (const float*)d_in[13];
    const float* g2  = (const float*)d_in[14];
    const float* be2 = (const float*)d_in[15];
    const float* W1  = (const float*)d_in[16];
    const float* bf1 = (const float*)d_in[17];
    const float* W2  = (const float*)d_in[18];
    const float* bf2 = (const float*)d_in[19];
    float* out = (float*)d_out;

    float *O, *O2, *Hb, *F1, *F2;
    __half *QK, *V, *S4, *Aa;
    cudaGetSymbolAddress((void**)&QK, g_QK);
    cudaGetSymbolAddress((void**)&V,  g_V);
    cudaGetSymbolAddress((void**)&O,  g_O);
    cudaGetSymbolAddress((void**)&O2, g_O2);
    cudaGetSymbolAddress((void**)&Hb, g_Hb);
    cudaGetSymbolAddress((void**)&F1, g_F1);
    cudaGetSymbolAddress((void**)&F2, g_F2);
    cudaGetSymbolAddress((void**)&S4, g_S4);
    cudaGetSymbolAddress((void**)&Aa, g_A);

    // 1. All Q_l, K_l projections + V_3 in one launch (9 GEMM slices, fp16 out)
    proj_k<<<dim3(4, 32, 9), 256>>>(x, y, Wq, bq, Wk, bk, Wv, bv, QK, V);
    // 2. All layers' masked scores in one launch (fp16 in/out)
    scores_k<<<dim3(8, 8, 128), 256>>>(QK, xm, ym, S4);
    // 3. Single fused softmax-sum (a_3 = sum_l softmax(S_l)), fp16 out
    softmax4_k<<<BB * HC * NXC, 256>>>(S4, Aa);
    // 4. attn @ V with split-K=2 (partials in O, O2)
    attnv_k<<<dim3(16, 32, 2), 128>>>(Aa, V, O, O2);
    // 5. Wo GEMM sums the partials on the fly: F2 = (O + O2) @ Wo + bo
    gemm2_k<<<dim3(4, 32), 256>>>(O, O2, Wo + (size_t)3 * EC * EC, bo + 3 * EC, F2, EC, EC, 0);
    resln_k<<<MC, 128>>>(x, F2, g1 + 3 * EC, be1 + 3 * EC, Hb);
    gemm_k<<<dim3(16, 32), 256>>>(Hb, W1 + (size_t)3 * EC * FFC, bf1 + (size_t)3 * FFC, F1, EC, FFC, 1);
    gemm_k<<<dim3(4, 32), 256>>>(F1, W2 + (size_t)3 * FFC * EC, bf2 + 3 * EC, O, FFC, EC, 0);
    resln_k<<<MC, 128>>>(Hb, O, g2 + 3 * EC, be2 + 3 * EC, out);
}

// round 12
// speedup vs baseline: 3.2748x; 1.0662x over previous
#include <cuda_runtime.h>
#include <cuda_fp16.h>
#include <math.h>
#include <stdint.h>

// Problem constants
#define BB   4
#define NXC  1024
#define NYC  1024
#define EC   512
#define HC   8
#define DHC  64
#define LC   4
#define FFC  2048
#define MC   (BB * NXC)

#define BNE  (BB * NXC * EC)                  // 2,097,152
#define BHNN ((size_t)BB * HC * NXC * NYC)    // 33,554,432

// ---------------------------------------------------------------------------
// Scratch (device globals; allocation-free per harness rules)
// ---------------------------------------------------------------------------
__device__ __half g_QK[8 * (size_t)BNE];      // Q0,K0,..,Q3,K3 fp16 (32MB)
__device__ __half g_V [BNE];                  // V3 fp16
__device__ float  g_O [BNE];                  // attnv partial 0 / W2 out
__device__ float  g_O2[BNE];                  // attnv partial 1
__device__ float  g_Hb[BNE];
__device__ float  g_F1[(size_t)MC * FFC];
__device__ float  g_F2[BNE];                  // Wo out
__device__ __half g_S4[4 * BHNN];             // 4 layers' raw scores fp16 (256MB)
__device__ __half g_A [BHNN];                 // summed attention fp16 (64MB)

#define MASKED_H (-30000.0f)

// ---------------------------------------------------------------------------
// FP16 MMA helpers (fp32 accumulate)
// ---------------------------------------------------------------------------
__device__ __forceinline__ uint32_t pack2(float a, float b) {
    __half2 h = __floats2half2_rn(a, b);
    return *(uint32_t*)&h;
}

__device__ __forceinline__ uint32_t sptr(const void* p) {
    return (uint32_t)__cvta_generic_to_shared(p);
}

__device__ __forceinline__ void mma16(float* c,
    uint32_t a0, uint32_t a1, uint32_t a2, uint32_t a3,
    uint32_t b0, uint32_t b1)
{
    asm volatile(
        "mma.sync.aligned.m16n8k16.row.col.f32.f16.f16.f32 "
        "{%0,%1,%2,%3},{%4,%5,%6,%7},{%8,%9},{%0,%1,%2,%3};"
        : "+f"(c[0]), "+f"(c[1]), "+f"(c[2]), "+f"(c[3])
        : "r"(a0), "r"(a1), "r"(a2), "r"(a3), "r"(b0), "r"(b1));
}

// ldmatrix x4 transposed (B fragments from [k][n] smem tiles)
__device__ __forceinline__ void ldm4t(uint32_t addr,
    uint32_t& r0, uint32_t& r1, uint32_t& r2, uint32_t& r3)
{
    asm volatile(
        "ldmatrix.sync.aligned.m8n8.x4.trans.shared.b16 {%0,%1,%2,%3}, [%4];"
        : "=r"(r0), "=r"(r1), "=r"(r2), "=r"(r3) : "r"(addr));
}

// ldmatrix x4 non-transposed (A fragments / k-contiguous B fragments)
__device__ __forceinline__ void ldm4(uint32_t addr,
    uint32_t& r0, uint32_t& r1, uint32_t& r2, uint32_t& r3)
{
    asm volatile(
        "ldmatrix.sync.aligned.m8n8.x4.shared.b16 {%0,%1,%2,%3}, [%4];"
        : "=r"(r0), "=r"(r1), "=r"(r2), "=r"(r3) : "r"(addr));
}

// Lane offsets for A-type ldmatrix.x4 (m16k16 fragment from [m][kpair] tile):
//   matrices: (m0..7,k0..7) (m8..15,k0..7) (m0..7,k8..15) (m8..15,k8..15)
#define LA_ROW(lane) (((lane) & 7) + (((lane) >> 3) & 1) * 8)
#define LA_COL(lane) ((((lane) >> 4) & 1) * 4)
// Lane offsets for scores K-side ldmatrix.x4 ([n][kpair] tile, two n-groups):
//   matrices: b0(g0) b1(g0) b0(g1) b1(g1)
#define LB_ROW(lane) (((lane) & 7) + (((lane) >> 4) & 1) * 8)
#define LB_COL(lane) ((((lane) >> 3) & 1) * 4)

// ---------------------------------------------------------------------------
// FP16 GEMM body: C[M,N] = (A (+A2?)) @ W[K,N] + bias (opt exact GELU)
// block 128x128, BK=16, 256 threads (8 warps 4x2), warp tile 32x64.
// A fragments: ldmatrix.x4; B fragments: ldmatrix.x4.trans.
// ---------------------------------------------------------------------------
__device__ __forceinline__ void gemm16_body(
    const float* __restrict__ A, const float* __restrict__ A2,
    const float* __restrict__ W,
    const float* __restrict__ bias, float* __restrict__ Cf,
    __half* __restrict__ Ch, int K, int N, int dogelu)
{
    __shared__ uint32_t As2[2][128][12];   // [m][kpair 0..7], stride 12 words
    __shared__ __half   Bs [2][16][136];   // [k][n], stride 136 halves

    const int tid  = threadIdx.x;
    const int warp = tid >> 5, lane = tid & 31;
    const int wm = warp >> 1, wn = warp & 1;
    const int g  = lane >> 2, tg = lane & 3;
    const int mblk = blockIdx.y * 128, nblk = blockIdx.x * 128;

    const int arow = tid >> 1, aseg = (tid & 1) * 4;    // kpair offset 0/4
    const int wrow = tid >> 4, wcol = (tid & 15) * 8;   // k row 0..15

    const float* Ag  = A  + (size_t)(mblk + arow) * K + aseg * 2;
    const float* Ag2 = A2 ? A2 + (size_t)(mblk + arow) * K + aseg * 2 : (const float*)0;
    const float* Wg  = W + (size_t)wrow * N + nblk + wcol;

    const int la_r = LA_ROW(lane), la_c = LA_COL(lane);
    const int bl_k = (lane & 7) + ((lane >> 3) & 1) * 8;
    const int bl_n = wn * 64 + (lane >> 4) * 8;

    float acc[2][8][4];
#pragma unroll
    for (int mi = 0; mi < 2; mi++)
#pragma unroll
        for (int ni = 0; ni < 8; ni++)
#pragma unroll
            for (int q = 0; q < 4; q++) acc[mi][ni][q] = 0.f;

    // stage 0
    {
        float4 a0 = *(const float4*)(Ag);
        float4 a1 = *(const float4*)(Ag + 4);
        if (Ag2) {
            float4 c0 = *(const float4*)(Ag2);
            float4 c1 = *(const float4*)(Ag2 + 4);
            a0.x += c0.x; a0.y += c0.y; a0.z += c0.z; a0.w += c0.w;
            a1.x += c1.x; a1.y += c1.y; a1.z += c1.z; a1.w += c1.w;
        }
        As2[0][arow][aseg+0] = pack2(a0.x, a0.y);
        As2[0][arow][aseg+1] = pack2(a0.z, a0.w);
        As2[0][arow][aseg+2] = pack2(a1.x, a1.y);
        As2[0][arow][aseg+3] = pack2(a1.z, a1.w);
        float4 w0 = *(const float4*)(Wg);
        float4 w1 = *(const float4*)(Wg + 4);
        __half2* bp = (__half2*)&Bs[0][wrow][wcol];
        bp[0] = __floats2half2_rn(w0.x, w0.y);
        bp[1] = __floats2half2_rn(w0.z, w0.w);
        bp[2] = __floats2half2_rn(w1.x, w1.y);
        bp[3] = __floats2half2_rn(w1.z, w1.w);
    }
    __syncthreads();

    const int nst = K >> 4;
    for (int s = 0; s < nst; s++) {
        const int buf = s & 1;
        const bool more = (s + 1 < nst);
        float4 pa0, pa1, pw0, pw1;
        if (more) {
            const float* Ap = Ag + (s + 1) * 16;
            const float* Wp = Wg + (size_t)(s + 1) * 16 * N;
            pa0 = *(const float4*)Ap; pa1 = *(const float4*)(Ap + 4);
            if (Ag2) {
                const float* Ap2 = Ag2 + (s + 1) * 16;
                float4 c0 = *(const float4*)Ap2;
                float4 c1 = *(const float4*)(Ap2 + 4);
                pa0.x += c0.x; pa0.y += c0.y; pa0.z += c0.z; pa0.w += c0.w;
                pa1.x += c1.x; pa1.y += c1.y; pa1.z += c1.z; pa1.w += c1.w;
            }
            pw0 = *(const float4*)Wp; pw1 = *(const float4*)(Wp + 4);
        }

        uint32_t af[2][4];
#pragma unroll
        for (int mi = 0; mi < 2; mi++)
            ldm4(sptr(&As2[buf][wm * 32 + mi * 16 + la_r][la_c]),
                 af[mi][0], af[mi][1], af[mi][2], af[mi][3]);
#pragma unroll
        for (int pair = 0; pair < 4; pair++) {
            uint32_t b00, b10, b01, b11;
            ldm4t(sptr(&Bs[buf][bl_k][bl_n + pair * 16]), b00, b10, b01, b11);
#pragma unroll
            for (int mi = 0; mi < 2; mi++) {
                mma16(acc[mi][2*pair    ], af[mi][0], af[mi][1], af[mi][2], af[mi][3], b00, b10);
                mma16(acc[mi][2*pair + 1], af[mi][0], af[mi][1], af[mi][2], af[mi][3], b01, b11);
            }
        }

        if (more) {
            const int nb = buf ^ 1;
            As2[nb][arow][aseg+0] = pack2(pa0.x, pa0.y);
            As2[nb][arow][aseg+1] = pack2(pa0.z, pa0.w);
            As2[nb][arow][aseg+2] = pack2(pa1.x, pa1.y);
            As2[nb][arow][aseg+3] = pack2(pa1.z, pa1.w);
            __half2* bp = (__half2*)&Bs[nb][wrow][wcol];
            bp[0] = __floats2half2_rn(pw0.x, pw0.y);
            bp[1] = __floats2half2_rn(pw0.z, pw0.w);
            bp[2] = __floats2half2_rn(pw1.x, pw1.y);
            bp[3] = __floats2half2_rn(pw1.z, pw1.w);
            __syncthreads();
        }
    }

#pragma unroll
    for (int mi = 0; mi < 2; mi++) {
        int r0 = mblk + wm * 32 + mi * 16 + g;
#pragma unroll
        for (int ni = 0; ni < 8; ni++) {
            int c = nblk + wn * 64 + ni * 8 + tg * 2;
            float b0 = bias[c], b1 = bias[c + 1];
            float v0 = acc[mi][ni][0] + b0, v1 = acc[mi][ni][1] + b1;
            float v2 = acc[mi][ni][2] + b0, v3 = acc[mi][ni][3] + b1;
            if (dogelu) {
                v0 = 0.5f * v0 * (1.0f + erff(v0 * 0.70710678118654752f));
                v1 = 0.5f * v1 * (1.0f + erff(v1 * 0.70710678118654752f));
                v2 = 0.5f * v2 * (1.0f + erff(v2 * 0.70710678118654752f));
                v3 = 0.5f * v3 * (1.0f + erff(v3 * 0.70710678118654752f));
            }
            if (Ch) {
                *(__half2*)&Ch[(size_t)r0 * N + c]       = __floats2half2_rn(v0, v1);
                *(__half2*)&Ch[(size_t)(r0 + 8) * N + c] = __floats2half2_rn(v2, v3);
            } else {
                *(float2*)&Cf[(size_t)r0 * N + c]       = make_float2(v0, v1);
                *(float2*)&Cf[(size_t)(r0 + 8) * N + c] = make_float2(v2, v3);
            }
        }
    }
}

__global__ __launch_bounds__(256) void gemm_k(
    const float* __restrict__ A, const float* __restrict__ W,
    const float* __restrict__ bias, float* __restrict__ C,
    int K, int N, int dogelu)
{
    gemm16_body(A, (const float*)0, W, bias, C, (__half*)0, K, N, dogelu);
}

// GEMM with elementwise-summed A operand: C = (A + A2) @ W + bias
__global__ __launch_bounds__(256) void gemm2_k(
    const float* __restrict__ A, const float* __restrict__ A2,
    const float* __restrict__ W,
    const float* __restrict__ bias, float* __restrict__ C,
    int K, int N, int dogelu)
{
    gemm16_body(A, A2, W, bias, C, (__half*)0, K, N, dogelu);
}

// Batched projections (fp16 out): z=0..7 -> (layer z/2, Q/K), z=8 -> V3.
__global__ __launch_bounds__(256) void proj_k(
    const float* __restrict__ x, const float* __restrict__ y,
    const float* __restrict__ Wq, const float* __restrict__ bq,
    const float* __restrict__ Wk, const float* __restrict__ bk,
    const float* __restrict__ Wv, const float* __restrict__ bv,
    __half* __restrict__ QK, __half* __restrict__ V)
{
    const int z = blockIdx.z;
    const float *A, *W, *Bi;
    __half* C;
    if (z < 8) {
        int l = z >> 1, isK = z & 1;
        A  = isK ? y : x;
        W  = (isK ? Wk : Wq) + (size_t)l * EC * EC;
        Bi = (isK ? bk : bq) + (size_t)l * EC;
        C  = QK + (size_t)z * BNE;
    } else {
        A = y; W = Wv + (size_t)3 * EC * EC; Bi = bv + (size_t)3 * EC; C = V;
    }
    gemm16_body(A, (const float*)0, W, Bi, (float*)0, C, EC, EC, 0);
}

// ---------------------------------------------------------------------------
// Scores (all layers/heads): S = (Q @ K^T)*0.125, masked, fp16 in+out.
// FAITHFUL head split: contiguous [1024 x 64] chunk at b*NX*E + h*NX*DH.
// Both operand fragments via ldmatrix.x4 (non-trans; [r][kpair] tiles).
// Grid (NY/128, NX/128, 4*32), 256 threads.
// ---------------------------------------------------------------------------
__global__ __launch_bounds__(256) void scores_k(
    const __half* __restrict__ QK, const int* __restrict__ xm,
    const int* __restrict__ ym, __half* __restrict__ S4)
{
    __shared__ uint32_t Qs2[128][36];   // [m][kpair 0..31]
    __shared__ uint32_t Ks2[128][36];   // [n][kpair 0..31]

    const int z = blockIdx.z;
    const int l = z >> 5, bh = z & 31, b = bh >> 3, h = bh & 7;
    const uint32_t* Qb = (const uint32_t*)(QK + (size_t)(2 * l) * BNE)
                         + (size_t)b * NXC * 256 + (size_t)h * NXC * 32;
    const uint32_t* Kb = (const uint32_t*)(QK + (size_t)(2 * l + 1) * BNE)
                         + (size_t)b * NYC * 256 + (size_t)h * NYC * 32;

    const int mblk = blockIdx.y * 128;
    const int nblk = blockIdx.x * 128;
    const int tid  = threadIdx.x;
    const int warp = tid >> 5, lane = tid & 31;
    const int wm = warp >> 1, wn = warp & 1;
    const int g = lane >> 2, tg = lane & 3;

    const int la_r = LA_ROW(lane), la_c = LA_COL(lane);
    const int lb_r = LB_ROW(lane), lb_c = LB_COL(lane);

    for (int t = tid; t < 128 * 32; t += 256) {
        int r = t >> 5, p = t & 31;
        Qs2[r][p] = Qb[(size_t)(mblk + r) * 32 + p];
        Ks2[r][p] = Kb[(size_t)(nblk + r) * 32 + p];
    }
    __syncthreads();

    float acc[2][8][4];
#pragma unroll
    for (int mi = 0; mi < 2; mi++)
#pragma unroll
        for (int ni = 0; ni < 8; ni++)
#pragma unroll
            for (int q = 0; q < 4; q++) acc[mi][ni][q] = 0.f;

#pragma unroll
    for (int c = 0; c < 4; c++) {          // 4 chunks of k16
        uint32_t af[2][4];
#pragma unroll
        for (int mi = 0; mi < 2; mi++)
            ldm4(sptr(&Qs2[wm * 32 + mi * 16 + la_r][8 * c + la_c]),
                 af[mi][0], af[mi][1], af[mi][2], af[mi][3]);
#pragma unroll
        for (int nq = 0; nq < 4; nq++) {   // 4 pairs of n-groups (16 n each)
            uint32_t b00, b01, b10, b11;
            ldm4(sptr(&Ks2[wn * 64 + nq * 16 + lb_r][8 * c + lb_c]),
                 b00, b01, b10, b11);
#pragma unroll
            for (int mi = 0; mi < 2; mi++) {
                mma16(acc[mi][2*nq    ], af[mi][0], af[mi][1], af[mi][2], af[mi][3], b00, b01);
                mma16(acc[mi][2*nq + 1], af[mi][0], af[mi][1], af[mi][2], af[mi][3], b10, b11);
            }
        }
    }

    __half* Sl = S4 + (size_t)l * BHNN + (size_t)bh * NXC * NYC;
#pragma unroll
    for (int mi = 0; mi < 2; mi++) {
        int r0 = mblk + wm * 32 + mi * 16 + g;
        int xr0 = xm[b * NXC + r0], xr1 = xm[b * NXC + r0 + 8];
#pragma unroll
        for (int ni = 0; ni < 8; ni++) {
            int c = nblk + wn * 64 + ni * 8 + tg * 2;
            int yc0 = ym[b * NYC + c], yc1 = ym[b * NYC + c + 1];
            float v0 = (xr0 && yc0) ? acc[mi][ni][0] * 0.125f : MASKED_H;
            float v1 = (xr0 && yc1) ? acc[mi][ni][1] * 0.125f : MASKED_H;
            float v2 = (xr1 && yc0) ? acc[mi][ni][2] * 0.125f : MASKED_H;
            float v3 = (xr1 && yc1) ? acc[mi][ni][3] * 0.125f : MASKED_H;
            *(__half2*)&Sl[(size_t)r0 * NYC + c]       = __floats2half2_rn(v0, v1);
            *(__half2*)&Sl[(size_t)(r0 + 8) * NYC + c] = __floats2half2_rn(v2, v3);
        }
    }
}

// ---------------------------------------------------------------------------
// Fused softmax-sum: A[row] = sum_{l=0..3} softmax(S_l[row]). fp16 in/out.
// ---------------------------------------------------------------------------
__global__ __launch_bounds__(256) void softmax4_k(
    const __half* __restrict__ S4, __half* __restrict__ A)
{
    __shared__ float sred[8];
    __shared__ float sbc;

    const size_t base = (size_t)blockIdx.x * NYC;
    const int tid = threadIdx.x, lane = tid & 31, w = tid >> 5;

    float acc[4] = {0.f, 0.f, 0.f, 0.f};

#pragma unroll
    for (int l = 0; l < 4; l++) {
        const __half2* S2 = (const __half2*)(S4 + (size_t)l * BHNN + base) + tid * 2;
        float2 f01 = __half22float2(S2[0]);
        float2 f23 = __half22float2(S2[1]);
        float v[4] = {f01.x, f01.y, f23.x, f23.y};

        float m = fmaxf(fmaxf(v[0], v[1]), fmaxf(v[2], v[3]));
#pragma unroll
        for (int o = 16; o > 0; o >>= 1) m = fmaxf(m, __shfl_xor_sync(0xffffffffu, m, o));
        if (lane == 0) sred[w] = m;
        __syncthreads();
        if (tid == 0) {
            float t = sred[0];
#pragma unroll
            for (int i = 1; i < 8; i++) t = fmaxf(t, sred[i]);
            sbc = t;
        }
        __syncthreads();
        const float bm = sbc;

        float p[4], s = 0.f;
#pragma unroll
        for (int i = 0; i < 4; i++) { p[i] = __expf(v[i] - bm); s += p[i]; }
#pragma unroll
        for (int o = 16; o > 0; o >>= 1) s += __shfl_xor_sync(0xffffffffu, s, o);
        if (lane == 0) sred[w] = s;
        __syncthreads();
        if (tid == 0) {
            float t = 0.f;
#pragma unroll
            for (int i = 0; i < 8; i++) t += sred[i];
            sbc = t;
        }
        __syncthreads();
        const float inv = 1.0f / sbc;
#pragma unroll
        for (int i = 0; i < 4; i++) acc[i] += p[i] * inv;
        __syncthreads();
    }

    *(__half2*)&A[base + tid * 4]     = __floats2half2_rn(acc[0], acc[1]);
    *(__half2*)&A[base + tid * 4 + 2] = __floats2half2_rn(acc[2], acc[3]);
}

// ---------------------------------------------------------------------------
// O_partial = attn[:, z*512:(z+1)*512] @ V[z*512:(z+1)*512, :]
// FAITHFUL V head split. Block 64x64, 128 threads, BK=32, split-K=2.
// A fragments: ldmatrix.x4; V fragments: ldmatrix.x4.trans.
// Grid (NX/64, B*H, 2).
// ---------------------------------------------------------------------------
__global__ __launch_bounds__(128) void attnv_k(
    const __half* __restrict__ Aa, const __half* __restrict__ V,
    float* __restrict__ O0, float* __restrict__ O1)
{
    __shared__ uint32_t As2[2][64][20];   // [m][kpair 0..15]
    __shared__ __half   Vs [2][32][136];  // [k][n], stride 136 halves

    const int bh = blockIdx.y, b = bh >> 3, h = bh & 7;
    const int mblk = blockIdx.x * 64;
    const int zz = blockIdx.z;            // split-K index
    const int tid = threadIdx.x;
    const int warp = tid >> 5, lane = tid & 31;
    const int g = lane >> 2, tg = lane & 3;

    const uint32_t* Ab = (const uint32_t*)(Aa + (size_t)bh * NXC * NYC);
    const __half* Vb = V + (size_t)b * NYC * EC + (size_t)h * NYC * DHC
                         + (size_t)zz * 512 * DHC;

    const int arow = tid >> 1, aseg = (tid & 1) * 8;   // kpair offset 0/8
    const int vrow = tid >> 2, vcol = (tid & 3) * 16;  // k row 0..31

    const uint32_t* Ag = Ab + (size_t)(mblk + arow) * 512 + zz * 256 + aseg;

    const int la_r = LA_ROW(lane), la_c = LA_COL(lane);
    const int vl_k = (lane & 7) + ((lane >> 3) & 1) * 8;
    const int vl_n = (lane >> 4) * 8;

    float acc[8][4];
#pragma unroll
    for (int ni = 0; ni < 8; ni++)
#pragma unroll
        for (int q = 0; q < 4; q++) acc[ni][q] = 0.f;

    // stage 0
    {
        uint4 u0 = *(const uint4*)(Ag);
        uint4 u1 = *(const uint4*)(Ag + 4);
        As2[0][arow][aseg+0]=u0.x; As2[0][arow][aseg+1]=u0.y;
        As2[0][arow][aseg+2]=u0.z; As2[0][arow][aseg+3]=u0.w;
        As2[0][arow][aseg+4]=u1.x; As2[0][arow][aseg+5]=u1.y;
        As2[0][arow][aseg+6]=u1.z; As2[0][arow][aseg+7]=u1.w;
        const __half* Vg = Vb + (size_t)vrow * DHC + vcol;
        *(uint4*)&Vs[0][vrow][vcol]     = *(const uint4*)(Vg);
        *(uint4*)&Vs[0][vrow][vcol + 8] = *(const uint4*)(Vg + 8);
    }
    __syncthreads();

    for (int s = 0; s < 16; s++) {
        const int buf = s & 1;
        const bool more = (s + 1 < 16);
        uint4 pa0, pa1, pv0, pv1;
        if (more) {
            const uint32_t* Ap = Ag + (s + 1) * 16;
            pa0 = *(const uint4*)(Ap);
            pa1 = *(const uint4*)(Ap + 4);
            const __half* Vg = Vb + (size_t)((s + 1) * 32 + vrow) * DHC + vcol;
            pv0 = *(const uint4*)(Vg);
            pv1 = *(const uint4*)(Vg + 8);
        }

#pragma unroll
        for (int cc = 0; cc < 2; cc++) {
            uint32_t a0, a1, a2, a3;
            ldm4(sptr(&As2[buf][warp * 16 + la_r][8 * cc + la_c]), a0, a1, a2, a3);
#pragma unroll
            for (int pair = 0; pair < 4; pair++) {
                uint32_t b00, b10, b01, b11;
                ldm4t(sptr(&Vs[buf][16*cc + vl_k][pair * 16 + vl_n]), b00, b10, b01, b11);
                mma16(acc[2*pair    ], a0, a1, a2, a3, b00, b10);
                mma16(acc[2*pair + 1], a0, a1, a2, a3, b01, b11);
            }
        }

        if (more) {
            const int nb = buf ^ 1;
            As2[nb][arow][aseg+0]=pa0.x; As2[nb][arow][aseg+1]=pa0.y;
            As2[nb][arow][aseg+2]=pa0.z; As2[nb][arow][aseg+3]=pa0.w;
            As2[nb][arow][aseg+4]=pa1.x; As2[nb][arow][aseg+5]=pa1.y;
            As2[nb][arow][aseg+6]=pa1.z; As2[nb][arow][aseg+7]=pa1.w;
            *(uint4*)&Vs[nb][vrow][vcol]     = pv0;
            *(uint4*)&Vs[nb][vrow][vcol + 8] = pv1;
            __syncthreads();
        }
    }

    // Output partial: transposed layout O[b, n, h*DH + d] (standard rows)
    float* Op = (zz == 0 ? O0 : O1);
    const int r0 = mblk + warp * 16 + g;
    float* Ob = Op + (size_t)b * NXC * EC + (size_t)h * DHC;
#pragma unroll
    for (int ni = 0; ni < 8; ni++) {
        int c = ni * 8 + tg * 2;
        *(float2*)&Ob[(size_t)r0 * EC + c]       = make_float2(acc[ni][0], acc[ni][1]);
        *(float2*)&Ob[(size_t)(r0 + 8) * EC + c] = make_float2(acc[ni][2], acc[ni][3]);
    }
}

// ---------------------------------------------------------------------------
// Residual + LayerNorm: Out[row] = LN(X[row] + R[row]) * g + be
// ---------------------------------------------------------------------------
__global__ __launch_bounds__(128) void resln_k(
    const float* __restrict__ X, const float* __restrict__ R,
    const float* __restrict__ g, const float* __restrict__ be,
    float* __restrict__ Out)
{
    __shared__ float sred[4];
    __shared__ float sbc;

    const size_t base = (size_t)blockIdx.x * EC;
    const int tid = threadIdx.x, lane = tid & 31, w = tid >> 5;

    float r[4];
    int col[4];
#pragma unroll
    for (int i = 0; i < 4; i++) {
        col[i] = tid + i * 128;
        r[i] = X[base + col[i]] + R[base + col[i]];
    }

    float s = r[0] + r[1] + r[2] + r[3];
#pragma unroll
    for (int o = 16; o > 0; o >>= 1) s += __shfl_xor_sync(0xffffffffu, s, o);
    if (lane == 0) sred[w] = s;
    __syncthreads();
    if (tid == 0) sbc = sred[0] + sred[1] + sred[2] + sred[3];
    __syncthreads();
    const float mu = sbc * (1.0f / EC);

    float d[4], ss = 0.f;
#pragma unroll
    for (int i = 0; i < 4; i++) { d[i] = r[i] - mu; ss += d[i] * d[i]; }
#pragma unroll
    for (int o = 16; o > 0; o >>= 1) ss += __shfl_xor_sync(0xffffffffu, ss, o);
    if (lane == 0) sred[w] = ss;
    __syncthreads();
    if (tid == 0) sbc = sred[0] + sred[1] + sred[2] + sred[3];
    __syncthreads();
    const float rs = rsqrtf(sbc * (1.0f / EC) + 1e-5f);

#pragma unroll
    for (int i = 0; i < 4; i++)
        Out[base + col[i]] = d[i] * rs * g[col[i]] + be[col[i]];
}

// ---------------------------------------------------------------------------
// Host
// ---------------------------------------------------------------------------
extern "C" void kernel_launch(void* const* d_in, const int* in_sizes, int n_in,
                              void* d_out, int out_size)
{
    (void)in_sizes; (void)n_in; (void)out_size;

    const float* x   = (const float*)d_in[0];
    const float* y   = (const float*)d_in[1];
    const int*   xm  = (const int*)  d_in[2];
    const int*   ym  = (const int*)  d_in[3];
    const float* Wq  = (const float*)d_in[4];
    const float* bq  = (const float*)d_in[5];
    const float* Wk  = (const float*)d_in[6];
    const float* bk  = (const float*)d_in[7];
    const float* Wv  = (const float*)d_in[8];
    const float* bv  = (const float*)d_in[9];
    const float* Wo  = (const float*)d_in[10];
    const float* bo  = (const float*)d_in[11];
    const float* g1  = (const float*)d_in[12];
    const float* be1 = (const float*)d_in[13];
    const float* g2  = (const float*)d_in[14];
    const float* be2 = (const float*)d_in[15];
    const float* W1  = (const float*)d_in[16];
    const float* bf1 = (const float*)d_in[17];
    const float* W2  = (const float*)d_in[18];
    const float* bf2 = (const float*)d_in[19];
    float* out = (float*)d_out;

    float *O, *O2, *Hb, *F1, *F2;
    __half *QK, *V, *S4, *Aa;
    cudaGetSymbolAddress((void**)&QK, g_QK);
    cudaGetSymbolAddress((void**)&V,  g_V);
    cudaGetSymbolAddress((void**)&O,  g_O);
    cudaGetSymbolAddress((void**)&O2, g_O2);
    cudaGetSymbolAddress((void**)&Hb, g_Hb);
    cudaGetSymbolAddress((void**)&F1, g_F1);
    cudaGetSymbolAddress((void**)&F2, g_F2);
    cudaGetSymbolAddress((void**)&S4, g_S4);
    cudaGetSymbolAddress((void**)&Aa, g_A);

    // 1. All Q_l, K_l projections + V_3 in one launch (9 GEMM slices, fp16 out)
    proj_k<<<dim3(4, 32, 9), 256>>>(x, y, Wq, bq, Wk, bk, Wv, bv, QK, V);
    // 2. All layers' masked scores in one launch (fp16 in/out)
    scores_k<<<dim3(8, 8, 128), 256>>>(QK, xm, ym, S4);
    // 3. Single fused softmax-sum (a_3 = sum_l softmax(S_l)), fp16 out
    softmax4_k<<<BB * HC * NXC, 256>>>(S4, Aa);
    // 4. attn @ V with split-K=2 (partials in O, O2)
    attnv_k<<<dim3(16, 32, 2), 128>>>(Aa, V, O, O2);
    // 5. Wo GEMM sums the partials on the fly: F2 = (O + O2) @ Wo + bo
    gemm2_k<<<dim3(4, 32), 256>>>(O, O2, Wo + (size_t)3 * EC * EC, bo + 3 * EC, F2, EC, EC, 0);
    resln_k<<<MC, 128>>>(x, F2, g1 + 3 * EC, be1 + 3 * EC, Hb);
    gemm_k<<<dim3(16, 32), 256>>>(Hb, W1 + (size_t)3 * EC * FFC, bf1 + (size_t)3 * FFC, F1, EC, FFC, 1);
    gemm_k<<<dim3(4, 32), 256>>>(F1, W2 + (size_t)3 * FFC * EC, bf2 + 3 * EC, O, FFC, EC, 0);
    resln_k<<<MC, 128>>>(Hb, O, g2 + 3 * EC, be2 + 3 * EC, out);
}

// round 13
// speedup vs baseline: 4.2447x; 1.2962x over previous
#include <cuda_runtime.h>
#include <cuda_fp16.h>
#include <math.h>
#include <stdint.h>

// Problem constants
#define BB   4
#define NXC  1024
#define NYC  1024
#define EC   512
#define HC   8
#define DHC  64
#define LC   4
#define FFC  2048
#define MC   (BB * NXC)

#define BNE  (BB * NXC * EC)                  // 2,097,152
#define BHNN ((size_t)BB * HC * NXC * NYC)    // 33,554,432

// ---------------------------------------------------------------------------
// Scratch (device globals; allocation-free per harness rules)
// ---------------------------------------------------------------------------
__device__ __half g_QK[8 * (size_t)BNE];      // Q0,K0,..,Q3,K3 fp16 (32MB)
__device__ __half g_V [BNE];                  // V3 fp16
__device__ float  g_O [BNE];                  // attnv partial 0 / W2 out
__device__ float  g_O2[BNE];                  // attnv partial 1
__device__ float  g_Hb[BNE];
__device__ float  g_F1[(size_t)MC * FFC];
__device__ float  g_F2[BNE];                  // Wo out
__device__ __half g_S4[4 * BHNN];             // 4 layers' raw scores fp16 (256MB)
__device__ __half g_A [BHNN];                 // summed attention fp16 (64MB)

#define MASKED_H (-30000.0f)

// ---------------------------------------------------------------------------
// Helpers
// ---------------------------------------------------------------------------
__device__ __forceinline__ uint32_t pack2(float a, float b) {
    __half2 h = __floats2half2_rn(a, b);
    return *(uint32_t*)&h;
}

__device__ __forceinline__ uint32_t sptr(const void* p) {
    return (uint32_t)__cvta_generic_to_shared(p);
}

__device__ __forceinline__ void cpa16(uint32_t saddr, const void* gptr) {
    asm volatile("cp.async.ca.shared.global [%0], [%1], 16;"
                 :: "r"(saddr), "l"(gptr));
}
#define CP_COMMIT() asm volatile("cp.async.commit_group;" ::: "memory")
#define CP_WAIT0()  asm volatile("cp.async.wait_group 0;" ::: "memory")
#define CP_WAIT1()  asm volatile("cp.async.wait_group 1;" ::: "memory")

__device__ __forceinline__ void mma16(float* c,
    uint32_t a0, uint32_t a1, uint32_t a2, uint32_t a3,
    uint32_t b0, uint32_t b1)
{
    asm volatile(
        "mma.sync.aligned.m16n8k16.row.col.f32.f16.f16.f32 "
        "{%0,%1,%2,%3},{%4,%5,%6,%7},{%8,%9},{%0,%1,%2,%3};"
        : "+f"(c[0]), "+f"(c[1]), "+f"(c[2]), "+f"(c[3])
        : "r"(a0), "r"(a1), "r"(a2), "r"(a3), "r"(b0), "r"(b1));
}

__device__ __forceinline__ void ldm4t(uint32_t addr,
    uint32_t& r0, uint32_t& r1, uint32_t& r2, uint32_t& r3)
{
    asm volatile(
        "ldmatrix.sync.aligned.m8n8.x4.trans.shared.b16 {%0,%1,%2,%3}, [%4];"
        : "=r"(r0), "=r"(r1), "=r"(r2), "=r"(r3) : "r"(addr));
}

__device__ __forceinline__ void ldm4(uint32_t addr,
    uint32_t& r0, uint32_t& r1, uint32_t& r2, uint32_t& r3)
{
    asm volatile(
        "ldmatrix.sync.aligned.m8n8.x4.shared.b16 {%0,%1,%2,%3}, [%4];"
        : "=r"(r0), "=r"(r1), "=r"(r2), "=r"(r3) : "r"(addr));
}

// A-type ldmatrix.x4 lane mapping ([m][kpair] tile)
#define LA_ROW(lane) (((lane) & 7) + (((lane) >> 3) & 1) * 8)
#define LA_COL(lane) ((((lane) >> 4) & 1) * 4)
// scores K-side ldmatrix.x4 lane mapping ([n][kpair] tile, two n-groups)
#define LB_ROW(lane) (((lane) & 7) + (((lane) >> 4) & 1) * 8)
#define LB_COL(lane) ((((lane) >> 3) & 1) * 4)

// ---------------------------------------------------------------------------
// FP16 GEMM body: C[M,N] = (A (+A2?)) @ W[K,N] + bias (opt exact GELU)
// block 128x128, BK=16, 256 threads (8 warps 4x2), warp tile 32x64.
// ---------------------------------------------------------------------------
__device__ __forceinline__ void gemm16_body(
    const float* __restrict__ A, const float* __restrict__ A2,
    const float* __restrict__ W,
    const float* __restrict__ bias, float* __restrict__ Cf,
    __half* __restrict__ Ch, int K, int N, int dogelu)
{
    __shared__ uint32_t As2[2][128][12];   // [m][kpair 0..7], stride 12 words
    __shared__ __half   Bs [2][16][136];   // [k][n], stride 136 halves

    const int tid  = threadIdx.x;
    const int warp = tid >> 5, lane = tid & 31;
    const int wm = warp >> 1, wn = warp & 1;
    const int g  = lane >> 2, tg = lane & 3;
    const int mblk = blockIdx.y * 128, nblk = blockIdx.x * 128;

    const int arow = tid >> 1, aseg = (tid & 1) * 4;    // kpair offset 0/4
    const int wrow = tid >> 4, wcol = (tid & 15) * 8;   // k row 0..15

    const float* Ag  = A  + (size_t)(mblk + arow) * K + aseg * 2;
    const float* Ag2 = A2 ? A2 + (size_t)(mblk + arow) * K + aseg * 2 : (const float*)0;
    const float* Wg  = W + (size_t)wrow * N + nblk + wcol;

    const int la_r = LA_ROW(lane), la_c = LA_COL(lane);
    const int bl_k = (lane & 7) + ((lane >> 3) & 1) * 8;
    const int bl_n = wn * 64 + (lane >> 4) * 8;

    float acc[2][8][4];
#pragma unroll
    for (int mi = 0; mi < 2; mi++)
#pragma unroll
        for (int ni = 0; ni < 8; ni++)
#pragma unroll
            for (int q = 0; q < 4; q++) acc[mi][ni][q] = 0.f;

    // stage 0
    {
        float4 a0 = *(const float4*)(Ag);
        float4 a1 = *(const float4*)(Ag + 4);
        if (Ag2) {
            float4 c0 = *(const float4*)(Ag2);
            float4 c1 = *(const float4*)(Ag2 + 4);
            a0.x += c0.x; a0.y += c0.y; a0.z += c0.z; a0.w += c0.w;
            a1.x += c1.x; a1.y += c1.y; a1.z += c1.z; a1.w += c1.w;
        }
        As2[0][arow][aseg+0] = pack2(a0.x, a0.y);
        As2[0][arow][aseg+1] = pack2(a0.z, a0.w);
        As2[0][arow][aseg+2] = pack2(a1.x, a1.y);
        As2[0][arow][aseg+3] = pack2(a1.z, a1.w);
        float4 w0 = *(const float4*)(Wg);
        float4 w1 = *(const float4*)(Wg + 4);
        __half2* bp = (__half2*)&Bs[0][wrow][wcol];
        bp[0] = __floats2half2_rn(w0.x, w0.y);
        bp[1] = __floats2half2_rn(w0.z, w0.w);
        bp[2] = __floats2half2_rn(w1.x, w1.y);
        bp[3] = __floats2half2_rn(w1.z, w1.w);
    }
    __syncthreads();

    const int nst = K >> 4;
    for (int s = 0; s < nst; s++) {
        const int buf = s & 1;
        const bool more = (s + 1 < nst);
        float4 pa0, pa1, pw0, pw1;
        if (more) {
            const float* Ap = Ag + (s + 1) * 16;
            const float* Wp = Wg + (size_t)(s + 1) * 16 * N;
            pa0 = *(const float4*)Ap; pa1 = *(const float4*)(Ap + 4);
            if (Ag2) {
                const float* Ap2 = Ag2 + (s + 1) * 16;
                float4 c0 = *(const float4*)Ap2;
                float4 c1 = *(const float4*)(Ap2 + 4);
                pa0.x += c0.x; pa0.y += c0.y; pa0.z += c0.z; pa0.w += c0.w;
                pa1.x += c1.x; pa1.y += c1.y; pa1.z += c1.z; pa1.w += c1.w;
            }
            pw0 = *(const float4*)Wp; pw1 = *(const float4*)(Wp + 4);
        }

        uint32_t af[2][4];
#pragma unroll
        for (int mi = 0; mi < 2; mi++)
            ldm4(sptr(&As2[buf][wm * 32 + mi * 16 + la_r][la_c]),
                 af[mi][0], af[mi][1], af[mi][2], af[mi][3]);
#pragma unroll
        for (int pair = 0; pair < 4; pair++) {
            uint32_t b00, b10, b01, b11;
            ldm4t(sptr(&Bs[buf][bl_k][bl_n + pair * 16]), b00, b10, b01, b11);
#pragma unroll
            for (int mi = 0; mi < 2; mi++) {
                mma16(acc[mi][2*pair    ], af[mi][0], af[mi][1], af[mi][2], af[mi][3], b00, b10);
                mma16(acc[mi][2*pair + 1], af[mi][0], af[mi][1], af[mi][2], af[mi][3], b01, b11);
            }
        }

        if (more) {
            const int nb = buf ^ 1;
            As2[nb][arow][aseg+0] = pack2(pa0.x, pa0.y);
            As2[nb][arow][aseg+1] = pack2(pa0.z, pa0.w);
            As2[nb][arow][aseg+2] = pack2(pa1.x, pa1.y);
            As2[nb][arow][aseg+3] = pack2(pa1.z, pa1.w);
            __half2* bp = (__half2*)&Bs[nb][wrow][wcol];
            bp[0] = __floats2half2_rn(pw0.x, pw0.y);
            bp[1] = __floats2half2_rn(pw0.z, pw0.w);
            bp[2] = __floats2half2_rn(pw1.x, pw1.y);
            bp[3] = __floats2half2_rn(pw1.z, pw1.w);
            __syncthreads();
        }
    }

#pragma unroll
    for (int mi = 0; mi < 2; mi++) {
        int r0 = mblk + wm * 32 + mi * 16 + g;
#pragma unroll
        for (int ni = 0; ni < 8; ni++) {
            int c = nblk + wn * 64 + ni * 8 + tg * 2;
            float b0 = bias[c], b1 = bias[c + 1];
            float v0 = acc[mi][ni][0] + b0, v1 = acc[mi][ni][1] + b1;
            float v2 = acc[mi][ni][2] + b0, v3 = acc[mi][ni][3] + b1;
            if (dogelu) {
                v0 = 0.5f * v0 * (1.0f + erff(v0 * 0.70710678118654752f));
                v1 = 0.5f * v1 * (1.0f + erff(v1 * 0.70710678118654752f));
                v2 = 0.5f * v2 * (1.0f + erff(v2 * 0.70710678118654752f));
                v3 = 0.5f * v3 * (1.0f + erff(v3 * 0.70710678118654752f));
            }
            if (Ch) {
                *(__half2*)&Ch[(size_t)r0 * N + c]       = __floats2half2_rn(v0, v1);
                *(__half2*)&Ch[(size_t)(r0 + 8) * N + c] = __floats2half2_rn(v2, v3);
            } else {
                *(float2*)&Cf[(size_t)r0 * N + c]       = make_float2(v0, v1);
                *(float2*)&Cf[(size_t)(r0 + 8) * N + c] = make_float2(v2, v3);
            }
        }
    }
}

__global__ __launch_bounds__(256) void gemm_k(
    const float* __restrict__ A, const float* __restrict__ W,
    const float* __restrict__ bias, float* __restrict__ C,
    int K, int N, int dogelu)
{
    gemm16_body(A, (const float*)0, W, bias, C, (__half*)0, K, N, dogelu);
}

__global__ __launch_bounds__(256) void gemm2_k(
    const float* __restrict__ A, const float* __restrict__ A2,
    const float* __restrict__ W,
    const float* __restrict__ bias, float* __restrict__ C,
    int K, int N, int dogelu)
{
    gemm16_body(A, A2, W, bias, C, (__half*)0, K, N, dogelu);
}

// Batched projections (fp16 out): z=0..7 -> (layer z/2, Q/K), z=8 -> V3.
__global__ __launch_bounds__(256) void proj_k(
    const float* __restrict__ x, const float* __restrict__ y,
    const float* __restrict__ Wq, const float* __restrict__ bq,
    const float* __restrict__ Wk, const float* __restrict__ bk,
    const float* __restrict__ Wv, const float* __restrict__ bv,
    __half* __restrict__ QK, __half* __restrict__ V)
{
    const int z = blockIdx.z;
    const float *A, *W, *Bi;
    __half* C;
    if (z < 8) {
        int l = z >> 1, isK = z & 1;
        A  = isK ? y : x;
        W  = (isK ? Wk : Wq) + (size_t)l * EC * EC;
        Bi = (isK ? bk : bq) + (size_t)l * EC;
        C  = QK + (size_t)z * BNE;
    } else {
        A = y; W = Wv + (size_t)3 * EC * EC; Bi = bv + (size_t)3 * EC; C = V;
    }
    gemm16_body(A, (const float*)0, W, Bi, (float*)0, C, EC, EC, 0);
}

// ---------------------------------------------------------------------------
// Scores: S = (Q @ K^T)*0.125, masked, fp16 in/out, cp.async tile loads.
// FAITHFUL head split: contiguous [1024 x 64] chunk at b*NX*E + h*NX*DH.
// Grid (NY/128, NX/128, 4*32), 256 threads.
// ---------------------------------------------------------------------------
__global__ __launch_bounds__(256) void scores_k(
    const __half* __restrict__ QK, const int* __restrict__ xm,
    const int* __restrict__ ym, __half* __restrict__ S4)
{
    __shared__ uint32_t Qs2[128][36];   // [m][kpair 0..31]
    __shared__ uint32_t Ks2[128][36];   // [n][kpair 0..31]

    const int z = blockIdx.z;
    const int l = z >> 5, bh = z & 31, b = bh >> 3, h = bh & 7;
    const uint32_t* Qb = (const uint32_t*)(QK + (size_t)(2 * l) * BNE)
                         + (size_t)b * NXC * 256 + (size_t)h * NXC * 32;
    const uint32_t* Kb = (const uint32_t*)(QK + (size_t)(2 * l + 1) * BNE)
                         + (size_t)b * NYC * 256 + (size_t)h * NYC * 32;

    const int mblk = blockIdx.y * 128;
    const int nblk = blockIdx.x * 128;
    const int tid  = threadIdx.x;
    const int warp = tid >> 5, lane = tid & 31;
    const int wm = warp >> 1, wn = warp & 1;
    const int g = lane >> 2, tg = lane & 3;

    const int la_r = LA_ROW(lane), la_c = LA_COL(lane);
    const int lb_r = LB_ROW(lane), lb_c = LB_COL(lane);

    // cp.async tile loads: thread covers one half-row (16 words) of Q and K
    {
        int r = tid >> 1;
        int wseg = (tid & 1) * 16;
        const uint32_t* qsrc = Qb + (size_t)(mblk + r) * 32 + wseg;
        const uint32_t* ksrc = Kb + (size_t)(nblk + r) * 32 + wseg;
#pragma unroll
        for (int i = 0; i < 4; i++) {
            cpa16(sptr(&Qs2[r][wseg + i * 4]), qsrc + i * 4);
            cpa16(sptr(&Ks2[r][wseg + i * 4]), ksrc + i * 4);
        }
    }
    CP_COMMIT();
    CP_WAIT0();
    __syncthreads();

    float acc[2][8][4];
#pragma unroll
    for (int mi = 0; mi < 2; mi++)
#pragma unroll
        for (int ni = 0; ni < 8; ni++)
#pragma unroll
            for (int q = 0; q < 4; q++) acc[mi][ni][q] = 0.f;

#pragma unroll
    for (int c = 0; c < 4; c++) {          // 4 chunks of k16
        uint32_t af[2][4];
#pragma unroll
        for (int mi = 0; mi < 2; mi++)
            ldm4(sptr(&Qs2[wm * 32 + mi * 16 + la_r][8 * c + la_c]),
                 af[mi][0], af[mi][1], af[mi][2], af[mi][3]);
#pragma unroll
        for (int nq = 0; nq < 4; nq++) {
            uint32_t b00, b01, b10, b11;
            ldm4(sptr(&Ks2[wn * 64 + nq * 16 + lb_r][8 * c + lb_c]),
                 b00, b01, b10, b11);
#pragma unroll
            for (int mi = 0; mi < 2; mi++) {
                mma16(acc[mi][2*nq    ], af[mi][0], af[mi][1], af[mi][2], af[mi][3], b00, b01);
                mma16(acc[mi][2*nq + 1], af[mi][0], af[mi][1], af[mi][2], af[mi][3], b10, b11);
            }
        }
    }

    __half* Sl = S4 + (size_t)l * BHNN + (size_t)bh * NXC * NYC;
#pragma unroll
    for (int mi = 0; mi < 2; mi++) {
        int r0 = mblk + wm * 32 + mi * 16 + g;
        int xr0 = xm[b * NXC + r0], xr1 = xm[b * NXC + r0 + 8];
#pragma unroll
        for (int ni = 0; ni < 8; ni++) {
            int c = nblk + wn * 64 + ni * 8 + tg * 2;
            int yc0 = ym[b * NYC + c], yc1 = ym[b * NYC + c + 1];
            float v0 = (xr0 && yc0) ? acc[mi][ni][0] * 0.125f : MASKED_H;
            float v1 = (xr0 && yc1) ? acc[mi][ni][1] * 0.125f : MASKED_H;
            float v2 = (xr1 && yc0) ? acc[mi][ni][2] * 0.125f : MASKED_H;
            float v3 = (xr1 && yc1) ? acc[mi][ni][3] * 0.125f : MASKED_H;
            *(__half2*)&Sl[(size_t)r0 * NYC + c]       = __floats2half2_rn(v0, v1);
            *(__half2*)&Sl[(size_t)(r0 + 8) * NYC + c] = __floats2half2_rn(v2, v3);
        }
    }
}

// ---------------------------------------------------------------------------
// Fused softmax-sum, warp-per-row: A[row] = sum_l softmax(S_l[row]).
// 8 rows per 256-thread block; no block barriers. fp16 in/out.
// Lane l covers halves [i*256 + l*8, +8) for i=0..3 (16B coalesced).
// ---------------------------------------------------------------------------
__global__ __launch_bounds__(256) void softmax4_k(
    const __half* __restrict__ S4, __half* __restrict__ A)
{
    const int warp = threadIdx.x >> 5, lane = threadIdx.x & 31;
    const size_t base = ((size_t)blockIdx.x * 8 + warp) * NYC;

    float acc[32];
#pragma unroll
    for (int i = 0; i < 32; i++) acc[i] = 0.f;

#pragma unroll
    for (int l = 0; l < 4; l++) {
        const __half* Sr = S4 + (size_t)l * BHNN + base;
        float v[32];
#pragma unroll
        for (int i = 0; i < 4; i++) {
            uint4 u = *(const uint4*)(Sr + i * 256 + lane * 8);
            float2 f;
            f = __half22float2(*(__half2*)&u.x); v[i*8+0]=f.x; v[i*8+1]=f.y;
            f = __half22float2(*(__half2*)&u.y); v[i*8+2]=f.x; v[i*8+3]=f.y;
            f = __half22float2(*(__half2*)&u.z); v[i*8+4]=f.x; v[i*8+5]=f.y;
            f = __half22float2(*(__half2*)&u.w); v[i*8+6]=f.x; v[i*8+7]=f.y;
        }
        float m = v[0];
#pragma unroll
        for (int i = 1; i < 32; i++) m = fmaxf(m, v[i]);
#pragma unroll
        for (int o = 16; o > 0; o >>= 1) m = fmaxf(m, __shfl_xor_sync(0xffffffffu, m, o));
        float s = 0.f;
#pragma unroll
        for (int i = 0; i < 32; i++) { v[i] = __expf(v[i] - m); s += v[i]; }
#pragma unroll
        for (int o = 16; o > 0; o >>= 1) s += __shfl_xor_sync(0xffffffffu, s, o);
        float inv = 1.0f / s;
#pragma unroll
        for (int i = 0; i < 32; i++) acc[i] += v[i] * inv;
    }

#pragma unroll
    for (int i = 0; i < 4; i++) {
        uint4 u;
        __half2* p = (__half2*)&u;
        p[0] = __floats2half2_rn(acc[i*8+0], acc[i*8+1]);
        p[1] = __floats2half2_rn(acc[i*8+2], acc[i*8+3]);
        p[2] = __floats2half2_rn(acc[i*8+4], acc[i*8+5]);
        p[3] = __floats2half2_rn(acc[i*8+6], acc[i*8+7]);
        *(uint4*)(A + base + i * 256 + lane * 8) = u;
    }
}

// ---------------------------------------------------------------------------
// O_partial = attn[:, z*512:(z+1)*512] @ V[z*512:(z+1)*512, :]
// 3-stage cp.async pipeline. Block 64x64, 128 threads, BK=32, split-K=2.
// Grid (NX/64, B*H, 2).
// ---------------------------------------------------------------------------
__global__ __launch_bounds__(128) void attnv_k(
    const __half* __restrict__ Aa, const __half* __restrict__ V,
    float* __restrict__ O0, float* __restrict__ O1)
{
    __shared__ uint32_t As2[3][64][20];   // [m][kpair 0..15]
    __shared__ __half   Vs [3][32][136];  // [k][n], stride 136 halves

    const int bh = blockIdx.y, b = bh >> 3, h = bh & 7;
    const int mblk = blockIdx.x * 64;
    const int zz = blockIdx.z;
    const int tid = threadIdx.x;
    const int warp = tid >> 5, lane = tid & 31;
    const int g = lane >> 2, tg = lane & 3;

    const uint32_t* Ab = (const uint32_t*)(Aa + (size_t)bh * NXC * NYC);
    const __half* Vb = V + (size_t)b * NYC * EC + (size_t)h * NYC * DHC
                         + (size_t)zz * 512 * DHC;

    const int arow = tid >> 1, aseg = (tid & 1) * 8;   // kpair offset 0/8
    const int vrow = tid >> 2, vcol = (tid & 3) * 16;  // k row 0..31

    const uint32_t* Ag = Ab + (size_t)(mblk + arow) * 512 + zz * 256 + aseg;

    const int la_r = LA_ROW(lane), la_c = LA_COL(lane);
    const int vl_k = (lane & 7) + ((lane >> 3) & 1) * 8;
    const int vl_n = (lane >> 4) * 8;

    float acc[8][4];
#pragma unroll
    for (int ni = 0; ni < 8; ni++)
#pragma unroll
        for (int q = 0; q < 4; q++) acc[ni][q] = 0.f;

#define AV_ISSUE(st, bf) do { \
        cpa16(sptr(&As2[bf][arow][aseg]),     Ag + (st) * 16); \
        cpa16(sptr(&As2[bf][arow][aseg + 4]), Ag + (st) * 16 + 4); \
        const __half* Vg_ = Vb + (size_t)((st) * 32 + vrow) * DHC + vcol; \
        cpa16(sptr(&Vs[bf][vrow][vcol]),     Vg_); \
        cpa16(sptr(&Vs[bf][vrow][vcol + 8]), Vg_ + 8); \
    } while (0)

    AV_ISSUE(0, 0); CP_COMMIT();
    AV_ISSUE(1, 1); CP_COMMIT();

    for (int s = 0; s < 16; s++) {
        CP_WAIT1();
        __syncthreads();
        const int buf = s % 3;

#pragma unroll
        for (int cc = 0; cc < 2; cc++) {
            uint32_t a0, a1, a2, a3;
            ldm4(sptr(&As2[buf][warp * 16 + la_r][8 * cc + la_c]), a0, a1, a2, a3);
#pragma unroll
            for (int pair = 0; pair < 4; pair++) {
                uint32_t b00, b10, b01, b11;
                ldm4t(sptr(&Vs[buf][16*cc + vl_k][pair * 16 + vl_n]), b00, b10, b01, b11);
                mma16(acc[2*pair    ], a0, a1, a2, a3, b00, b10);
                mma16(acc[2*pair + 1], a0, a1, a2, a3, b01, b11);
            }
        }

        if (s + 2 < 16) AV_ISSUE(s + 2, (s + 2) % 3);
        CP_COMMIT();
    }
#undef AV_ISSUE

    float* Op = (zz == 0 ? O0 : O1);
    const int r0 = mblk + warp * 16 + g;
    float* Ob = Op + (size_t)b * NXC * EC + (size_t)h * DHC;
#pragma unroll
    for (int ni = 0; ni < 8; ni++) {
        int c = ni * 8 + tg * 2;
        *(float2*)&Ob[(size_t)r0 * EC + c]       = make_float2(acc[ni][0], acc[ni][1]);
        *(float2*)&Ob[(size_t)(r0 + 8) * EC + c] = make_float2(acc[ni][2], acc[ni][3]);
    }
}

// ---------------------------------------------------------------------------
// Residual + LayerNorm: Out[row] = LN(X[row] + R[row]) * g + be
// ---------------------------------------------------------------------------
__global__ __launch_bounds__(128) void resln_k(
    const float* __restrict__ X, const float* __restrict__ R,
    const float* __restrict__ g, const float* __restrict__ be,
    float* __restrict__ Out)
{
    __shared__ float sred[4];
    __shared__ float sbc;

    const size_t base = (size_t)blockIdx.x * EC;
    const int tid = threadIdx.x, lane = tid & 31, w = tid >> 5;

    float r[4];
    int col[4];
#pragma unroll
    for (int i = 0; i < 4; i++) {
        col[i] = tid + i * 128;
        r[i] = X[base + col[i]] + R[base + col[i]];
    }

    float s = r[0] + r[1] + r[2] + r[3];
#pragma unroll
    for (int o = 16; o > 0; o >>= 1) s += __shfl_xor_sync(0xffffffffu, s, o);
    if (lane == 0) sred[w] = s;
    __syncthreads();
    if (tid == 0) sbc = sred[0] + sred[1] + sred[2] + sred[3];
    __syncthreads();
    const float mu = sbc * (1.0f / EC);

    float d[4], ss = 0.f;
#pragma unroll
    for (int i = 0; i < 4; i++) { d[i] = r[i] - mu; ss += d[i] * d[i]; }
#pragma unroll
    for (int o = 16; o > 0; o >>= 1) ss += __shfl_xor_sync(0xffffffffu, ss, o);
    if (lane == 0) sred[w] = ss;
    __syncthreads();
    if (tid == 0) sbc = sred[0] + sred[1] + sred[2] + sred[3];
    __syncthreads();
    const float rs = rsqrtf(sbc * (1.0f / EC) + 1e-5f);

#pragma unroll
    for (int i = 0; i < 4; i++)
        Out[base + col[i]] = d[i] * rs * g[col[i]] + be[col[i]];
}

// ---------------------------------------------------------------------------
// Host
// ---------------------------------------------------------------------------
extern "C" void kernel_launch(void* const* d_in, const int* in_sizes, int n_in,
                              void* d_out, int out_size)
{
    (void)in_sizes; (void)n_in; (void)out_size;

    const float* x   = (const float*)d_in[0];
    const float* y   = (const float*)d_in[1];
    const int*   xm  = (const int*)  d_in[2];
    const int*   ym  = (const int*)  d_in[3];
    const float* Wq  = (const float*)d_in[4];
    const float* bq  = (const float*)d_in[5];
    const float* Wk  = (const float*)d_in[6];
    const float* bk  = (const float*)d_in[7];
    const float* Wv  = (const float*)d_in[8];
    const float* bv  = (const float*)d_in[9];
    const float* Wo  = (const float*)d_in[10];
    const float* bo  = (const float*)d_in[11];
    const float* g1  = (const float*)d_in[12];
    const float* be1 = (const float*)d_in[13];
    const float* g2  = (const float*)d_in[14];
    const float* be2 = (const float*)d_in[15];
    const float* W1  = (const float*)d_in[16];
    const float* bf1 = (const float*)d_in[17];
    const float* W2  = (const float*)d_in[18];
    const float* bf2 = (const float*)d_in[19];
    float* out = (float*)d_out;

    float *O, *O2, *Hb, *F1, *F2;
    __half *QK, *V, *S4, *Aa;
    cudaGetSymbolAddress((void**)&QK, g_QK);
    cudaGetSymbolAddress((void**)&V,  g_V);
    cudaGetSymbolAddress((void**)&O,  g_O);
    cudaGetSymbolAddress((void**)&O2, g_O2);
    cudaGetSymbolAddress((void**)&Hb, g_Hb);
    cudaGetSymbolAddress((void**)&F1, g_F1);
    cudaGetSymbolAddress((void**)&F2, g_F2);
    cudaGetSymbolAddress((void**)&S4, g_S4);
    cudaGetSymbolAddress((void**)&Aa, g_A);

    // 1. All Q_l, K_l projections + V_3 in one launch (9 GEMM slices, fp16 out)
    proj_k<<<dim3(4, 32, 9), 256>>>(x, y, Wq, bq, Wk, bk, Wv, bv, QK, V);
    // 2. All layers' masked scores in one launch (fp16 in/out, cp.async)
    scores_k<<<dim3(8, 8, 128), 256>>>(QK, xm, ym, S4);
    // 3. Fused softmax-sum, warp-per-row (a_3 = sum_l softmax(S_l))
    softmax4_k<<<BB * HC * NXC / 8, 256>>>(S4, Aa);
    // 4. attn @ V with split-K=2 (partials in O, O2), cp.async pipeline
    attnv_k<<<dim3(16, 32, 2), 128>>>(Aa, V, O, O2);
    // 5. Wo GEMM sums the partials on the fly: F2 = (O + O2) @ Wo + bo
    gemm2_k<<<dim3(4, 32), 256>>>(O, O2, Wo + (size_t)3 * EC * EC, bo + 3 * EC, F2, EC, EC, 0);
    resln_k<<<MC, 128>>>(x, F2, g1 + 3 * EC, be1 + 3 * EC, Hb);
    gemm_k<<<dim3(16, 32), 256>>>(Hb, W1 + (size_t)3 * EC * FFC, bf1 + (size_t)3 * FFC, F1, EC, FFC, 1);
    gemm_k<<<dim3(4, 32), 256>>>(F1, W2 + (size_t)3 * FFC * EC, bf2 + 3 * EC, O, FFC, EC, 0);
    resln_k<<<MC, 128>>>(Hb, O, g2 + 3 * EC, be2 + 3 * EC, out);
}

// round 14
// speedup vs baseline: 4.7280x; 1.1138x over previous
#include <cuda_runtime.h>
#include <cuda_fp16.h>
#include <math.h>
#include <stdint.h>

// Problem constants
#define BB   4
#define NXC  1024
#define NYC  1024
#define EC   512
#define HC   8
#define DHC  64
#define LC   4
#define FFC  2048
#define MC   (BB * NXC)

#define BNE  (BB * NXC * EC)                  // 2,097,152
#define BHNN ((size_t)BB * HC * NXC * NYC)    // 33,554,432
#define EE   (EC * EC)                        // 262,144

// ---------------------------------------------------------------------------
// Scratch (device globals; allocation-free per harness rules)
// ---------------------------------------------------------------------------
__device__ __half g_QK[8 * (size_t)BNE];      // Q0,K0,..,Q3,K3 fp16
__device__ __half g_V [BNE];                  // V3 fp16
__device__ float  g_O [BNE];                  // attnv partial 0 / W2 out
__device__ float  g_O2[BNE];                  // attnv partial 1
__device__ float  g_Hb[BNE];
__device__ float  g_F2[BNE];                  // Wo out
__device__ __half g_S4[4 * BHNN];             // 4 layers' raw scores fp16 (256MB)
__device__ __half g_A [BHNN];                 // summed attention fp16 (64MB)
// fp16 conversions
__device__ __half g_Xh [BNE];
__device__ __half g_Yh [BNE];
__device__ __half g_Wqh[4 * EE];
__device__ __half g_Wkh[4 * EE];
__device__ __half g_Wvh[EE];
__device__ __half g_W1h[(size_t)EC * FFC];
__device__ __half g_W2h[(size_t)FFC * EC];
__device__ __half g_Hbh[BNE];
__device__ __half g_F1h[(size_t)MC * FFC];

#define MASKED_H (-30000.0f)

// ---------------------------------------------------------------------------
// Helpers
// ---------------------------------------------------------------------------
__device__ __forceinline__ uint32_t pack2(float a, float b) {
    __half2 h = __floats2half2_rn(a, b);
    return *(uint32_t*)&h;
}

__device__ __forceinline__ uint32_t sptr(const void* p) {
    return (uint32_t)__cvta_generic_to_shared(p);
}

__device__ __forceinline__ void cpa16(uint32_t saddr, const void* gptr) {
    asm volatile("cp.async.ca.shared.global [%0], [%1], 16;"
                 :: "r"(saddr), "l"(gptr));
}
#define CP_COMMIT() asm volatile("cp.async.commit_group;" ::: "memory")
#define CP_WAIT0()  asm volatile("cp.async.wait_group 0;" ::: "memory")
#define CP_WAIT1()  asm volatile("cp.async.wait_group 1;" ::: "memory")

__device__ __forceinline__ void mma16(float* c,
    uint32_t a0, uint32_t a1, uint32_t a2, uint32_t a3,
    uint32_t b0, uint32_t b1)
{
    asm volatile(
        "mma.sync.aligned.m16n8k16.row.col.f32.f16.f16.f32 "
        "{%0,%1,%2,%3},{%4,%5,%6,%7},{%8,%9},{%0,%1,%2,%3};"
        : "+f"(c[0]), "+f"(c[1]), "+f"(c[2]), "+f"(c[3])
        : "r"(a0), "r"(a1), "r"(a2), "r"(a3), "r"(b0), "r"(b1));
}

__device__ __forceinline__ void ldm4t(uint32_t addr,
    uint32_t& r0, uint32_t& r1, uint32_t& r2, uint32_t& r3)
{
    asm volatile(
        "ldmatrix.sync.aligned.m8n8.x4.trans.shared.b16 {%0,%1,%2,%3}, [%4];"
        : "=r"(r0), "=r"(r1), "=r"(r2), "=r"(r3) : "r"(addr));
}

__device__ __forceinline__ void ldm4(uint32_t addr,
    uint32_t& r0, uint32_t& r1, uint32_t& r2, uint32_t& r3)
{
    asm volatile(
        "ldmatrix.sync.aligned.m8n8.x4.shared.b16 {%0,%1,%2,%3}, [%4];"
        : "=r"(r0), "=r"(r1), "=r"(r2), "=r"(r3) : "r"(addr));
}

#define LA_ROW(lane) (((lane) & 7) + (((lane) >> 3) & 1) * 8)
#define LA_COL(lane) ((((lane) >> 4) & 1) * 4)
#define LB_ROW(lane) (((lane) & 7) + (((lane) >> 4) & 1) * 8)
#define LB_COL(lane) ((((lane) >> 3) & 1) * 4)

// ---------------------------------------------------------------------------
// fp32 -> fp16 conversion (grid-stride, vectorized)
// ---------------------------------------------------------------------------
__global__ __launch_bounds__(256) void cvt_k(
    const float* __restrict__ src, __half* __restrict__ dst, int n)
{
    for (int i = (blockIdx.x * 256 + threadIdx.x) * 4; i < n;
         i += gridDim.x * 256 * 4) {
        float4 v = *(const float4*)(src + i);
        *(uint32_t*)(dst + i)     = pack2(v.x, v.y);
        *(uint32_t*)(dst + i + 2) = pack2(v.z, v.w);
    }
}

// ---------------------------------------------------------------------------
// Pure-fp16 GEMM: C = A[M,K]h @ W[K,N]h + bias (opt GELU); out fp32 or fp16.
// block 128x128, BK=16, 256 threads (8 warps 4x2), 3-stage cp.async.
// ---------------------------------------------------------------------------
__device__ __forceinline__ void hgemm_body(
    const __half* __restrict__ A, const __half* __restrict__ W,
    const float* __restrict__ bias, float* __restrict__ Cf,
    __half* __restrict__ Ch, int K, int N, int dogelu)
{
    __shared__ uint32_t Ah[3][128][12];    // [m][kpair 0..7]
    __shared__ __half   Bs[3][16][136];    // [k][n]

    const int tid  = threadIdx.x;
    const int warp = tid >> 5, lane = tid & 31;
    const int wm = warp >> 1, wn = warp & 1;
    const int g  = lane >> 2, tg = lane & 3;
    const int mblk = blockIdx.y * 128, nblk = blockIdx.x * 128;

    const int arow = tid >> 1, aseg = (tid & 1) * 4;    // kpair word offset 0/4
    const int wrow = tid >> 4, wcol = (tid & 15) * 8;   // k row 0..15

    const __half* Ag = A + (size_t)(mblk + arow) * K + aseg * 2;
    const __half* Wg = W + (size_t)wrow * N + nblk + wcol;

    const int la_r = LA_ROW(lane), la_c = LA_COL(lane);
    const int bl_k = (lane & 7) + ((lane >> 3) & 1) * 8;
    const int bl_n = wn * 64 + (lane >> 4) * 8;

    float acc[2][8][4];
#pragma unroll
    for (int mi = 0; mi < 2; mi++)
#pragma unroll
        for (int ni = 0; ni < 8; ni++)
#pragma unroll
            for (int q = 0; q < 4; q++) acc[mi][ni][q] = 0.f;

    const int nst = K >> 4;

#define HG_ISSUE(st, bf) do { \
        cpa16(sptr(&Ah[bf][arow][aseg]), Ag + (st) * 16); \
        cpa16(sptr(&Bs[bf][wrow][wcol]), Wg + (size_t)(st) * 16 * N); \
    } while (0)

    HG_ISSUE(0, 0); CP_COMMIT();
    HG_ISSUE(1, 1); CP_COMMIT();

    for (int s = 0; s < nst; s++) {
        CP_WAIT1();
        __syncthreads();
        const int buf = s % 3;

        uint32_t af[2][4];
#pragma unroll
        for (int mi = 0; mi < 2; mi++)
            ldm4(sptr(&Ah[buf][wm * 32 + mi * 16 + la_r][la_c]),
                 af[mi][0], af[mi][1], af[mi][2], af[mi][3]);
#pragma unroll
        for (int pair = 0; pair < 4; pair++) {
            uint32_t b00, b10, b01, b11;
            ldm4t(sptr(&Bs[buf][bl_k][bl_n + pair * 16]), b00, b10, b01, b11);
#pragma unroll
            for (int mi = 0; mi < 2; mi++) {
                mma16(acc[mi][2*pair    ], af[mi][0], af[mi][1], af[mi][2], af[mi][3], b00, b10);
                mma16(acc[mi][2*pair + 1], af[mi][0], af[mi][1], af[mi][2], af[mi][3], b01, b11);
            }
        }

        if (s + 2 < nst) HG_ISSUE(s + 2, (s + 2) % 3);
        CP_COMMIT();
    }
#undef HG_ISSUE

#pragma unroll
    for (int mi = 0; mi < 2; mi++) {
        int r0 = mblk + wm * 32 + mi * 16 + g;
#pragma unroll
        for (int ni = 0; ni < 8; ni++) {
            int c = nblk + wn * 64 + ni * 8 + tg * 2;
            float b0 = bias[c], b1 = bias[c + 1];
            float v0 = acc[mi][ni][0] + b0, v1 = acc[mi][ni][1] + b1;
            float v2 = acc[mi][ni][2] + b0, v3 = acc[mi][ni][3] + b1;
            if (dogelu) {
                v0 = 0.5f * v0 * (1.0f + erff(v0 * 0.70710678118654752f));
                v1 = 0.5f * v1 * (1.0f + erff(v1 * 0.70710678118654752f));
                v2 = 0.5f * v2 * (1.0f + erff(v2 * 0.70710678118654752f));
                v3 = 0.5f * v3 * (1.0f + erff(v3 * 0.70710678118654752f));
            }
            if (Ch) {
                *(__half2*)&Ch[(size_t)r0 * N + c]       = __floats2half2_rn(v0, v1);
                *(__half2*)&Ch[(size_t)(r0 + 8) * N + c] = __floats2half2_rn(v2, v3);
            } else {
                *(float2*)&Cf[(size_t)r0 * N + c]       = make_float2(v0, v1);
                *(float2*)&Cf[(size_t)(r0 + 8) * N + c] = make_float2(v2, v3);
            }
        }
    }
}

__global__ __launch_bounds__(256) void hgemm_k(
    const __half* __restrict__ A, const __half* __restrict__ W,
    const float* __restrict__ bias, float* __restrict__ Cf,
    __half* __restrict__ Ch, int K, int N, int dogelu)
{
    hgemm_body(A, W, bias, Cf, Ch, K, N, dogelu);
}

// Batched projections: z=0..7 -> (layer z/2, Q/K), z=8 -> V3. Pure fp16.
__global__ __launch_bounds__(256) void proj_k(
    const __half* __restrict__ Xh, const __half* __restrict__ Yh,
    const __half* __restrict__ Wqh, const float* __restrict__ bq,
    const __half* __restrict__ Wkh, const float* __restrict__ bk,
    const __half* __restrict__ Wvh, const float* __restrict__ bv,
    __half* __restrict__ QK, __half* __restrict__ V)
{
    const int z = blockIdx.z;
    const __half *A, *W;
    const float* Bi;
    __half* C;
    if (z < 8) {
        int l = z >> 1, isK = z & 1;
        A  = isK ? Yh : Xh;
        W  = (isK ? Wkh : Wqh) + (size_t)l * EE;
        Bi = (isK ? bk : bq) + (size_t)l * EC;
        C  = QK + (size_t)z * BNE;
    } else {
        A = Yh; W = Wvh; Bi = bv + (size_t)3 * EC; C = V;
    }
    hgemm_body(A, W, Bi, (float*)0, C, EC, EC, 0);
}

// ---------------------------------------------------------------------------
// FP32-input GEMM (Wo only): C = (A + A2) @ W + bias. Old proven path.
// ---------------------------------------------------------------------------
__device__ __forceinline__ void gemm16_body(
    const float* __restrict__ A, const float* __restrict__ A2,
    const float* __restrict__ W,
    const float* __restrict__ bias, float* __restrict__ Cf,
    int K, int N)
{
    __shared__ uint32_t As2[2][128][12];
    __shared__ __half   Bs [2][16][136];

    const int tid  = threadIdx.x;
    const int warp = tid >> 5, lane = tid & 31;
    const int wm = warp >> 1, wn = warp & 1;
    const int g  = lane >> 2, tg = lane & 3;
    const int mblk = blockIdx.y * 128, nblk = blockIdx.x * 128;

    const int arow = tid >> 1, aseg = (tid & 1) * 4;
    const int wrow = tid >> 4, wcol = (tid & 15) * 8;

    const float* Ag  = A  + (size_t)(mblk + arow) * K + aseg * 2;
    const float* Ag2 = A2 + (size_t)(mblk + arow) * K + aseg * 2;
    const float* Wg  = W + (size_t)wrow * N + nblk + wcol;

    const int la_r = LA_ROW(lane), la_c = LA_COL(lane);
    const int bl_k = (lane & 7) + ((lane >> 3) & 1) * 8;
    const int bl_n = wn * 64 + (lane >> 4) * 8;

    float acc[2][8][4];
#pragma unroll
    for (int mi = 0; mi < 2; mi++)
#pragma unroll
        for (int ni = 0; ni < 8; ni++)
#pragma unroll
            for (int q = 0; q < 4; q++) acc[mi][ni][q] = 0.f;

    {
        float4 a0 = *(const float4*)(Ag);
        float4 a1 = *(const float4*)(Ag + 4);
        float4 c0 = *(const float4*)(Ag2);
        float4 c1 = *(const float4*)(Ag2 + 4);
        a0.x += c0.x; a0.y += c0.y; a0.z += c0.z; a0.w += c0.w;
        a1.x += c1.x; a1.y += c1.y; a1.z += c1.z; a1.w += c1.w;
        As2[0][arow][aseg+0] = pack2(a0.x, a0.y);
        As2[0][arow][aseg+1] = pack2(a0.z, a0.w);
        As2[0][arow][aseg+2] = pack2(a1.x, a1.y);
        As2[0][arow][aseg+3] = pack2(a1.z, a1.w);
        float4 w0 = *(const float4*)(Wg);
        float4 w1 = *(const float4*)(Wg + 4);
        __half2* bp = (__half2*)&Bs[0][wrow][wcol];
        bp[0] = __floats2half2_rn(w0.x, w0.y);
        bp[1] = __floats2half2_rn(w0.z, w0.w);
        bp[2] = __floats2half2_rn(w1.x, w1.y);
        bp[3] = __floats2half2_rn(w1.z, w1.w);
    }
    __syncthreads();

    const int nst = K >> 4;
    for (int s = 0; s < nst; s++) {
        const int buf = s & 1;
        const bool more = (s + 1 < nst);
        float4 pa0, pa1, pw0, pw1;
        if (more) {
            const float* Ap = Ag + (s + 1) * 16;
            const float* Ap2 = Ag2 + (s + 1) * 16;
            const float* Wp = Wg + (size_t)(s + 1) * 16 * N;
            pa0 = *(const float4*)Ap; pa1 = *(const float4*)(Ap + 4);
            float4 c0 = *(const float4*)Ap2;
            float4 c1 = *(const float4*)(Ap2 + 4);
            pa0.x += c0.x; pa0.y += c0.y; pa0.z += c0.z; pa0.w += c0.w;
            pa1.x += c1.x; pa1.y += c1.y; pa1.z += c1.z; pa1.w += c1.w;
            pw0 = *(const float4*)Wp; pw1 = *(const float4*)(Wp + 4);
        }

        uint32_t af[2][4];
#pragma unroll
        for (int mi = 0; mi < 2; mi++)
            ldm4(sptr(&As2[buf][wm * 32 + mi * 16 + la_r][la_c]),
                 af[mi][0], af[mi][1], af[mi][2], af[mi][3]);
#pragma unroll
        for (int pair = 0; pair < 4; pair++) {
            uint32_t b00, b10, b01, b11;
            ldm4t(sptr(&Bs[buf][bl_k][bl_n + pair * 16]), b00, b10, b01, b11);
#pragma unroll
            for (int mi = 0; mi < 2; mi++) {
                mma16(acc[mi][2*pair    ], af[mi][0], af[mi][1], af[mi][2], af[mi][3], b00, b10);
                mma16(acc[mi][2*pair + 1], af[mi][0], af[mi][1], af[mi][2], af[mi][3], b01, b11);
            }
        }

        if (more) {
            const int nb = buf ^ 1;
            As2[nb][arow][aseg+0] = pack2(pa0.x, pa0.y);
            As2[nb][arow][aseg+1] = pack2(pa0.z, pa0.w);
            As2[nb][arow][aseg+2] = pack2(pa1.x, pa1.y);
            As2[nb][arow][aseg+3] = pack2(pa1.z, pa1.w);
            __half2* bp = (__half2*)&Bs[nb][wrow][wcol];
            bp[0] = __floats2half2_rn(pw0.x, pw0.y);
            bp[1] = __floats2half2_rn(pw0.z, pw0.w);
            bp[2] = __floats2half2_rn(pw1.x, pw1.y);
            bp[3] = __floats2half2_rn(pw1.z, pw1.w);
            __syncthreads();
        }
    }

#pragma unroll
    for (int mi = 0; mi < 2; mi++) {
        int r0 = mblk + wm * 32 + mi * 16 + g;
#pragma unroll
        for (int ni = 0; ni < 8; ni++) {
            int c = nblk + wn * 64 + ni * 8 + tg * 2;
            float b0 = bias[c], b1 = bias[c + 1];
            *(float2*)&Cf[(size_t)r0 * N + c] =
                make_float2(acc[mi][ni][0] + b0, acc[mi][ni][1] + b1);
            *(float2*)&Cf[(size_t)(r0 + 8) * N + c] =
                make_float2(acc[mi][ni][2] + b0, acc[mi][ni][3] + b1);
        }
    }
}

__global__ __launch_bounds__(256) void gemm2_k(
    const float* __restrict__ A, const float* __restrict__ A2,
    const float* __restrict__ W,
    const float* __restrict__ bias, float* __restrict__ C,
    int K, int N)
{
    gemm16_body(A, A2, W, bias, C, K, N);
}

// ---------------------------------------------------------------------------
// Scores: S = (Q @ K^T)*0.125, masked, fp16 in/out, cp.async tile loads.
// FAITHFUL head split: contiguous [1024 x 64] chunk at b*NX*E + h*NX*DH.
// Grid (NY/128, NX/128, 4*32), 256 threads.
// ---------------------------------------------------------------------------
__global__ __launch_bounds__(256) void scores_k(
    const __half* __restrict__ QK, const int* __restrict__ xm,
    const int* __restrict__ ym, __half* __restrict__ S4)
{
    __shared__ uint32_t Qs2[128][36];
    __shared__ uint32_t Ks2[128][36];

    const int z = blockIdx.z;
    const int l = z >> 5, bh = z & 31, b = bh >> 3, h = bh & 7;
    const uint32_t* Qb = (const uint32_t*)(QK + (size_t)(2 * l) * BNE)
                         + (size_t)b * NXC * 256 + (size_t)h * NXC * 32;
    const uint32_t* Kb = (const uint32_t*)(QK + (size_t)(2 * l + 1) * BNE)
                         + (size_t)b * NYC * 256 + (size_t)h * NYC * 32;

    const int mblk = blockIdx.y * 128;
    const int nblk = blockIdx.x * 128;
    const int tid  = threadIdx.x;
    const int warp = tid >> 5, lane = tid & 31;
    const int wm = warp >> 1, wn = warp & 1;
    const int g = lane >> 2, tg = lane & 3;

    const int la_r = LA_ROW(lane), la_c = LA_COL(lane);
    const int lb_r = LB_ROW(lane), lb_c = LB_COL(lane);

    {
        int r = tid >> 1;
        int wseg = (tid & 1) * 16;
        const uint32_t* qsrc = Qb + (size_t)(mblk + r) * 32 + wseg;
        const uint32_t* ksrc = Kb + (size_t)(nblk + r) * 32 + wseg;
#pragma unroll
        for (int i = 0; i < 4; i++) {
            cpa16(sptr(&Qs2[r][wseg + i * 4]), qsrc + i * 4);
            cpa16(sptr(&Ks2[r][wseg + i * 4]), ksrc + i * 4);
        }
    }
    CP_COMMIT();
    CP_WAIT0();
    __syncthreads();

    float acc[2][8][4];
#pragma unroll
    for (int mi = 0; mi < 2; mi++)
#pragma unroll
        for (int ni = 0; ni < 8; ni++)
#pragma unroll
            for (int q = 0; q < 4; q++) acc[mi][ni][q] = 0.f;

#pragma unroll
    for (int c = 0; c < 4; c++) {
        uint32_t af[2][4];
#pragma unroll
        for (int mi = 0; mi < 2; mi++)
            ldm4(sptr(&Qs2[wm * 32 + mi * 16 + la_r][8 * c + la_c]),
                 af[mi][0], af[mi][1], af[mi][2], af[mi][3]);
#pragma unroll
        for (int nq = 0; nq < 4; nq++) {
            uint32_t b00, b01, b10, b11;
            ldm4(sptr(&Ks2[wn * 64 + nq * 16 + lb_r][8 * c + lb_c]),
                 b00, b01, b10, b11);
#pragma unroll
            for (int mi = 0; mi < 2; mi++) {
                mma16(acc[mi][2*nq    ], af[mi][0], af[mi][1], af[mi][2], af[mi][3], b00, b01);
                mma16(acc[mi][2*nq + 1], af[mi][0], af[mi][1], af[mi][2], af[mi][3], b10, b11);
            }
        }
    }

    __half* Sl = S4 + (size_t)l * BHNN + (size_t)bh * NXC * NYC;
#pragma unroll
    for (int mi = 0; mi < 2; mi++) {
        int r0 = mblk + wm * 32 + mi * 16 + g;
        int xr0 = xm[b * NXC + r0], xr1 = xm[b * NXC + r0 + 8];
#pragma unroll
        for (int ni = 0; ni < 8; ni++) {
            int c = nblk + wn * 64 + ni * 8 + tg * 2;
            int yc0 = ym[b * NYC + c], yc1 = ym[b * NYC + c + 1];
            float v0 = (xr0 && yc0) ? acc[mi][ni][0] * 0.125f : MASKED_H;
            float v1 = (xr0 && yc1) ? acc[mi][ni][1] * 0.125f : MASKED_H;
            float v2 = (xr1 && yc0) ? acc[mi][ni][2] * 0.125f : MASKED_H;
            float v3 = (xr1 && yc1) ? acc[mi][ni][3] * 0.125f : MASKED_H;
            *(__half2*)&Sl[(size_t)r0 * NYC + c]       = __floats2half2_rn(v0, v1);
            *(__half2*)&Sl[(size_t)(r0 + 8) * NYC + c] = __floats2half2_rn(v2, v3);
        }
    }
}

// ---------------------------------------------------------------------------
// Fused softmax-sum, warp-per-row: A[row] = sum_l softmax(S_l[row]).
// ---------------------------------------------------------------------------
__global__ __launch_bounds__(256) void softmax4_k(
    const __half* __restrict__ S4, __half* __restrict__ A)
{
    const int warp = threadIdx.x >> 5, lane = threadIdx.x & 31;
    const size_t base = ((size_t)blockIdx.x * 8 + warp) * NYC;

    float acc[32];
#pragma unroll
    for (int i = 0; i < 32; i++) acc[i] = 0.f;

#pragma unroll
    for (int l = 0; l < 4; l++) {
        const __half* Sr = S4 + (size_t)l * BHNN + base;
        float v[32];
#pragma unroll
        for (int i = 0; i < 4; i++) {
            uint4 u = *(const uint4*)(Sr + i * 256 + lane * 8);
            float2 f;
            f = __half22float2(*(__half2*)&u.x); v[i*8+0]=f.x; v[i*8+1]=f.y;
            f = __half22float2(*(__half2*)&u.y); v[i*8+2]=f.x; v[i*8+3]=f.y;
            f = __half22float2(*(__half2*)&u.z); v[i*8+4]=f.x; v[i*8+5]=f.y;
            f = __half22float2(*(__half2*)&u.w); v[i*8+6]=f.x; v[i*8+7]=f.y;
        }
        float m = v[0];
#pragma unroll
        for (int i = 1; i < 32; i++) m = fmaxf(m, v[i]);
#pragma unroll
        for (int o = 16; o > 0; o >>= 1) m = fmaxf(m, __shfl_xor_sync(0xffffffffu, m, o));
        float s = 0.f;
#pragma unroll
        for (int i = 0; i < 32; i++) { v[i] = __expf(v[i] - m); s += v[i]; }
#pragma unroll
        for (int o = 16; o > 0; o >>= 1) s += __shfl_xor_sync(0xffffffffu, s, o);
        float inv = 1.0f / s;
#pragma unroll
        for (int i = 0; i < 32; i++) acc[i] += v[i] * inv;
    }

#pragma unroll
    for (int i = 0; i < 4; i++) {
        uint4 u;
        __half2* p = (__half2*)&u;
        p[0] = __floats2half2_rn(acc[i*8+0], acc[i*8+1]);
        p[1] = __floats2half2_rn(acc[i*8+2], acc[i*8+3]);
        p[2] = __floats2half2_rn(acc[i*8+4], acc[i*8+5]);
        p[3] = __floats2half2_rn(acc[i*8+6], acc[i*8+7]);
        *(uint4*)(A + base + i * 256 + lane * 8) = u;
    }
}

// ---------------------------------------------------------------------------
// O_partial = attn[:, z*512:(z+1)*512] @ V[z*512:(z+1)*512, :]
// 3-stage cp.async pipeline. Block 64x64, 128 threads, BK=32, split-K=2.
// ---------------------------------------------------------------------------
__global__ __launch_bounds__(128) void attnv_k(
    const __half* __restrict__ Aa, const __half* __restrict__ V,
    float* __restrict__ O0, float* __restrict__ O1)
{
    __shared__ uint32_t As2[3][64][20];
    __shared__ __half   Vs [3][32][136];

    const int bh = blockIdx.y, b = bh >> 3, h = bh & 7;
    const int mblk = blockIdx.x * 64;
    const int zz = blockIdx.z;
    const int tid = threadIdx.x;
    const int warp = tid >> 5, lane = tid & 31;
    const int g = lane >> 2, tg = lane & 3;

    const uint32_t* Ab = (const uint32_t*)(Aa + (size_t)bh * NXC * NYC);
    const __half* Vb = V + (size_t)b * NYC * EC + (size_t)h * NYC * DHC
                         + (size_t)zz * 512 * DHC;

    const int arow = tid >> 1, aseg = (tid & 1) * 8;
    const int vrow = tid >> 2, vcol = (tid & 3) * 16;

    const uint32_t* Ag = Ab + (size_t)(mblk + arow) * 512 + zz * 256 + aseg;

    const int la_r = LA_ROW(lane), la_c = LA_COL(lane);
    const int vl_k = (lane & 7) + ((lane >> 3) & 1) * 8;
    const int vl_n = (lane >> 4) * 8;

    float acc[8][4];
#pragma unroll
    for (int ni = 0; ni < 8; ni++)
#pragma unroll
        for (int q = 0; q < 4; q++) acc[ni][q] = 0.f;

#define AV_ISSUE(st, bf) do { \
        cpa16(sptr(&As2[bf][arow][aseg]),     Ag + (st) * 16); \
        cpa16(sptr(&As2[bf][arow][aseg + 4]), Ag + (st) * 16 + 4); \
        const __half* Vg_ = Vb + (size_t)((st) * 32 + vrow) * DHC + vcol; \
        cpa16(sptr(&Vs[bf][vrow][vcol]),     Vg_); \
        cpa16(sptr(&Vs[bf][vrow][vcol + 8]), Vg_ + 8); \
    } while (0)

    AV_ISSUE(0, 0); CP_COMMIT();
    AV_ISSUE(1, 1); CP_COMMIT();

    for (int s = 0; s < 16; s++) {
        CP_WAIT1();
        __syncthreads();
        const int buf = s % 3;

#pragma unroll
        for (int cc = 0; cc < 2; cc++) {
            uint32_t a0, a1, a2, a3;
            ldm4(sptr(&As2[buf][warp * 16 + la_r][8 * cc + la_c]), a0, a1, a2, a3);
#pragma unroll
            for (int pair = 0; pair < 4; pair++) {
                uint32_t b00, b10, b01, b11;
                ldm4t(sptr(&Vs[buf][16*cc + vl_k][pair * 16 + vl_n]), b00, b10, b01, b11);
                mma16(acc[2*pair    ], a0, a1, a2, a3, b00, b10);
                mma16(acc[2*pair + 1], a0, a1, a2, a3, b01, b11);
            }
        }

        if (s + 2 < 16) AV_ISSUE(s + 2, (s + 2) % 3);
        CP_COMMIT();
    }
#undef AV_ISSUE

    float* Op = (zz == 0 ? O0 : O1);
    const int r0 = mblk + warp * 16 + g;
    float* Ob = Op + (size_t)b * NXC * EC + (size_t)h * DHC;
#pragma unroll
    for (int ni = 0; ni < 8; ni++) {
        int c = ni * 8 + tg * 2;
        *(float2*)&Ob[(size_t)r0 * EC + c]       = make_float2(acc[ni][0], acc[ni][1]);
        *(float2*)&Ob[(size_t)(r0 + 8) * EC + c] = make_float2(acc[ni][2], acc[ni][3]);
    }
}

// ---------------------------------------------------------------------------
// Residual + LayerNorm: Out = LN(X + R) * g + be. Optional fp16 copy.
// ---------------------------------------------------------------------------
__global__ __launch_bounds__(128) void resln_k(
    const float* __restrict__ X, const float* __restrict__ R,
    const float* __restrict__ g, const float* __restrict__ be,
    float* __restrict__ Out, __half* __restrict__ Outh)
{
    __shared__ float sred[4];
    __shared__ float sbc;

    const size_t base = (size_t)blockIdx.x * EC;
    const int tid = threadIdx.x, lane = tid & 31, w = tid >> 5;

    float r[4];
    int col[4];
#pragma unroll
    for (int i = 0; i < 4; i++) {
        col[i] = tid + i * 128;
        r[i] = X[base + col[i]] + R[base + col[i]];
    }

    float s = r[0] + r[1] + r[2] + r[3];
#pragma unroll
    for (int o = 16; o > 0; o >>= 1) s += __shfl_xor_sync(0xffffffffu, s, o);
    if (lane == 0) sred[w] = s;
    __syncthreads();
    if (tid == 0) sbc = sred[0] + sred[1] + sred[2] + sred[3];
    __syncthreads();
    const float mu = sbc * (1.0f / EC);

    float d[4], ss = 0.f;
#pragma unroll
    for (int i = 0; i < 4; i++) { d[i] = r[i] - mu; ss += d[i] * d[i]; }
#pragma unroll
    for (int o = 16; o > 0; o >>= 1) ss += __shfl_xor_sync(0xffffffffu, ss, o);
    if (lane == 0) sred[w] = ss;
    __syncthreads();
    if (tid == 0) sbc = sred[0] + sred[1] + sred[2] + sred[3];
    __syncthreads();
    const float rs = rsqrtf(sbc * (1.0f / EC) + 1e-5f);

#pragma unroll
    for (int i = 0; i < 4; i++) {
        float v = d[i] * rs * g[col[i]] + be[col[i]];
        Out[base + col[i]] = v;
        if (Outh) Outh[base + col[i]] = __float2half_rn(v);
    }
}

// ---------------------------------------------------------------------------
// Host
// ---------------------------------------------------------------------------
extern "C" void kernel_launch(void* const* d_in, const int* in_sizes, int n_in,
                              void* d_out, int out_size)
{
    (void)in_sizes; (void)n_in; (void)out_size;

    const float* x   = (const float*)d_in[0];
    const float* y   = (const float*)d_in[1];
    const int*   xm  = (const int*)  d_in[2];
    const int*   ym  = (const int*)  d_in[3];
    const float* Wq  = (const float*)d_in[4];
    const float* bq  = (const float*)d_in[5];
    const float* Wk  = (const float*)d_in[6];
    const float* bk  = (const float*)d_in[7];
    const float* Wv  = (const float*)d_in[8];
    const float* bv  = (const float*)d_in[9];
    const float* Wo  = (const float*)d_in[10];
    const float* bo  = (const float*)d_in[11];
    const float* g1  = (const float*)d_in[12];
    const float* be1 = (const float*)d_in[13];
    const float* g2  = (const float*)d_in[14];
    const float* be2 = (const float*)d_in[15];
    const float* W1  = (const float*)d_in[16];
    const float* bf1 = (const float*)d_in[17];
    const float* W2  = (const float*)d_in[18];
    const float* bf2 = (const float*)d_in[19];
    float* out = (float*)d_out;

    float *O, *O2, *Hb, *F2;
    __half *QK, *V, *S4, *Aa, *Xh, *Yh, *Wqh, *Wkh, *Wvh, *W1h, *W2h, *Hbh, *F1h;
    cudaGetSymbolAddress((void**)&QK,  g_QK);
    cudaGetSymbolAddress((void**)&V,   g_V);
    cudaGetSymbolAddress((void**)&O,   g_O);
    cudaGetSymbolAddress((void**)&O2,  g_O2);
    cudaGetSymbolAddress((void**)&Hb,  g_Hb);
    cudaGetSymbolAddress((void**)&F2,  g_F2);
    cudaGetSymbolAddress((void**)&S4,  g_S4);
    cudaGetSymbolAddress((void**)&Aa,  g_A);
    cudaGetSymbolAddress((void**)&Xh,  g_Xh);
    cudaGetSymbolAddress((void**)&Yh,  g_Yh);
    cudaGetSymbolAddress((void**)&Wqh, g_Wqh);
    cudaGetSymbolAddress((void**)&Wkh, g_Wkh);
    cudaGetSymbolAddress((void**)&Wvh, g_Wvh);
    cudaGetSymbolAddress((void**)&W1h, g_W1h);
    cudaGetSymbolAddress((void**)&W2h, g_W2h);
    cudaGetSymbolAddress((void**)&Hbh, g_Hbh);
    cudaGetSymbolAddress((void**)&F1h, g_F1h);

    // 0. fp32 -> fp16 conversions
    cvt_k<<<512, 256>>>(x, Xh, BNE);
    cvt_k<<<512, 256>>>(y, Yh, BNE);
    cvt_k<<<512, 256>>>(Wq, Wqh, 4 * EE);
    cvt_k<<<512, 256>>>(Wk, Wkh, 4 * EE);
    cvt_k<<<256, 256>>>(Wv + (size_t)3 * EE, Wvh, EE);
    cvt_k<<<512, 256>>>(W1 + (size_t)3 * EC * FFC, W1h, EC * FFC);
    cvt_k<<<512, 256>>>(W2 + (size_t)3 * FFC * EC, W2h, FFC * EC);

    // 1. All Q_l, K_l projections + V_3 (pure-fp16 GEMM)
    proj_k<<<dim3(4, 32, 9), 256>>>(Xh, Yh, Wqh, bq, Wkh, bk, Wvh, bv, QK, V);
    // 2. All layers' masked scores
    scores_k<<<dim3(8, 8, 128), 256>>>(QK, xm, ym, S4);
    // 3. Fused softmax-sum (a_3 = sum_l softmax(S_l))
    softmax4_k<<<BB * HC * NXC / 8, 256>>>(S4, Aa);
    // 4. attn @ V split-K=2
    attnv_k<<<dim3(16, 32, 2), 128>>>(Aa, V, O, O2);
    // 5. Wo GEMM sums partials (fp32-input path): F2 = (O + O2) @ Wo + bo
    gemm2_k<<<dim3(4, 32), 256>>>(O, O2, Wo + (size_t)3 * EE, bo + 3 * EC, F2, EC, EC);
    resln_k<<<MC, 128>>>(x, F2, g1 + 3 * EC, be1 + 3 * EC, Hb, Hbh);
    // 6. FFN (pure-fp16 GEMMs)
    hgemm_k<<<dim3(16, 32), 256>>>(Hbh, W1h, bf1 + (size_t)3 * FFC, (float*)0, F1h, EC, FFC, 1);
    hgemm_k<<<dim3(4, 32), 256>>>(F1h, W2h, bf2 + 3 * EC, O, (__half*)0, FFC, EC, 0);
    resln_k<<<MC, 128>>>(Hb, O, g2 + 3 * EC, be2 + 3 * EC, out, (__half*)0);
}

// round 16
// speedup vs baseline: 4.8216x; 1.0198x over previous
#include <cuda_runtime.h>
#include <cuda_fp16.h>
#include <math.h>
#include <stdint.h>

// Problem constants
#define BB   4
#define NXC  1024
#define NYC  1024
#define EC   512
#define HC   8
#define DHC  64
#define LC   4
#define FFC  2048
#define MC   (BB * NXC)

#define BNE  (BB * NXC * EC)                  // 2,097,152
#define BHNN ((size_t)BB * HC * NXC * NYC)    // 33,554,432
#define EE   (EC * EC)

// ---------------------------------------------------------------------------
// Scratch (device globals; allocation-free per harness rules)
// ---------------------------------------------------------------------------
__device__ __half g_QK[8 * (size_t)BNE];      // Q0,K0,..,Q3,K3 fp16 (full)
__device__ __half g_Kc[4 * (size_t)BNE];      // compacted-position K, 4 layers
__device__ __half g_V [BNE];                  // V3 fp16 (full)
__device__ __half g_Vc[BNE];                  // V3 compacted positions
__device__ float  g_O [BNE];                  // attnv partial 0 / W2 out
__device__ float  g_O2[BNE];                  // attnv partial 1
__device__ float  g_Hb[BNE];
__device__ float  g_F2[BNE];
__device__ __half g_S4[4 * BHNN];             // scores fp16 (compacted cols)
__device__ __half g_A [BHNN];                 // summed attention fp16
__device__ __half g_Xh [BNE];
__device__ __half g_Yh [BNE];
__device__ __half g_Wqh[4 * EE];
__device__ __half g_Wkh[4 * EE];
__device__ __half g_Wvh[EE];
__device__ __half g_W1h[(size_t)EC * FFC];
__device__ __half g_W2h[(size_t)FFC * EC];
__device__ __half g_Hbh[BNE];
__device__ __half g_F1h[(size_t)MC * FFC];
__device__ float  g_CS[BB * EC];              // per-(b,h,d) colsum of V positions
__device__ int    g_Nc[BB];                   // # unmasked y positions per batch
__device__ int    g_NcPad[BB];                // Nc rounded up to 256
__device__ int    g_yidx[BB][NYC];            // position compaction indices

#define MASKED_H (-30000.0f)

// ---------------------------------------------------------------------------
// Helpers
// ---------------------------------------------------------------------------
__device__ __forceinline__ uint32_t pack2(float a, float b) {
    __half2 h = __floats2half2_rn(a, b);
    return *(uint32_t*)&h;
}

__device__ __forceinline__ uint32_t sptr(const void* p) {
    return (uint32_t)__cvta_generic_to_shared(p);
}

__device__ __forceinline__ void cpa16(uint32_t saddr, const void* gptr) {
    asm volatile("cp.async.ca.shared.global [%0], [%1], 16;"
                 :: "r"(saddr), "l"(gptr));
}
#define CP_COMMIT() asm volatile("cp.async.commit_group;" ::: "memory")
#define CP_WAIT0()  asm volatile("cp.async.wait_group 0;" ::: "memory")
#define CP_WAIT1()  asm volatile("cp.async.wait_group 1;" ::: "memory")

__device__ __forceinline__ void mma16(float* c,
    uint32_t a0, uint32_t a1, uint32_t a2, uint32_t a3,
    uint32_t b0, uint32_t b1)
{
    asm volatile(
        "mma.sync.aligned.m16n8k16.row.col.f32.f16.f16.f32 "
        "{%0,%1,%2,%3},{%4,%5,%6,%7},{%8,%9},{%0,%1,%2,%3};"
        : "+f"(c[0]), "+f"(c[1]), "+f"(c[2]), "+f"(c[3])
        : "r"(a0), "r"(a1), "r"(a2), "r"(a3), "r"(b0), "r"(b1));
}

__device__ __forceinline__ void ldm4t(uint32_t addr,
    uint32_t& r0, uint32_t& r1, uint32_t& r2, uint32_t& r3)
{
    asm volatile(
        "ldmatrix.sync.aligned.m8n8.x4.trans.shared.b16 {%0,%1,%2,%3}, [%4];"
        : "=r"(r0), "=r"(r1), "=r"(r2), "=r"(r3) : "r"(addr));
}

__device__ __forceinline__ void ldm4(uint32_t addr,
    uint32_t& r0, uint32_t& r1, uint32_t& r2, uint32_t& r3)
{
    asm volatile(
        "ldmatrix.sync.aligned.m8n8.x4.shared.b16 {%0,%1,%2,%3}, [%4];"
        : "=r"(r0), "=r"(r1), "=r"(r2), "=r"(r3) : "r"(addr));
}

#define LA_ROW(lane) (((lane) & 7) + (((lane) >> 3) & 1) * 8)
#define LA_COL(lane) ((((lane) >> 4) & 1) * 4)
#define LB_ROW(lane) (((lane) & 7) + (((lane) >> 4) & 1) * 8)
#define LB_COL(lane) ((((lane) >> 3) & 1) * 4)

// ---------------------------------------------------------------------------
// fp32 -> fp16 conversion
// ---------------------------------------------------------------------------
__global__ __launch_bounds__(256) void cvt_k(
    const float* __restrict__ src, __half* __restrict__ dst, int n)
{
    for (int i = (blockIdx.x * 256 + threadIdx.x) * 4; i < n;
         i += gridDim.x * 256 * 4) {
        float4 v = *(const float4*)(src + i);
        *(uint32_t*)(dst + i)     = pack2(v.x, v.y);
        *(uint32_t*)(dst + i + 2) = pack2(v.z, v.w);
    }
}

// ---------------------------------------------------------------------------
// Per-batch compaction index of unmasked y POSITIONS (deterministic).
// ---------------------------------------------------------------------------
__global__ __launch_bounds__(1024) void maskscan_k(const int* __restrict__ ym)
{
    __shared__ int wtot[32];
    __shared__ int wbase[32];
    const int b = blockIdx.x, tid = threadIdx.x;
    const int lane = tid & 31, w = tid >> 5;
    int v = (ym[b * NYC + tid] != 0) ? 1 : 0;
    unsigned mask = __ballot_sync(0xffffffffu, v);
    int pos = __popc(mask & ((1u << lane) - 1u));
    if (lane == 0) wtot[w] = __popc(mask);
    __syncthreads();
    if (tid < 32) {
        int e = 0;
        for (int i = 0; i < 32; i++) if (i < tid) e += wtot[i];
        wbase[tid] = e;
        if (tid == 31) {
            int tot = e + wtot[31];
            g_Nc[b] = tot;
            g_NcPad[b] = ((tot + 255) >> 8) << 8;
        }
    }
    __syncthreads();
    if (v) g_yidx[b][wbase[w] + pos] = tid;
}

// Gather compacted K HEAD-BLOCK POSITIONS for all 4 layers.
// Grid (8 chunks, 4*32), 256 thr. Kc[l][b,h][j] = K[l][b,h][yidx[j]].
__global__ __launch_bounds__(256) void gatherK_k(
    const __half* __restrict__ QK, __half* __restrict__ Kc)
{
    const int zl = blockIdx.y;                 // l*32 + bh
    const int l = zl >> 5, bh = zl & 31, b = bh >> 3, h = bh & 7;
    const int chunk = blockIdx.x, tid = threadIdx.x;
    const int Nc = g_Nc[b];
    const __half* sb = QK + (size_t)(2 * l + 1) * BNE
                       + (size_t)b * NYC * EC + (size_t)h * NYC * DHC;
    __half* db = Kc + (size_t)l * BNE
                    + (size_t)b * NYC * EC + (size_t)h * NYC * DHC;
    for (int t = tid; t < 128 * 8; t += 256) {
        int j = chunk * 128 + (t >> 3);
        int q = (t & 7) * 8;
        uint4 val = make_uint4(0, 0, 0, 0);
        if (j < Nc) {
            int src = g_yidx[b][j];
            val = *(const uint4*)(sb + (size_t)src * DHC + q);
        }
        *(uint4*)(db + (size_t)j * DHC + q) = val;
    }
}

// Gather compacted V head-block positions. Grid (8, 32), 256 thr.
__global__ __launch_bounds__(256) void gatherV_k(
    const __half* __restrict__ V, __half* __restrict__ Vc)
{
    const int bh = blockIdx.y, b = bh >> 3, h = bh & 7;
    const int chunk = blockIdx.x, tid = threadIdx.x;
    const int Nc = g_Nc[b];
    const __half* sb = V  + (size_t)b * NYC * EC + (size_t)h * NYC * DHC;
    __half*       db = Vc + (size_t)b * NYC * EC + (size_t)h * NYC * DHC;
    for (int t = tid; t < 128 * 8; t += 256) {
        int j = chunk * 128 + (t >> 3);
        int q = (t & 7) * 8;
        uint4 val = make_uint4(0, 0, 0, 0);
        if (j < Nc) {
            int src = g_yidx[b][j];
            val = *(const uint4*)(sb + (size_t)src * DHC + q);
        }
        *(uint4*)(db + (size_t)j * DHC + q) = val;
    }
}

// Per-(b,h,d) sum of FULL V over all 1024 positions. Grid (4, 8), 64 thr.
__global__ __launch_bounds__(64) void colsumV_k(
    const __half* __restrict__ V, float* __restrict__ CS)
{
    const int b = blockIdx.x, h = blockIdx.y, d = threadIdx.x;
    const __half* p = V + (size_t)b * NYC * EC + (size_t)h * NYC * DHC + d;
    float s = 0.f;
#pragma unroll 8
    for (int m = 0; m < NYC; m++) s += __half2float(p[(size_t)m * DHC]);
    CS[b * EC + h * DHC + d] = s;
}

// Fallback for fully-masked x rows: O0 = (4/1024)*colsumV, O1 = 0.
__global__ __launch_bounds__(128) void fallback_k(
    const int* __restrict__ xm, const float* __restrict__ CS,
    float* __restrict__ O0, float* __restrict__ O1)
{
    const int n = blockIdx.x;
    if (xm[n] != 0) return;
    const int b = n >> 10, tid = threadIdx.x;
#pragma unroll
    for (int i = 0; i < 4; i++) {
        int c = tid + i * 128;
        O0[(size_t)n * EC + c] = 0.00390625f * CS[b * EC + c];
        O1[(size_t)n * EC + c] = 0.f;
    }
}

// ---------------------------------------------------------------------------
// Pure-fp16 GEMM body (3-stage cp.async).
// ---------------------------------------------------------------------------
__device__ __forceinline__ void hgemm_body(
    const __half* __restrict__ A, const __half* __restrict__ W,
    const float* __restrict__ bias, float* __restrict__ Cf,
    __half* __restrict__ Ch, int K, int N, int dogelu)
{
    __shared__ uint32_t Ah[3][128][12];
    __shared__ __half   Bs[3][16][136];

    const int tid  = threadIdx.x;
    const int warp = tid >> 5, lane = tid & 31;
    const int wm = warp >> 1, wn = warp & 1;
    const int g  = lane >> 2, tg = lane & 3;
    const int mblk = blockIdx.y * 128, nblk = blockIdx.x * 128;

    const int arow = tid >> 1, aseg = (tid & 1) * 4;
    const int wrow = tid >> 4, wcol = (tid & 15) * 8;

    const __half* Ag = A + (size_t)(mblk + arow) * K + aseg * 2;
    const __half* Wg = W + (size_t)wrow * N + nblk + wcol;

    const int la_r = LA_ROW(lane), la_c = LA_COL(lane);
    const int bl_k = (lane & 7) + ((lane >> 3) & 1) * 8;
    const int bl_n = wn * 64 + (lane >> 4) * 8;

    float acc[2][8][4];
#pragma unroll
    for (int mi = 0; mi < 2; mi++)
#pragma unroll
        for (int ni = 0; ni < 8; ni++)
#pragma unroll
            for (int q = 0; q < 4; q++) acc[mi][ni][q] = 0.f;

    const int nst = K >> 4;

#define HG_ISSUE(st, bf) do { \
        cpa16(sptr(&Ah[bf][arow][aseg]), Ag + (st) * 16); \
        cpa16(sptr(&Bs[bf][wrow][wcol]), Wg + (size_t)(st) * 16 * N); \
    } while (0)

    HG_ISSUE(0, 0); CP_COMMIT();
    HG_ISSUE(1, 1); CP_COMMIT();

    for (int s = 0; s < nst; s++) {
        CP_WAIT1();
        __syncthreads();
        const int buf = s % 3;

        uint32_t af[2][4];
#pragma unroll
        for (int mi = 0; mi < 2; mi++)
            ldm4(sptr(&Ah[buf][wm * 32 + mi * 16 + la_r][la_c]),
                 af[mi][0], af[mi][1], af[mi][2], af[mi][3]);
#pragma unroll
        for (int pair = 0; pair < 4; pair++) {
            uint32_t b00, b10, b01, b11;
            ldm4t(sptr(&Bs[buf][bl_k][bl_n + pair * 16]), b00, b10, b01, b11);
#pragma unroll
            for (int mi = 0; mi < 2; mi++) {
                mma16(acc[mi][2*pair    ], af[mi][0], af[mi][1], af[mi][2], af[mi][3], b00, b10);
                mma16(acc[mi][2*pair + 1], af[mi][0], af[mi][1], af[mi][2], af[mi][3], b01, b11);
            }
        }

        if (s + 2 < nst) HG_ISSUE(s + 2, (s + 2) % 3);
        CP_COMMIT();
    }
#undef HG_ISSUE

#pragma unroll
    for (int mi = 0; mi < 2; mi++) {
        int r0 = mblk + wm * 32 + mi * 16 + g;
#pragma unroll
        for (int ni = 0; ni < 8; ni++) {
            int c = nblk + wn * 64 + ni * 8 + tg * 2;
            float b0 = bias[c], b1 = bias[c + 1];
            float v0 = acc[mi][ni][0] + b0, v1 = acc[mi][ni][1] + b1;
            float v2 = acc[mi][ni][2] + b0, v3 = acc[mi][ni][3] + b1;
            if (dogelu) {
                v0 = 0.5f * v0 * (1.0f + erff(v0 * 0.70710678118654752f));
                v1 = 0.5f * v1 * (1.0f + erff(v1 * 0.70710678118654752f));
                v2 = 0.5f * v2 * (1.0f + erff(v2 * 0.70710678118654752f));
                v3 = 0.5f * v3 * (1.0f + erff(v3 * 0.70710678118654752f));
            }
            if (Ch) {
                *(__half2*)&Ch[(size_t)r0 * N + c]       = __floats2half2_rn(v0, v1);
                *(__half2*)&Ch[(size_t)(r0 + 8) * N + c] = __floats2half2_rn(v2, v3);
            } else {
                *(float2*)&Cf[(size_t)r0 * N + c]       = make_float2(v0, v1);
                *(float2*)&Cf[(size_t)(r0 + 8) * N + c] = make_float2(v2, v3);
            }
        }
    }
}

__global__ __launch_bounds__(256) void hgemm_k(
    const __half* __restrict__ A, const __half* __restrict__ W,
    const float* __restrict__ bias, float* __restrict__ Cf,
    __half* __restrict__ Ch, int K, int N, int dogelu)
{
    hgemm_body(A, W, bias, Cf, Ch, K, N, dogelu);
}

// Batched projections (all on FULL inputs): z=0..7 -> Q/K, z=8 -> V3.
__global__ __launch_bounds__(256) void proj_k(
    const __half* __restrict__ Xh, const __half* __restrict__ Yh,
    const __half* __restrict__ Wqh, const float* __restrict__ bq,
    const __half* __restrict__ Wkh, const float* __restrict__ bk,
    const __half* __restrict__ Wvh, const float* __restrict__ bv,
    __half* __restrict__ QK, __half* __restrict__ V)
{
    const int z = blockIdx.z;
    const __half *A, *W;
    const float* Bi;
    __half* C;
    if (z < 8) {
        int l = z >> 1, isK = z & 1;
        A  = isK ? Yh : Xh;
        W  = (isK ? Wkh : Wqh) + (size_t)l * EE;
        Bi = (isK ? bk : bq) + (size_t)l * EC;
        C  = QK + (size_t)z * BNE;
    } else {
        A = Yh; W = Wvh; Bi = bv + (size_t)3 * EC; C = V;
    }
    hgemm_body(A, W, Bi, (float*)0, C, EC, EC, 0);
}

// ---------------------------------------------------------------------------
// FP32-input GEMM (Wo only): C = (A + A2) @ W + bias.
// ---------------------------------------------------------------------------
__device__ __forceinline__ void gemm16_body(
    const float* __restrict__ A, const float* __restrict__ A2,
    const float* __restrict__ W,
    const float* __restrict__ bias, float* __restrict__ Cf,
    int K, int N)
{
    __shared__ uint32_t As2[2][128][12];
    __shared__ __half   Bs [2][16][136];

    const int tid  = threadIdx.x;
    const int warp = tid >> 5, lane = tid & 31;
    const int wm = warp >> 1, wn = warp & 1;
    const int g  = lane >> 2, tg = lane & 3;
    const int mblk = blockIdx.y * 128, nblk = blockIdx.x * 128;

    const int arow = tid >> 1, aseg = (tid & 1) * 4;
    const int wrow = tid >> 4, wcol = (tid & 15) * 8;

    const float* Ag  = A  + (size_t)(mblk + arow) * K + aseg * 2;
    const float* Ag2 = A2 + (size_t)(mblk + arow) * K + aseg * 2;
    const float* Wg  = W + (size_t)wrow * N + nblk + wcol;

    const int la_r = LA_ROW(lane), la_c = LA_COL(lane);
    const int bl_k = (lane & 7) + ((lane >> 3) & 1) * 8;
    const int bl_n = wn * 64 + (lane >> 4) * 8;

    float acc[2][8][4];
#pragma unroll
    for (int mi = 0; mi < 2; mi++)
#pragma unroll
        for (int ni = 0; ni < 8; ni++)
#pragma unroll
            for (int q = 0; q < 4; q++) acc[mi][ni][q] = 0.f;

    {
        float4 a0 = *(const float4*)(Ag);
        float4 a1 = *(const float4*)(Ag + 4);
        float4 c0 = *(const float4*)(Ag2);
        float4 c1 = *(const float4*)(Ag2 + 4);
        a0.x += c0.x; a0.y += c0.y; a0.z += c0.z; a0.w += c0.w;
        a1.x += c1.x; a1.y += c1.y; a1.z += c1.z; a1.w += c1.w;
        As2[0][arow][aseg+0] = pack2(a0.x, a0.y);
        As2[0][arow][aseg+1] = pack2(a0.z, a0.w);
        As2[0][arow][aseg+2] = pack2(a1.x, a1.y);
        As2[0][arow][aseg+3] = pack2(a1.z, a1.w);
        float4 w0 = *(const float4*)(Wg);
        float4 w1 = *(const float4*)(Wg + 4);
        __half2* bp = (__half2*)&Bs[0][wrow][wcol];
        bp[0] = __floats2half2_rn(w0.x, w0.y);
        bp[1] = __floats2half2_rn(w0.z, w0.w);
        bp[2] = __floats2half2_rn(w1.x, w1.y);
        bp[3] = __floats2half2_rn(w1.z, w1.w);
    }
    __syncthreads();

    const int nst = K >> 4;
    for (int s = 0; s < nst; s++) {
        const int buf = s & 1;
        const bool more = (s + 1 < nst);
        float4 pa0, pa1, pw0, pw1;
        if (more) {
            const float* Ap = Ag + (s + 1) * 16;
            const float* Ap2 = Ag2 + (s + 1) * 16;
            const float* Wp = Wg + (size_t)(s + 1) * 16 * N;
            pa0 = *(const float4*)Ap; pa1 = *(const float4*)(Ap + 4);
            float4 c0 = *(const float4*)Ap2;
            float4 c1 = *(const float4*)(Ap2 + 4);
            pa0.x += c0.x; pa0.y += c0.y; pa0.z += c0.z; pa0.w += c0.w;
            pa1.x += c1.x; pa1.y += c1.y; pa1.z += c1.z; pa1.w += c1.w;
            pw0 = *(const float4*)Wp; pw1 = *(const float4*)(Wp + 4);
        }

        uint32_t af[2][4];
#pragma unroll
        for (int mi = 0; mi < 2; mi++)
            ldm4(sptr(&As2[buf][wm * 32 + mi * 16 + la_r][la_c]),
                 af[mi][0], af[mi][1], af[mi][2], af[mi][3]);
#pragma unroll
        for (int pair = 0; pair < 4; pair++) {
            uint32_t b00, b10, b01, b11;
            ldm4t(sptr(&Bs[buf][bl_k][bl_n + pair * 16]), b00, b10, b01, b11);
#pragma unroll
            for (int mi = 0; mi < 2; mi++) {
                mma16(acc[mi][2*pair    ], af[mi][0], af[mi][1], af[mi][2], af[mi][3], b00, b10);
                mma16(acc[mi][2*pair + 1], af[mi][0], af[mi][1], af[mi][2], af[mi][3], b01, b11);
            }
        }

        if (more) {
            const int nb = buf ^ 1;
            As2[nb][arow][aseg+0] = pack2(pa0.x, pa0.y);
            As2[nb][arow][aseg+1] = pack2(pa0.z, pa0.w);
            As2[nb][arow][aseg+2] = pack2(pa1.x, pa1.y);
            As2[nb][arow][aseg+3] = pack2(pa1.z, pa1.w);
            __half2* bp = (__half2*)&Bs[nb][wrow][wcol];
            bp[0] = __floats2half2_rn(pw0.x, pw0.y);
            bp[1] = __floats2half2_rn(pw0.z, pw0.w);
            bp[2] = __floats2half2_rn(pw1.x, pw1.y);
            bp[3] = __floats2half2_rn(pw1.z, pw1.w);
            __syncthreads();
        }
    }

#pragma unroll
    for (int mi = 0; mi < 2; mi++) {
        int r0 = mblk + wm * 32 + mi * 16 + g;
#pragma unroll
        for (int ni = 0; ni < 8; ni++) {
            int c = nblk + wn * 64 + ni * 8 + tg * 2;
            float b0 = bias[c], b1 = bias[c + 1];
            *(float2*)&Cf[(size_t)r0 * N + c] =
                make_float2(acc[mi][ni][0] + b0, acc[mi][ni][1] + b1);
            *(float2*)&Cf[(size_t)(r0 + 8) * N + c] =
                make_float2(acc[mi][ni][2] + b0, acc[mi][ni][3] + b1);
        }
    }
}

__global__ __launch_bounds__(256) void gemm2_k(
    const float* __restrict__ A, const float* __restrict__ A2,
    const float* __restrict__ W,
    const float* __restrict__ bias, float* __restrict__ C,
    int K, int N)
{
    gemm16_body(A, A2, W, bias, C, K, N);
}

// ---------------------------------------------------------------------------
// Scores over COMPACTED K positions (from g_Kc). Column tiles >= NcPad exit.
// Grid (NY/128, NX/128, 4*32), 256 threads.
// ---------------------------------------------------------------------------
__global__ __launch_bounds__(256) void scores_k(
    const __half* __restrict__ QK, const __half* __restrict__ Kc,
    const int* __restrict__ xm, __half* __restrict__ S4)
{
    __shared__ uint32_t Qs2[128][36];
    __shared__ uint32_t Ks2[128][36];

    const int z = blockIdx.z;
    const int l = z >> 5, bh = z & 31, b = bh >> 3, h = bh & 7;
    const int Nc = g_Nc[b], NcPad = g_NcPad[b];
    const int nblk = blockIdx.x * 128;
    if (nblk >= NcPad) return;

    const uint32_t* Qb = (const uint32_t*)(QK + (size_t)(2 * l) * BNE)
                         + (size_t)b * NXC * 256 + (size_t)h * NXC * 32;
    const uint32_t* Kb = (const uint32_t*)(Kc + (size_t)l * BNE)
                         + (size_t)b * NYC * 256 + (size_t)h * NYC * 32;

    const int mblk = blockIdx.y * 128;
    const int tid  = threadIdx.x;
    const int warp = tid >> 5, lane = tid & 31;
    const int wm = warp >> 1, wn = warp & 1;
    const int g = lane >> 2, tg = lane & 3;

    const int la_r = LA_ROW(lane), la_c = LA_COL(lane);
    const int lb_r = LB_ROW(lane), lb_c = LB_COL(lane);

    {
        int r = tid >> 1;
        int wseg = (tid & 1) * 16;
        const uint32_t* qsrc = Qb + (size_t)(mblk + r) * 32 + wseg;
        const uint32_t* ksrc = Kb + (size_t)(nblk + r) * 32 + wseg;
#pragma unroll
        for (int i = 0; i < 4; i++) {
            cpa16(sptr(&Qs2[r][wseg + i * 4]), qsrc + i * 4);
            cpa16(sptr(&Ks2[r][wseg + i * 4]), ksrc + i * 4);
        }
    }
    CP_COMMIT();
    CP_WAIT0();
    __syncthreads();

    float acc[2][8][4];
#pragma unroll
    for (int mi = 0; mi < 2; mi++)
#pragma unroll
        for (int ni = 0; ni < 8; ni++)
#pragma unroll
            for (int q = 0; q < 4; q++) acc[mi][ni][q] = 0.f;

#pragma unroll
    for (int c = 0; c < 4; c++) {
        uint32_t af[2][4];
#pragma unroll
        for (int mi = 0; mi < 2; mi++)
            ldm4(sptr(&Qs2[wm * 32 + mi * 16 + la_r][8 * c + la_c]),
                 af[mi][0], af[mi][1], af[mi][2], af[mi][3]);
#pragma unroll
        for (int nq = 0; nq < 4; nq++) {
            uint32_t b00, b01, b10, b11;
            ldm4(sptr(&Ks2[wn * 64 + nq * 16 + lb_r][8 * c + lb_c]),
                 b00, b01, b10, b11);
#pragma unroll
            for (int mi = 0; mi < 2; mi++) {
                mma16(acc[mi][2*nq    ], af[mi][0], af[mi][1], af[mi][2], af[mi][3], b00, b01);
                mma16(acc[mi][2*nq + 1], af[mi][0], af[mi][1], af[mi][2], af[mi][3], b10, b11);
            }
        }
    }

    __half* Sl = S4 + (size_t)l * BHNN + (size_t)bh * NXC * NYC;
#pragma unroll
    for (int mi = 0; mi < 2; mi++) {
        int r0 = mblk + wm * 32 + mi * 16 + g;
        int xr0 = xm[b * NXC + r0], xr1 = xm[b * NXC + r0 + 8];
#pragma unroll
        for (int ni = 0; ni < 8; ni++) {
            int c = nblk + wn * 64 + ni * 8 + tg * 2;
            int c0v = (c < Nc), c1v = (c + 1 < Nc);
            float v0 = (xr0 && c0v) ? acc[mi][ni][0] * 0.125f : MASKED_H;
            float v1 = (xr0 && c1v) ? acc[mi][ni][1] * 0.125f : MASKED_H;
            float v2 = (xr1 && c0v) ? acc[mi][ni][2] * 0.125f : MASKED_H;
            float v3 = (xr1 && c1v) ? acc[mi][ni][3] * 0.125f : MASKED_H;
            *(__half2*)&Sl[(size_t)r0 * NYC + c]       = __floats2half2_rn(v0, v1);
            *(__half2*)&Sl[(size_t)(r0 + 8) * NYC + c] = __floats2half2_rn(v2, v3);
        }
    }
}

// ---------------------------------------------------------------------------
// Fused softmax-sum over compacted width. Warp-per-row, 8 rows/block.
// ---------------------------------------------------------------------------
__global__ __launch_bounds__(256) void softmax4_k(
    const __half* __restrict__ S4, __half* __restrict__ A)
{
    const int warp = threadIdx.x >> 5, lane = threadIdx.x & 31;
    const int row = blockIdx.x * 8 + warp;
    const int b = row >> 13;
    const int NcPad = g_NcPad[b];
    const size_t base = (size_t)row * NYC;

    float acc[32];
#pragma unroll
    for (int i = 0; i < 32; i++) acc[i] = 0.f;

#pragma unroll
    for (int l = 0; l < 4; l++) {
        const __half* Sr = S4 + (size_t)l * BHNN + base;
        float v[32];
#pragma unroll
        for (int i = 0; i < 4; i++) {
            if (i * 256 < NcPad) {
                uint4 u = *(const uint4*)(Sr + i * 256 + lane * 8);
                float2 f;
                f = __half22float2(*(__half2*)&u.x); v[i*8+0]=f.x; v[i*8+1]=f.y;
                f = __half22float2(*(__half2*)&u.y); v[i*8+2]=f.x; v[i*8+3]=f.y;
                f = __half22float2(*(__half2*)&u.z); v[i*8+4]=f.x; v[i*8+5]=f.y;
                f = __half22float2(*(__half2*)&u.w); v[i*8+6]=f.x; v[i*8+7]=f.y;
            } else {
#pragma unroll
                for (int j = 0; j < 8; j++) v[i*8+j] = MASKED_H;
            }
        }
        float m = v[0];
#pragma unroll
        for (int i = 1; i < 32; i++) m = fmaxf(m, v[i]);
#pragma unroll
        for (int o = 16; o > 0; o >>= 1) m = fmaxf(m, __shfl_xor_sync(0xffffffffu, m, o));
        float s = 0.f;
#pragma unroll
        for (int i = 0; i < 32; i++) { v[i] = __expf(v[i] - m); s += v[i]; }
#pragma unroll
        for (int o = 16; o > 0; o >>= 1) s += __shfl_xor_sync(0xffffffffu, s, o);
        float inv = 1.0f / s;
#pragma unroll
        for (int i = 0; i < 32; i++) acc[i] += v[i] * inv;
    }

#pragma unroll
    for (int i = 0; i < 4; i++) {
        if (i * 256 < NcPad) {
            uint4 u;
            __half2* p = (__half2*)&u;
            p[0] = __floats2half2_rn(acc[i*8+0], acc[i*8+1]);
            p[1] = __floats2half2_rn(acc[i*8+2], acc[i*8+3]);
            p[2] = __floats2half2_rn(acc[i*8+4], acc[i*8+5]);
            p[3] = __floats2half2_rn(acc[i*8+6], acc[i*8+7]);
            *(uint4*)(A + base + i * 256 + lane * 8) = u;
        }
    }
}

// ---------------------------------------------------------------------------
// attnv over compacted K-dim: each zz handles NcPad/2 positions.
// 3-stage cp.async, BK=32, split-K=2. Grid (NX/64, B*H, 2).
// ---------------------------------------------------------------------------
__global__ __launch_bounds__(128) void attnv_k(
    const __half* __restrict__ Aa, const __half* __restrict__ Vc,
    float* __restrict__ O0, float* __restrict__ O1)
{
    __shared__ uint32_t As2[3][64][20];
    __shared__ __half   Vs [3][32][136];

    const int bh = blockIdx.y, b = bh >> 3, h = bh & 7;
    const int mblk = blockIdx.x * 64;
    const int zz = blockIdx.z;
    const int tid = threadIdx.x;
    const int warp = tid >> 5, lane = tid & 31;
    const int g = lane >> 2, tg = lane & 3;

    const int NcPad = g_NcPad[b];
    const int nst = NcPad >> 6;
    const int krows = zz * (NcPad >> 1);

    const uint32_t* Ab = (const uint32_t*)(Aa + (size_t)bh * NXC * NYC);
    const __half* Vb = Vc + (size_t)b * NYC * EC + (size_t)h * NYC * DHC
                          + (size_t)krows * DHC;

    const int arow = tid >> 1, aseg = (tid & 1) * 8;
    const int vrow = tid >> 2, vcol = (tid & 3) * 16;

    const uint32_t* Ag = Ab + (size_t)(mblk + arow) * 512 + (krows >> 1) + aseg;

    const int la_r = LA_ROW(lane), la_c = LA_COL(lane);
    const int vl_k = (lane & 7) + ((lane >> 3) & 1) * 8;
    const int vl_n = (lane >> 4) * 8;

    float acc[8][4];
#pragma unroll
    for (int ni = 0; ni < 8; ni++)
#pragma unroll
        for (int q = 0; q < 4; q++) acc[ni][q] = 0.f;

#define AV_ISSUE(st, bf) do { \
        cpa16(sptr(&As2[bf][arow][aseg]),     Ag + (st) * 16); \
        cpa16(sptr(&As2[bf][arow][aseg + 4]), Ag + (st) * 16 + 4); \
        const __half* Vg_ = Vb + (size_t)((st) * 32 + vrow) * DHC + vcol; \
        cpa16(sptr(&Vs[bf][vrow][vcol]),     Vg_); \
        cpa16(sptr(&Vs[bf][vrow][vcol + 8]), Vg_ + 8); \
    } while (0)

    AV_ISSUE(0, 0); CP_COMMIT();
    AV_ISSUE(1, 1); CP_COMMIT();

    for (int s = 0; s < nst; s++) {
        CP_WAIT1();
        __syncthreads();
        const int buf = s % 3;

#pragma unroll
        for (int cc = 0; cc < 2; cc++) {
            uint32_t a0, a1, a2, a3;
            ldm4(sptr(&As2[buf][warp * 16 + la_r][8 * cc + la_c]), a0, a1, a2, a3);
#pragma unroll
            for (int pair = 0; pair < 4; pair++) {
                uint32_t b00, b10, b01, b11;
                ldm4t(sptr(&Vs[buf][16*cc + vl_k][pair * 16 + vl_n]), b00, b10, b01, b11);
                mma16(acc[2*pair    ], a0, a1, a2, a3, b00, b10);
                mma16(acc[2*pair + 1], a0, a1, a2, a3, b01, b11);
            }
        }

        if (s + 2 < nst) AV_ISSUE(s + 2, (s + 2) % 3);
        CP_COMMIT();
    }
#undef AV_ISSUE

    float* Op = (zz == 0 ? O0 : O1);
    const int r0 = mblk + warp * 16 + g;
    float* Ob = Op + (size_t)b * NXC * EC + (size_t)h * DHC;
#pragma unroll
    for (int ni = 0; ni < 8; ni++) {
        int c = ni * 8 + tg * 2;
        *(float2*)&Ob[(size_t)r0 * EC + c]       = make_float2(acc[ni][0], acc[ni][1]);
        *(float2*)&Ob[(size_t)(r0 + 8) * EC + c] = make_float2(acc[ni][2], acc[ni][3]);
    }
}

// ---------------------------------------------------------------------------
// Residual + LayerNorm (optional fp16 copy)
// ---------------------------------------------------------------------------
__global__ __launch_bounds__(128) void resln_k(
    const float* __restrict__ X, const float* __restrict__ R,
    const float* __restrict__ g, const float* __restrict__ be,
    float* __restrict__ Out, __half* __restrict__ Outh)
{
    __shared__ float sred[4];
    __shared__ float sbc;

    const size_t base = (size_t)blockIdx.x * EC;
    const int tid = threadIdx.x, lane = tid & 31, w = tid >> 5;

    float r[4];
    int col[4];
#pragma unroll
    for (int i = 0; i < 4; i++) {
        col[i] = tid + i * 128;
        r[i] = X[base + col[i]] + R[base + col[i]];
    }

    float s = r[0] + r[1] + r[2] + r[3];
#pragma unroll
    for (int o = 16; o > 0; o >>= 1) s += __shfl_xor_sync(0xffffffffu, s, o);
    if (lane == 0) sred[w] = s;
    __syncthreads();
    if (tid == 0) sbc = sred[0] + sred[1] + sred[2] + sred[3];
    __syncthreads();
    const float mu = sbc * (1.0f / EC);

    float d[4], ss = 0.f;
#pragma unroll
    for (int i = 0; i < 4; i++) { d[i] = r[i] - mu; ss += d[i] * d[i]; }
#pragma unroll
    for (int o = 16; o > 0; o >>= 1) ss += __shfl_xor_sync(0xffffffffu, ss, o);
    if (lane == 0) sred[w] = ss;
    __syncthreads();
    if (tid == 0) sbc = sred[0] + sred[1] + sred[2] + sred[3];
    __syncthreads();
    const float rs = rsqrtf(sbc * (1.0f / EC) + 1e-5f);

#pragma unroll
    for (int i = 0; i < 4; i++) {
        float v = d[i] * rs * g[col[i]] + be[col[i]];
        Out[base + col[i]] = v;
        if (Outh) Outh[base + col[i]] = __float2half_rn(v);
    }
}

// ---------------------------------------------------------------------------
// Host
// ---------------------------------------------------------------------------
extern "C" void kernel_launch(void* const* d_in, const int* in_sizes, int n_in,
                              void* d_out, int out_size)
{
    (void)in_sizes; (void)n_in; (void)out_size;

    const float* x   = (const float*)d_in[0];
    const float* y   = (const float*)d_in[1];
    const int*   xm  = (const int*)  d_in[2];
    const int*   ym  = (const int*)  d_in[3];
    const float* Wq  = (const float*)d_in[4];
    const float* bq  = (const float*)d_in[5];
    const float* Wk  = (const float*)d_in[6];
    const float* bk  = (const float*)d_in[7];
    const float* Wv  = (const float*)d_in[8];
    const float* bv  = (const float*)d_in[9];
    const float* Wo  = (const float*)d_in[10];
    const float* bo  = (const float*)d_in[11];
    const float* g1  = (const float*)d_in[12];
    const float* be1 = (const float*)d_in[13];
    const float* g2  = (const float*)d_in[14];
    const float* be2 = (const float*)d_in[15];
    const float* W1  = (const float*)d_in[16];
    const float* bf1 = (const float*)d_in[17];
    const float* W2  = (const float*)d_in[18];
    const float* bf2 = (const float*)d_in[19];
    float* out = (float*)d_out;

    float *O, *O2, *Hb, *F2, *CS;
    __half *QK, *Kc, *V, *Vc, *S4, *Aa, *Xh, *Yh, *Wqh, *Wkh, *Wvh, *W1h, *W2h, *Hbh, *F1h;
    cudaGetSymbolAddress((void**)&QK,  g_QK);
    cudaGetSymbolAddress((void**)&Kc,  g_Kc);
    cudaGetSymbolAddress((void**)&V,   g_V);
    cudaGetSymbolAddress((void**)&Vc,  g_Vc);
    cudaGetSymbolAddress((void**)&O,   g_O);
    cudaGetSymbolAddress((void**)&O2,  g_O2);
    cudaGetSymbolAddress((void**)&Hb,  g_Hb);
    cudaGetSymbolAddress((void**)&F2,  g_F2);
    cudaGetSymbolAddress((void**)&S4,  g_S4);
    cudaGetSymbolAddress((void**)&Aa,  g_A);
    cudaGetSymbolAddress((void**)&Xh,  g_Xh);
    cudaGetSymbolAddress((void**)&Yh,  g_Yh);
    cudaGetSymbolAddress((void**)&Wqh, g_Wqh);
    cudaGetSymbolAddress((void**)&Wkh, g_Wkh);
    cudaGetSymbolAddress((void**)&Wvh, g_Wvh);
    cudaGetSymbolAddress((void**)&W1h, g_W1h);
    cudaGetSymbolAddress((void**)&W2h, g_W2h);
    cudaGetSymbolAddress((void**)&Hbh, g_Hbh);
    cudaGetSymbolAddress((void**)&F1h, g_F1h);
    cudaGetSymbolAddress((void**)&CS,  g_CS);

    // 0. conversions + position-compaction index
    cvt_k<<<512, 256>>>(x, Xh, BNE);
    cvt_k<<<512, 256>>>(y, Yh, BNE);
    cvt_k<<<512, 256>>>(Wq, Wqh, 4 * EE);
    cvt_k<<<512, 256>>>(Wk, Wkh, 4 * EE);
    cvt_k<<<256, 256>>>(Wv + (size_t)3 * EE, Wvh, EE);
    cvt_k<<<512, 256>>>(W1 + (size_t)3 * EC * FFC, W1h, EC * FFC);
    cvt_k<<<512, 256>>>(W2 + (size_t)3 * FFC * EC, W2h, FFC * EC);
    maskscan_k<<<BB, 1024>>>(ym);

    // 1. full projections; then gather compacted K/V head-block POSITIONS
    proj_k<<<dim3(4, 32, 9), 256>>>(Xh, Yh, Wqh, bq, Wkh, bk, Wvh, bv, QK, V);
    gatherK_k<<<dim3(8, 128), 256>>>(QK, Kc);
    gatherV_k<<<dim3(8, 32), 256>>>(V, Vc);
    colsumV_k<<<dim3(BB, HC), 64>>>(V, CS);

    // 2-4. attention over compacted positions
    scores_k<<<dim3(8, 8, 128), 256>>>(QK, Kc, xm, S4);
    softmax4_k<<<BB * HC * NXC / 8, 256>>>(S4, Aa);
    attnv_k<<<dim3(16, 32, 2), 128>>>(Aa, Vc, O, O2);
    fallback_k<<<MC, 128>>>(xm, CS, O, O2);

    // 5. tail
    gemm2_k<<<dim3(4, 32), 256>>>(O, O2, Wo + (size_t)3 * EE, bo + 3 * EC, F2, EC, EC);
    resln_k<<<MC, 128>>>(x, F2, g1 + 3 * EC, be1 + 3 * EC, Hb, Hbh);
    hgemm_k<<<dim3(16, 32), 256>>>(Hbh, W1h, bf1 + (size_t)3 * FFC, (float*)0, F1h, EC, FFC, 1);
    hgemm_k<<<dim3(4, 32), 256>>>(F1h, W2h, bf2 + 3 * EC, O, (__half*)0, FFC, EC, 0);
    resln_k<<<MC, 128>>>(Hb, O, g2 + 3 * EC, be2 + 3 * EC, out, (__half*)0);
}

// round 17
// speedup vs baseline: 5.8682x; 1.2171x over previous
#include <cuda_runtime.h>
#include <cuda_fp16.h>
#include <math.h>
#include <stdint.h>

// Problem constants
#define BB   4
#define NXC  1024
#define NYC  1024
#define EC   512
#define HC   8
#define DHC  64
#define LC   4
#define FFC  2048
#define MC   (BB * NXC)

#define BNE  (BB * NXC * EC)                  // 2,097,152
#define BHNN ((size_t)BB * HC * NXC * NYC)    // 33,554,432
#define EE   (EC * EC)

// ---------------------------------------------------------------------------
// Scratch (device globals; allocation-free per harness rules)
// ---------------------------------------------------------------------------
__device__ __half g_QK[8 * (size_t)BNE];      // Q0,K0,..,Q3,K3 fp16 (full)
__device__ __half g_Qc[4 * (size_t)BNE];      // compacted-position Q, 4 layers
__device__ __half g_Kc[4 * (size_t)BNE];      // compacted-position K, 4 layers
__device__ __half g_V [BNE];                  // V3 fp16 (full)
__device__ __half g_Vc[BNE];                  // V3 compacted positions
__device__ float  g_O [BNE];                  // attnv partial 0 / W2 out
__device__ float  g_O2[BNE];                  // attnv partial 1
__device__ float  g_Hb[BNE];
__device__ float  g_F2[BNE];
__device__ __half g_S4[4 * BHNN];             // scores fp16 (compacted rows+cols)
__device__ __half g_A [BHNN];                 // summed attention fp16
__device__ __half g_Xh [BNE];
__device__ __half g_Yh [BNE];
__device__ __half g_Wqh[4 * EE];
__device__ __half g_Wkh[4 * EE];
__device__ __half g_Wvh[EE];
__device__ __half g_W1h[(size_t)EC * FFC];
__device__ __half g_W2h[(size_t)FFC * EC];
__device__ __half g_Hbh[BNE];
__device__ __half g_F1h[(size_t)MC * FFC];
__device__ float  g_CS[BB * EC];              // per-(b,h,d) colsum of V positions
__device__ int    g_Nc[BB];                   // # unmasked y positions
__device__ int    g_NcPad[BB];
__device__ int    g_yidx[BB * NYC];
__device__ int    g_Nx[BB];                   // # unmasked x positions
__device__ int    g_NxPad[BB];
__device__ int    g_xidx[BB * NXC];

#define MASKED_H (-30000.0f)

// ---------------------------------------------------------------------------
// Helpers
// ---------------------------------------------------------------------------
__device__ __forceinline__ uint32_t pack2(float a, float b) {
    __half2 h = __floats2half2_rn(a, b);
    return *(uint32_t*)&h;
}

__device__ __forceinline__ uint32_t sptr(const void* p) {
    return (uint32_t)__cvta_generic_to_shared(p);
}

__device__ __forceinline__ void cpa16(uint32_t saddr, const void* gptr) {
    asm volatile("cp.async.ca.shared.global [%0], [%1], 16;"
                 :: "r"(saddr), "l"(gptr));
}
#define CP_COMMIT() asm volatile("cp.async.commit_group;" ::: "memory")
#define CP_WAIT0()  asm volatile("cp.async.wait_group 0;" ::: "memory")
#define CP_WAIT1()  asm volatile("cp.async.wait_group 1;" ::: "memory")

__device__ __forceinline__ void mma16(float* c,
    uint32_t a0, uint32_t a1, uint32_t a2, uint32_t a3,
    uint32_t b0, uint32_t b1)
{
    asm volatile(
        "mma.sync.aligned.m16n8k16.row.col.f32.f16.f16.f32 "
        "{%0,%1,%2,%3},{%4,%5,%6,%7},{%8,%9},{%0,%1,%2,%3};"
        : "+f"(c[0]), "+f"(c[1]), "+f"(c[2]), "+f"(c[3])
        : "r"(a0), "r"(a1), "r"(a2), "r"(a3), "r"(b0), "r"(b1));
}

__device__ __forceinline__ void ldm4t(uint32_t addr,
    uint32_t& r0, uint32_t& r1, uint32_t& r2, uint32_t& r3)
{
    asm volatile(
        "ldmatrix.sync.aligned.m8n8.x4.trans.shared.b16 {%0,%1,%2,%3}, [%4];"
        : "=r"(r0), "=r"(r1), "=r"(r2), "=r"(r3) : "r"(addr));
}

__device__ __forceinline__ void ldm4(uint32_t addr,
    uint32_t& r0, uint32_t& r1, uint32_t& r2, uint32_t& r3)
{
    asm volatile(
        "ldmatrix.sync.aligned.m8n8.x4.shared.b16 {%0,%1,%2,%3}, [%4];"
        : "=r"(r0), "=r"(r1), "=r"(r2), "=r"(r3) : "r"(addr));
}

#define LA_ROW(lane) (((lane) & 7) + (((lane) >> 3) & 1) * 8)
#define LA_COL(lane) ((((lane) >> 4) & 1) * 4)
#define LB_ROW(lane) (((lane) & 7) + (((lane) >> 4) & 1) * 8)
#define LB_COL(lane) ((((lane) >> 3) & 1) * 4)

// ---------------------------------------------------------------------------
// Merged fp32 -> fp16 conversion over 7 segments (one launch)
// ---------------------------------------------------------------------------
__global__ __launch_bounds__(256) void cvtall_k(
    const float* s0, __half* d0, int n0,
    const float* s1, __half* d1, int n1,
    const float* s2, __half* d2, int n2,
    const float* s3, __half* d3, int n3,
    const float* s4, __half* d4, int n4,
    const float* s5, __half* d5, int n5,
    const float* s6, __half* d6, int n6)
{
    const int total = n0 + n1 + n2 + n3 + n4 + n5 + n6;
    for (int i = (blockIdx.x * 256 + threadIdx.x) * 4; i < total;
         i += gridDim.x * 256 * 4) {
        int j = i;
        const float* s; __half* d;
        if      (j < n0)                          { s = s0; d = d0; }
        else if ((j -= n0) < n1)                  { s = s1; d = d1; }
        else if ((j -= n1) < n2)                  { s = s2; d = d2; }
        else if ((j -= n2) < n3)                  { s = s3; d = d3; }
        else if ((j -= n3) < n4)                  { s = s4; d = d4; }
        else if ((j -= n4) < n5)                  { s = s5; d = d5; }
        else     { j -= n5;                         s = s6; d = d6; }
        float4 v = *(const float4*)(s + j);
        *(uint32_t*)(d + j)     = pack2(v.x, v.y);
        *(uint32_t*)(d + j + 2) = pack2(v.z, v.w);
    }
}

// ---------------------------------------------------------------------------
// Per-batch compaction index of unmasked positions (generic, deterministic).
// ---------------------------------------------------------------------------
__global__ __launch_bounds__(1024) void maskscan_k(
    const int* __restrict__ mask, int* __restrict__ Np,
    int* __restrict__ NPadp, int* __restrict__ idx)
{
    __shared__ int wtot[32];
    __shared__ int wbase[32];
    const int b = blockIdx.x, tid = threadIdx.x;
    const int lane = tid & 31, w = tid >> 5;
    int v = (mask[b * NYC + tid] != 0) ? 1 : 0;
    unsigned m = __ballot_sync(0xffffffffu, v);
    int pos = __popc(m & ((1u << lane) - 1u));
    if (lane == 0) wtot[w] = __popc(m);
    __syncthreads();
    if (tid < 32) {
        int e = 0;
        for (int i = 0; i < 32; i++) if (i < tid) e += wtot[i];
        wbase[tid] = e;
        if (tid == 31) {
            int tot = e + wtot[31];
            Np[b] = tot;
            NPadp[b] = ((tot + 255) >> 8) << 8;
        }
    }
    __syncthreads();
    if (v) idx[b * NYC + wbase[w] + pos] = tid;
}

// Gather compacted Q AND K head-block positions for all 4 layers.
// Grid (8, 256): zl<128 -> K (yidx), zl>=128 -> Q (xidx). 256 thr.
__global__ __launch_bounds__(256) void gatherQK_k(
    const __half* __restrict__ QK, __half* __restrict__ Qc,
    __half* __restrict__ Kc)
{
    int zl = blockIdx.y;
    const int isQ = (zl >= 128);
    if (isQ) zl -= 128;
    const int l = zl >> 5, bh = zl & 31, b = bh >> 3, h = bh & 7;
    const int chunk = blockIdx.x, tid = threadIdx.x;
    const int Nv = isQ ? g_Nx[b] : g_Nc[b];
    const int* idx = (isQ ? g_xidx : g_yidx) + b * NYC;
    const __half* sb = QK + (size_t)(2 * l + (isQ ? 0 : 1)) * BNE
                       + (size_t)b * NYC * EC + (size_t)h * NYC * DHC;
    __half* db = (isQ ? Qc : Kc) + (size_t)l * BNE
                 + (size_t)b * NYC * EC + (size_t)h * NYC * DHC;
    for (int t = tid; t < 128 * 8; t += 256) {
        int j = chunk * 128 + (t >> 3);
        int q = (t & 7) * 8;
        uint4 val = make_uint4(0, 0, 0, 0);
        if (j < Nv) {
            int src = idx[j];
            val = *(const uint4*)(sb + (size_t)src * DHC + q);
        }
        *(uint4*)(db + (size_t)j * DHC + q) = val;
    }
}

// Gather compacted V head-block positions. Grid (8, 32), 256 thr.
__global__ __launch_bounds__(256) void gatherV_k(
    const __half* __restrict__ V, __half* __restrict__ Vc)
{
    const int bh = blockIdx.y, b = bh >> 3, h = bh & 7;
    const int chunk = blockIdx.x, tid = threadIdx.x;
    const int Nc = g_Nc[b];
    const __half* sb = V  + (size_t)b * NYC * EC + (size_t)h * NYC * DHC;
    __half*       db = Vc + (size_t)b * NYC * EC + (size_t)h * NYC * DHC;
    for (int t = tid; t < 128 * 8; t += 256) {
        int j = chunk * 128 + (t >> 3);
        int q = (t & 7) * 8;
        uint4 val = make_uint4(0, 0, 0, 0);
        if (j < Nc) {
            int src = g_yidx[b * NYC + j];
            val = *(const uint4*)(sb + (size_t)src * DHC + q);
        }
        *(uint4*)(db + (size_t)j * DHC + q) = val;
    }
}

// Per-(b,h,d) sum of FULL V over all 1024 positions. Grid (4, 8), 64 thr.
__global__ __launch_bounds__(64) void colsumV_k(
    const __half* __restrict__ V, float* __restrict__ CS)
{
    const int b = blockIdx.x, h = blockIdx.y, d = threadIdx.x;
    const __half* p = V + (size_t)b * NYC * EC + (size_t)h * NYC * DHC + d;
    float s = 0.f;
#pragma unroll 8
    for (int m = 0; m < NYC; m++) s += __half2float(p[(size_t)m * DHC]);
    CS[b * EC + h * DHC + d] = s;
}

// Fallback for fully-masked x rows: O0 = (4/1024)*colsumV, O1 = 0.
__global__ __launch_bounds__(128) void fallback_k(
    const int* __restrict__ xm, const float* __restrict__ CS,
    float* __restrict__ O0, float* __restrict__ O1)
{
    const int n = blockIdx.x;
    if (xm[n] != 0) return;
    const int b = n >> 10, tid = threadIdx.x;
#pragma unroll
    for (int i = 0; i < 4; i++) {
        int c = tid + i * 128;
        O0[(size_t)n * EC + c] = 0.00390625f * CS[b * EC + c];
        O1[(size_t)n * EC + c] = 0.f;
    }
}

// ---------------------------------------------------------------------------
// Pure-fp16 GEMM body (3-stage cp.async).
// ---------------------------------------------------------------------------
__device__ __forceinline__ void hgemm_body(
    const __half* __restrict__ A, const __half* __restrict__ W,
    const float* __restrict__ bias, float* __restrict__ Cf,
    __half* __restrict__ Ch, int K, int N, int dogelu)
{
    __shared__ uint32_t Ah[3][128][12];
    __shared__ __half   Bs[3][16][136];

    const int tid  = threadIdx.x;
    const int warp = tid >> 5, lane = tid & 31;
    const int wm = warp >> 1, wn = warp & 1;
    const int g  = lane >> 2, tg = lane & 3;
    const int mblk = blockIdx.y * 128, nblk = blockIdx.x * 128;

    const int arow = tid >> 1, aseg = (tid & 1) * 4;
    const int wrow = tid >> 4, wcol = (tid & 15) * 8;

    const __half* Ag = A + (size_t)(mblk + arow) * K + aseg * 2;
    const __half* Wg = W + (size_t)wrow * N + nblk + wcol;

    const int la_r = LA_ROW(lane), la_c = LA_COL(lane);
    const int bl_k = (lane & 7) + ((lane >> 3) & 1) * 8;
    const int bl_n = wn * 64 + (lane >> 4) * 8;

    float acc[2][8][4];
#pragma unroll
    for (int mi = 0; mi < 2; mi++)
#pragma unroll
        for (int ni = 0; ni < 8; ni++)
#pragma unroll
            for (int q = 0; q < 4; q++) acc[mi][ni][q] = 0.f;

    const int nst = K >> 4;

#define HG_ISSUE(st, bf) do { \
        cpa16(sptr(&Ah[bf][arow][aseg]), Ag + (st) * 16); \
        cpa16(sptr(&Bs[bf][wrow][wcol]), Wg + (size_t)(st) * 16 * N); \
    } while (0)

    HG_ISSUE(0, 0); CP_COMMIT();
    HG_ISSUE(1, 1); CP_COMMIT();

    for (int s = 0; s < nst; s++) {
        CP_WAIT1();
        __syncthreads();
        const int buf = s % 3;

        uint32_t af[2][4];
#pragma unroll
        for (int mi = 0; mi < 2; mi++)
            ldm4(sptr(&Ah[buf][wm * 32 + mi * 16 + la_r][la_c]),
                 af[mi][0], af[mi][1], af[mi][2], af[mi][3]);
#pragma unroll
        for (int pair = 0; pair < 4; pair++) {
            uint32_t b00, b10, b01, b11;
            ldm4t(sptr(&Bs[buf][bl_k][bl_n + pair * 16]), b00, b10, b01, b11);
#pragma unroll
            for (int mi = 0; mi < 2; mi++) {
                mma16(acc[mi][2*pair    ], af[mi][0], af[mi][1], af[mi][2], af[mi][3], b00, b10);
                mma16(acc[mi][2*pair + 1], af[mi][0], af[mi][1], af[mi][2], af[mi][3], b01, b11);
            }
        }

        if (s + 2 < nst) HG_ISSUE(s + 2, (s + 2) % 3);
        CP_COMMIT();
    }
#undef HG_ISSUE

#pragma unroll
    for (int mi = 0; mi < 2; mi++) {
        int r0 = mblk + wm * 32 + mi * 16 + g;
#pragma unroll
        for (int ni = 0; ni < 8; ni++) {
            int c = nblk + wn * 64 + ni * 8 + tg * 2;
            float b0 = bias[c], b1 = bias[c + 1];
            float v0 = acc[mi][ni][0] + b0, v1 = acc[mi][ni][1] + b1;
            float v2 = acc[mi][ni][2] + b0, v3 = acc[mi][ni][3] + b1;
            if (dogelu) {
                v0 = 0.5f * v0 * (1.0f + erff(v0 * 0.70710678118654752f));
                v1 = 0.5f * v1 * (1.0f + erff(v1 * 0.70710678118654752f));
                v2 = 0.5f * v2 * (1.0f + erff(v2 * 0.70710678118654752f));
                v3 = 0.5f * v3 * (1.0f + erff(v3 * 0.70710678118654752f));
            }
            if (Ch) {
                *(__half2*)&Ch[(size_t)r0 * N + c]       = __floats2half2_rn(v0, v1);
                *(__half2*)&Ch[(size_t)(r0 + 8) * N + c] = __floats2half2_rn(v2, v3);
            } else {
                *(float2*)&Cf[(size_t)r0 * N + c]       = make_float2(v0, v1);
                *(float2*)&Cf[(size_t)(r0 + 8) * N + c] = make_float2(v2, v3);
            }
        }
    }
}

__global__ __launch_bounds__(256) void hgemm_k(
    const __half* __restrict__ A, const __half* __restrict__ W,
    const float* __restrict__ bias, float* __restrict__ Cf,
    __half* __restrict__ Ch, int K, int N, int dogelu)
{
    hgemm_body(A, W, bias, Cf, Ch, K, N, dogelu);
}

// Batched projections (FULL inputs): z=0..7 -> Q/K, z=8 -> V3.
__global__ __launch_bounds__(256) void proj_k(
    const __half* __restrict__ Xh, const __half* __restrict__ Yh,
    const __half* __restrict__ Wqh, const float* __restrict__ bq,
    const __half* __restrict__ Wkh, const float* __restrict__ bk,
    const __half* __restrict__ Wvh, const float* __restrict__ bv,
    __half* __restrict__ QK, __half* __restrict__ V)
{
    const int z = blockIdx.z;
    const __half *A, *W;
    const float* Bi;
    __half* C;
    if (z < 8) {
        int l = z >> 1, isK = z & 1;
        A  = isK ? Yh : Xh;
        W  = (isK ? Wkh : Wqh) + (size_t)l * EE;
        Bi = (isK ? bk : bq) + (size_t)l * EC;
        C  = QK + (size_t)z * BNE;
    } else {
        A = Yh; W = Wvh; Bi = bv + (size_t)3 * EC; C = V;
    }
    hgemm_body(A, W, Bi, (float*)0, C, EC, EC, 0);
}

// ---------------------------------------------------------------------------
// FP32-input GEMM (Wo only): C = (A + A2) @ W + bias.
// ---------------------------------------------------------------------------
__device__ __forceinline__ void gemm16_body(
    const float* __restrict__ A, const float* __restrict__ A2,
    const float* __restrict__ W,
    const float* __restrict__ bias, float* __restrict__ Cf,
    int K, int N)
{
    __shared__ uint32_t As2[2][128][12];
    __shared__ __half   Bs [2][16][136];

    const int tid  = threadIdx.x;
    const int warp = tid >> 5, lane = tid & 31;
    const int wm = warp >> 1, wn = warp & 1;
    const int g  = lane >> 2, tg = lane & 3;
    const int mblk = blockIdx.y * 128, nblk = blockIdx.x * 128;

    const int arow = tid >> 1, aseg = (tid & 1) * 4;
    const int wrow = tid >> 4, wcol = (tid & 15) * 8;

    const float* Ag  = A  + (size_t)(mblk + arow) * K + aseg * 2;
    const float* Ag2 = A2 + (size_t)(mblk + arow) * K + aseg * 2;
    const float* Wg  = W + (size_t)wrow * N + nblk + wcol;

    const int la_r = LA_ROW(lane), la_c = LA_COL(lane);
    const int bl_k = (lane & 7) + ((lane >> 3) & 1) * 8;
    const int bl_n = wn * 64 + (lane >> 4) * 8;

    float acc[2][8][4];
#pragma unroll
    for (int mi = 0; mi < 2; mi++)
#pragma unroll
        for (int ni = 0; ni < 8; ni++)
#pragma unroll
            for (int q = 0; q < 4; q++) acc[mi][ni][q] = 0.f;

    {
        float4 a0 = *(const float4*)(Ag);
        float4 a1 = *(const float4*)(Ag + 4);
        float4 c0 = *(const float4*)(Ag2);
        float4 c1 = *(const float4*)(Ag2 + 4);
        a0.x += c0.x; a0.y += c0.y; a0.z += c0.z; a0.w += c0.w;
        a1.x += c1.x; a1.y += c1.y; a1.z += c1.z; a1.w += c1.w;
        As2[0][arow][aseg+0] = pack2(a0.x, a0.y);
        As2[0][arow][aseg+1] = pack2(a0.z, a0.w);
        As2[0][arow][aseg+2] = pack2(a1.x, a1.y);
        As2[0][arow][aseg+3] = pack2(a1.z, a1.w);
        float4 w0 = *(const float4*)(Wg);
        float4 w1 = *(const float4*)(Wg + 4);
        __half2* bp = (__half2*)&Bs[0][wrow][wcol];
        bp[0] = __floats2half2_rn(w0.x, w0.y);
        bp[1] = __floats2half2_rn(w0.z, w0.w);
        bp[2] = __floats2half2_rn(w1.x, w1.y);
        bp[3] = __floats2half2_rn(w1.z, w1.w);
    }
    __syncthreads();

    const int nst = K >> 4;
    for (int s = 0; s < nst; s++) {
        const int buf = s & 1;
        const bool more = (s + 1 < nst);
        float4 pa0, pa1, pw0, pw1;
        if (more) {
            const float* Ap = Ag + (s + 1) * 16;
            const float* Ap2 = Ag2 + (s + 1) * 16;
            const float* Wp = Wg + (size_t)(s + 1) * 16 * N;
            pa0 = *(const float4*)Ap; pa1 = *(const float4*)(Ap + 4);
            float4 c0 = *(const float4*)Ap2;
            float4 c1 = *(const float4*)(Ap2 + 4);
            pa0.x += c0.x; pa0.y += c0.y; pa0.z += c0.z; pa0.w += c0.w;
            pa1.x += c1.x; pa1.y += c1.y; pa1.z += c1.z; pa1.w += c1.w;
            pw0 = *(const float4*)Wp; pw1 = *(const float4*)(Wp + 4);
        }

        uint32_t af[2][4];
#pragma unroll
        for (int mi = 0; mi < 2; mi++)
            ldm4(sptr(&As2[buf][wm * 32 + mi * 16 + la_r][la_c]),
                 af[mi][0], af[mi][1], af[mi][2], af[mi][3]);
#pragma unroll
        for (int pair = 0; pair < 4; pair++) {
            uint32_t b00, b10, b01, b11;
            ldm4t(sptr(&Bs[buf][bl_k][bl_n + pair * 16]), b00, b10, b01, b11);
#pragma unroll
            for (int mi = 0; mi < 2; mi++) {
                mma16(acc[mi][2*pair    ], af[mi][0], af[mi][1], af[mi][2], af[mi][3], b00, b10);
                mma16(acc[mi][2*pair + 1], af[mi][0], af[mi][1], af[mi][2], af[mi][3], b01, b11);
            }
        }

        if (more) {
            const int nb = buf ^ 1;
            As2[nb][arow][aseg+0] = pack2(pa0.x, pa0.y);
            As2[nb][arow][aseg+1] = pack2(pa0.z, pa0.w);
            As2[nb][arow][aseg+2] = pack2(pa1.x, pa1.y);
            As2[nb][arow][aseg+3] = pack2(pa1.z, pa1.w);
            __half2* bp = (__half2*)&Bs[nb][wrow][wcol];
            bp[0] = __floats2half2_rn(pw0.x, pw0.y);
            bp[1] = __floats2half2_rn(pw0.z, pw0.w);
            bp[2] = __floats2half2_rn(pw1.x, pw1.y);
            bp[3] = __floats2half2_rn(pw1.z, pw1.w);
            __syncthreads();
        }
    }

#pragma unroll
    for (int mi = 0; mi < 2; mi++) {
        int r0 = mblk + wm * 32 + mi * 16 + g;
#pragma unroll
        for (int ni = 0; ni < 8; ni++) {
            int c = nblk + wn * 64 + ni * 8 + tg * 2;
            float b0 = bias[c], b1 = bias[c + 1];
            *(float2*)&Cf[(size_t)r0 * N + c] =
                make_float2(acc[mi][ni][0] + b0, acc[mi][ni][1] + b1);
            *(float2*)&Cf[(size_t)(r0 + 8) * N + c] =
                make_float2(acc[mi][ni][2] + b0, acc[mi][ni][3] + b1);
        }
    }
}

__global__ __launch_bounds__(256) void gemm2_k(
    const float* __restrict__ A, const float* __restrict__ A2,
    const float* __restrict__ W,
    const float* __restrict__ bias, float* __restrict__ C,
    int K, int N)
{
    gemm16_body(A, A2, W, bias, C, K, N);
}

// ---------------------------------------------------------------------------
// Scores over COMPACTED Q rows x COMPACTED K cols. Tiles beyond pads exit.
// Grid (NY/128, NX/128, 4*32), 256 threads.
// ---------------------------------------------------------------------------
__global__ __launch_bounds__(256) void scores_k(
    const __half* __restrict__ Qc, const __half* __restrict__ Kc,
    __half* __restrict__ S4)
{
    __shared__ uint32_t Qs2[128][36];
    __shared__ uint32_t Ks2[128][36];

    const int z = blockIdx.z;
    const int l = z >> 5, bh = z & 31, b = bh >> 3, h = bh & 7;
    const int Nc = g_Nc[b], NcPad = g_NcPad[b], NxPad = g_NxPad[b];
    const int nblk = blockIdx.x * 128;
    const int mblk = blockIdx.y * 128;
    if (nblk >= NcPad || mblk >= NxPad) return;

    const uint32_t* Qb = (const uint32_t*)(Qc + (size_t)l * BNE)
                         + (size_t)b * NXC * 256 + (size_t)h * NXC * 32;
    const uint32_t* Kb = (const uint32_t*)(Kc + (size_t)l * BNE)
                         + (size_t)b * NYC * 256 + (size_t)h * NYC * 32;

    const int tid  = threadIdx.x;
    const int warp = tid >> 5, lane = tid & 31;
    const int wm = warp >> 1, wn = warp & 1;
    const int g = lane >> 2, tg = lane & 3;

    const int la_r = LA_ROW(lane), la_c = LA_COL(lane);
    const int lb_r = LB_ROW(lane), lb_c = LB_COL(lane);

    {
        int r = tid >> 1;
        int wseg = (tid & 1) * 16;
        const uint32_t* qsrc = Qb + (size_t)(mblk + r) * 32 + wseg;
        const uint32_t* ksrc = Kb + (size_t)(nblk + r) * 32 + wseg;
#pragma unroll
        for (int i = 0; i < 4; i++) {
            cpa16(sptr(&Qs2[r][wseg + i * 4]), qsrc + i * 4);
            cpa16(sptr(&Ks2[r][wseg + i * 4]), ksrc + i * 4);
        }
    }
    CP_COMMIT();
    CP_WAIT0();
    __syncthreads();

    float acc[2][8][4];
#pragma unroll
    for (int mi = 0; mi < 2; mi++)
#pragma unroll
        for (int ni = 0; ni < 8; ni++)
#pragma unroll
            for (int q = 0; q < 4; q++) acc[mi][ni][q] = 0.f;

#pragma unroll
    for (int c = 0; c < 4; c++) {
        uint32_t af[2][4];
#pragma unroll
        for (int mi = 0; mi < 2; mi++)
            ldm4(sptr(&Qs2[wm * 32 + mi * 16 + la_r][8 * c + la_c]),
                 af[mi][0], af[mi][1], af[mi][2], af[mi][3]);
#pragma unroll
        for (int nq = 0; nq < 4; nq++) {
            uint32_t b00, b01, b10, b11;
            ldm4(sptr(&Ks2[wn * 64 + nq * 16 + lb_r][8 * c + lb_c]),
                 b00, b01, b10, b11);
#pragma unroll
            for (int mi = 0; mi < 2; mi++) {
                mma16(acc[mi][2*nq    ], af[mi][0], af[mi][1], af[mi][2], af[mi][3], b00, b01);
                mma16(acc[mi][2*nq + 1], af[mi][0], af[mi][1], af[mi][2], af[mi][3], b10, b11);
            }
        }
    }

    __half* Sl = S4 + (size_t)l * BHNN + (size_t)bh * NXC * NYC;
#pragma unroll
    for (int mi = 0; mi < 2; mi++) {
        int r0 = mblk + wm * 32 + mi * 16 + g;
#pragma unroll
        for (int ni = 0; ni < 8; ni++) {
            int c = nblk + wn * 64 + ni * 8 + tg * 2;
            int c0v = (c < Nc), c1v = (c + 1 < Nc);
            float v0 = c0v ? acc[mi][ni][0] * 0.125f : MASKED_H;
            float v1 = c1v ? acc[mi][ni][1] * 0.125f : MASKED_H;
            float v2 = c0v ? acc[mi][ni][2] * 0.125f : MASKED_H;
            float v3 = c1v ? acc[mi][ni][3] * 0.125f : MASKED_H;
            *(__half2*)&Sl[(size_t)r0 * NYC + c]       = __floats2half2_rn(v0, v1);
            *(__half2*)&Sl[(size_t)(r0 + 8) * NYC + c] = __floats2half2_rn(v2, v3);
        }
    }
}

// ---------------------------------------------------------------------------
// Fused softmax-sum over compacted rows+cols. Warp-per-row, 8 rows/block.
// ---------------------------------------------------------------------------
__global__ __launch_bounds__(256) void softmax4_k(
    const __half* __restrict__ S4, __half* __restrict__ A)
{
    const int warp = threadIdx.x >> 5, lane = threadIdx.x & 31;
    const int row = blockIdx.x * 8 + warp;
    const int b = row >> 13;
    const int r = row & (NXC - 1);
    if (r >= g_NxPad[b]) return;
    const int NcPad = g_NcPad[b];
    const size_t base = (size_t)row * NYC;

    float acc[32];
#pragma unroll
    for (int i = 0; i < 32; i++) acc[i] = 0.f;

#pragma unroll
    for (int l = 0; l < 4; l++) {
        const __half* Sr = S4 + (size_t)l * BHNN + base;
        float v[32];
#pragma unroll
        for (int i = 0; i < 4; i++) {
            if (i * 256 < NcPad) {
                uint4 u = *(const uint4*)(Sr + i * 256 + lane * 8);
                float2 f;
                f = __half22float2(*(__half2*)&u.x); v[i*8+0]=f.x; v[i*8+1]=f.y;
                f = __half22float2(*(__half2*)&u.y); v[i*8+2]=f.x; v[i*8+3]=f.y;
                f = __half22float2(*(__half2*)&u.z); v[i*8+4]=f.x; v[i*8+5]=f.y;
                f = __half22float2(*(__half2*)&u.w); v[i*8+6]=f.x; v[i*8+7]=f.y;
            } else {
#pragma unroll
                for (int j = 0; j < 8; j++) v[i*8+j] = MASKED_H;
            }
        }
        float m = v[0];
#pragma unroll
        for (int i = 1; i < 32; i++) m = fmaxf(m, v[i]);
#pragma unroll
        for (int o = 16; o > 0; o >>= 1) m = fmaxf(m, __shfl_xor_sync(0xffffffffu, m, o));
        float s = 0.f;
#pragma unroll
        for (int i = 0; i < 32; i++) { v[i] = __expf(v[i] - m); s += v[i]; }
#pragma unroll
        for (int o = 16; o > 0; o >>= 1) s += __shfl_xor_sync(0xffffffffu, s, o);
        float inv = 1.0f / s;
#pragma unroll
        for (int i = 0; i < 32; i++) acc[i] += v[i] * inv;
    }

#pragma unroll
    for (int i = 0; i < 4; i++) {
        if (i * 256 < NcPad) {
            uint4 u;
            __half2* p = (__half2*)&u;
            p[0] = __floats2half2_rn(acc[i*8+0], acc[i*8+1]);
            p[1] = __floats2half2_rn(acc[i*8+2], acc[i*8+3]);
            p[2] = __floats2half2_rn(acc[i*8+4], acc[i*8+5]);
            p[3] = __floats2half2_rn(acc[i*8+6], acc[i*8+7]);
            *(uint4*)(A + base + i * 256 + lane * 8) = u;
        }
    }
}

// ---------------------------------------------------------------------------
// attnv over compacted rows & K-dim, scattering output rows via xidx.
// 3-stage cp.async, BK=32, split-K=2. Grid (NX/64, B*H, 2).
// ---------------------------------------------------------------------------
__global__ __launch_bounds__(128) void attnv_k(
    const __half* __restrict__ Aa, const __half* __restrict__ Vc,
    float* __restrict__ O0, float* __restrict__ O1)
{
    __shared__ uint32_t As2[3][64][20];
    __shared__ __half   Vs [3][32][136];

    const int bh = blockIdx.y, b = bh >> 3, h = bh & 7;
    const int mblk = blockIdx.x * 64;
    const int zz = blockIdx.z;
    const int tid = threadIdx.x;
    const int warp = tid >> 5, lane = tid & 31;
    const int g = lane >> 2, tg = lane & 3;

    const int NcPad = g_NcPad[b], NxPad = g_NxPad[b], Nx = g_Nx[b];
    if (mblk >= NxPad) return;
    const int nst = NcPad >> 6;
    const int krows = zz * (NcPad >> 1);

    const uint32_t* Ab = (const uint32_t*)(Aa + (size_t)bh * NXC * NYC);
    const __half* Vb = Vc + (size_t)b * NYC * EC + (size_t)h * NYC * DHC
                          + (size_t)krows * DHC;

    const int arow = tid >> 1, aseg = (tid & 1) * 8;
    const int vrow = tid >> 2, vcol = (tid & 3) * 16;

    const uint32_t* Ag = Ab + (size_t)(mblk + arow) * 512 + (krows >> 1) + aseg;

    const int la_r = LA_ROW(lane), la_c = LA_COL(lane);
    const int vl_k = (lane & 7) + ((lane >> 3) & 1) * 8;
    const int vl_n = (lane >> 4) * 8;

    float acc[8][4];
#pragma unroll
    for (int ni = 0; ni < 8; ni++)
#pragma unroll
        for (int q = 0; q < 4; q++) acc[ni][q] = 0.f;

#define AV_ISSUE(st, bf) do { \
        cpa16(sptr(&As2[bf][arow][aseg]),     Ag + (st) * 16); \
        cpa16(sptr(&As2[bf][arow][aseg + 4]), Ag + (st) * 16 + 4); \
        const __half* Vg_ = Vb + (size_t)((st) * 32 + vrow) * DHC + vcol; \
        cpa16(sptr(&Vs[bf][vrow][vcol]),     Vg_); \
        cpa16(sptr(&Vs[bf][vrow][vcol + 8]), Vg_ + 8); \
    } while (0)

    AV_ISSUE(0, 0); CP_COMMIT();
    AV_ISSUE(1, 1); CP_COMMIT();

    for (int s = 0; s < nst; s++) {
        CP_WAIT1();
        __syncthreads();
        const int buf = s % 3;

#pragma unroll
        for (int cc = 0; cc < 2; cc++) {
            uint32_t a0, a1, a2, a3;
            ldm4(sptr(&As2[buf][warp * 16 + la_r][8 * cc + la_c]), a0, a1, a2, a3);
#pragma unroll
            for (int pair = 0; pair < 4; pair++) {
                uint32_t b00, b10, b01, b11;
                ldm4t(sptr(&Vs[buf][16*cc + vl_k][pair * 16 + vl_n]), b00, b10, b01, b11);
                mma16(acc[2*pair    ], a0, a1, a2, a3, b00, b10);
                mma16(acc[2*pair + 1], a0, a1, a2, a3, b01, b11);
            }
        }

        if (s + 2 < nst) AV_ISSUE(s + 2, (s + 2) % 3);
        CP_COMMIT();
    }
#undef AV_ISSUE

    float* Op = (zz == 0 ? O0 : O1);
    const int r0 = mblk + warp * 16 + g;
    const int fr0 = (r0     < Nx) ? g_xidx[b * NXC + r0]     : -1;
    const int fr1 = (r0 + 8 < Nx) ? g_xidx[b * NXC + r0 + 8] : -1;
    float* Ob = Op + (size_t)b * NXC * EC + (size_t)h * DHC;
#pragma unroll
    for (int ni = 0; ni < 8; ni++) {
        int c = ni * 8 + tg * 2;
        if (fr0 >= 0)
            *(float2*)&Ob[(size_t)fr0 * EC + c] = make_float2(acc[ni][0], acc[ni][1]);
        if (fr1 >= 0)
            *(float2*)&Ob[(size_t)fr1 * EC + c] = make_float2(acc[ni][2], acc[ni][3]);
    }
}

// ---------------------------------------------------------------------------
// Residual + LayerNorm (optional fp16 copy)
// ---------------------------------------------------------------------------
__global__ __launch_bounds__(128) void resln_k(
    const float* __restrict__ X, const float* __restrict__ R,
    const float* __restrict__ g, const float* __restrict__ be,
    float* __restrict__ Out, __half* __restrict__ Outh)
{
    __shared__ float sred[4];
    __shared__ float sbc;

    const size_t base = (size_t)blockIdx.x * EC;
    const int tid = threadIdx.x, lane = tid & 31, w = tid >> 5;

    float r[4];
    int col[4];
#pragma unroll
    for (int i = 0; i < 4; i++) {
        col[i] = tid + i * 128;
        r[i] = X[base + col[i]] + R[base + col[i]];
    }

    float s = r[0] + r[1] + r[2] + r[3];
#pragma unroll
    for (int o = 16; o > 0; o >>= 1) s += __shfl_xor_sync(0xffffffffu, s, o);
    if (lane == 0) sred[w] = s;
    __syncthreads();
    if (tid == 0) sbc = sred[0] + sred[1] + sred[2] + sred[3];
    __syncthreads();
    const float mu = sbc * (1.0f / EC);

    float d[4], ss = 0.f;
#pragma unroll
    for (int i = 0; i < 4; i++) { d[i] = r[i] - mu; ss += d[i] * d[i]; }
#pragma unroll
    for (int o = 16; o > 0; o >>= 1) ss += __shfl_xor_sync(0xffffffffu, ss, o);
    if (lane == 0) sred[w] = ss;
    __syncthreads();
    if (tid == 0) sbc = sred[0] + sred[1] + sred[2] + sred[3];
    __syncthreads();
    const float rs = rsqrtf(sbc * (1.0f / EC) + 1e-5f);

#pragma unroll
    for (int i = 0; i < 4; i++) {
        float v = d[i] * rs * g[col[i]] + be[col[i]];
        Out[base + col[i]] = v;
        if (Outh) Outh[base + col[i]] = __float2half_rn(v);
    }
}

// ---------------------------------------------------------------------------
// Host
// ---------------------------------------------------------------------------
extern "C" void kernel_launch(void* const* d_in, const int* in_sizes, int n_in,
                              void* d_out, int out_size)
{
    (void)in_sizes; (void)n_in; (void)out_size;

    const float* x   = (const float*)d_in[0];
    const float* y   = (const float*)d_in[1];
    const int*   xm  = (const int*)  d_in[2];
    const int*   ym  = (const int*)  d_in[3];
    const float* Wq  = (const float*)d_in[4];
    const float* bq  = (const float*)d_in[5];
    const float* Wk  = (const float*)d_in[6];
    const float* bk  = (const float*)d_in[7];
    const float* Wv  = (const float*)d_in[8];
    const float* bv  = (const float*)d_in[9];
    const float* Wo  = (const float*)d_in[10];
    const float* bo  = (const float*)d_in[11];
    const float* g1  = (const float*)d_in[12];
    const float* be1 = (const float*)d_in[13];
    const float* g2  = (const float*)d_in[14];
    const float* be2 = (const float*)d_in[15];
    const float* W1  = (const float*)d_in[16];
    const float* bf1 = (const float*)d_in[17];
    const float* W2  = (const float*)d_in[18];
    const float* bf2 = (const float*)d_in[19];
    float* out = (float*)d_out;

    float *O, *O2, *Hb, *F2, *CS;
    __half *QK, *Qc, *Kc, *V, *Vc, *S4, *Aa, *Xh, *Yh;
    __half *Wqh, *Wkh, *Wvh, *W1h, *W2h, *Hbh, *F1h;
    int *Ncp, *NcPadp, *yidxp, *Nxp, *NxPadp, *xidxp;
    cudaGetSymbolAddress((void**)&QK,  g_QK);
    cudaGetSymbolAddress((void**)&Qc,  g_Qc);
    cudaGetSymbolAddress((void**)&Kc,  g_Kc);
    cudaGetSymbolAddress((void**)&V,   g_V);
    cudaGetSymbolAddress((void**)&Vc,  g_Vc);
    cudaGetSymbolAddress((void**)&O,   g_O);
    cudaGetSymbolAddress((void**)&O2,  g_O2);
    cudaGetSymbolAddress((void**)&Hb,  g_Hb);
    cudaGetSymbolAddress((void**)&F2,  g_F2);
    cudaGetSymbolAddress((void**)&S4,  g_S4);
    cudaGetSymbolAddress((void**)&Aa,  g_A);
    cudaGetSymbolAddress((void**)&Xh,  g_Xh);
    cudaGetSymbolAddress((void**)&Yh,  g_Yh);
    cudaGetSymbolAddress((void**)&Wqh, g_Wqh);
    cudaGetSymbolAddress((void**)&Wkh, g_Wkh);
    cudaGetSymbolAddress((void**)&Wvh, g_Wvh);
    cudaGetSymbolAddress((void**)&W1h, g_W1h);
    cudaGetSymbolAddress((void**)&W2h, g_W2h);
    cudaGetSymbolAddress((void**)&Hbh, g_Hbh);
    cudaGetSymbolAddress((void**)&F1h, g_F1h);
    cudaGetSymbolAddress((void**)&CS,  g_CS);
    cudaGetSymbolAddress((void**)&Ncp,    g_Nc);
    cudaGetSymbolAddress((void**)&NcPadp, g_NcPad);
    cudaGetSymbolAddress((void**)&yidxp,  g_yidx);
    cudaGetSymbolAddress((void**)&Nxp,    g_Nx);
    cudaGetSymbolAddress((void**)&NxPadp, g_NxPad);
    cudaGetSymbolAddress((void**)&xidxp,  g_xidx);

    // 0. conversions (single launch) + compaction indices for ym and xm
    cvtall_k<<<1024, 256>>>(
        x, Xh, BNE, y, Yh, BNE,
        Wq, Wqh, 4 * EE, Wk, Wkh, 4 * EE,
        Wv + (size_t)3 * EE, Wvh, EE,
        W1 + (size_t)3 * EC * FFC, W1h, EC * FFC,
        W2 + (size_t)3 * FFC * EC, W2h, FFC * EC);
    maskscan_k<<<BB, 1024>>>(ym, Ncp, NcPadp, yidxp);
    maskscan_k<<<BB, 1024>>>(xm, Nxp, NxPadp, xidxp);

    // 1. full projections; gather compacted Q/K/V head-block POSITIONS
    proj_k<<<dim3(4, 32, 9), 256>>>(Xh, Yh, Wqh, bq, Wkh, bk, Wvh, bv, QK, V);
    gatherQK_k<<<dim3(8, 256), 256>>>(QK, Qc, Kc);
    gatherV_k<<<dim3(8, 32), 256>>>(V, Vc);
    colsumV_k<<<dim3(BB, HC), 64>>>(V, CS);

    // 2-4. attention over compacted rows & columns; attnv scatters rows
    scores_k<<<dim3(8, 8, 128), 256>>>(Qc, Kc, S4);
    softmax4_k<<<BB * HC * NXC / 8, 256>>>(S4, Aa);
    attnv_k<<<dim3(16, 32, 2), 128>>>(Aa, Vc, O, O2);
    fallback_k<<<MC, 128>>>(xm, CS, O, O2);

    // 5. tail
    gemm2_k<<<dim3(4, 32), 256>>>(O, O2, Wo + (size_t)3 * EE, bo + 3 * EC, F2, EC, EC);
    resln_k<<<MC, 128>>>(x, F2, g1 + 3 * EC, be1 + 3 * EC, Hb, Hbh);
    hgemm_k<<<dim3(16, 32), 256>>>(Hbh, W1h, bf1 + (size_t)3 * FFC, (float*)0, F1h, EC, FFC, 1);
    hgemm_k<<<dim3(4, 32), 256>>>(F1h, W2h, bf2 + 3 * EC, O, (__half*)0, FFC, EC, 0);
    resln_k<<<MC, 128>>>(Hb, O, g2 + 3 * EC, be2 + 3 * EC, out, (__half*)0);
}